// round 1
// baseline (speedup 1.0000x reference)
#include <cuda_runtime.h>
#include <cstdint>

#define N_OBJ  20000
#define N_ROOM 500
#define N_ATTR 2000
#define IN_F   300
#define HDIM   512
#define EOO    640000
#define ERO    50000
#define EAO    100000
#define BATCH  8

// ---------------- scratch (device globals, no allocation) ----------------
__device__ float g_aggOO[(size_t)N_OBJ * IN_F];
__device__ float g_aggRO[(size_t)N_OBJ * IN_F];
__device__ float g_aggAO[(size_t)N_OBJ * IN_F];
__device__ float g_hobj [(size_t)N_OBJ * HDIM];
__device__ float g_agg2 [(size_t)N_OBJ * HDIM];
__device__ int   g_dout_oo[N_OBJ];
__device__ int   g_din_oo [N_OBJ];
__device__ int   g_dout_ro[N_ROOM];
__device__ int   g_din_ro [N_OBJ];
__device__ int   g_dout_ao[N_ATTR];
__device__ int   g_din_ao [N_OBJ];

// ---------------- zero scratch ----------------
__global__ void zero_scratch() {
    size_t tid    = (size_t)blockIdx.x * blockDim.x + threadIdx.x;
    size_t stride = (size_t)gridDim.x * blockDim.x;
    float4 z4 = make_float4(0.f, 0.f, 0.f, 0.f);
    int4   zi = make_int4(0, 0, 0, 0);

    const size_t nA = (size_t)N_OBJ * IN_F / 4;
    float4* a0 = (float4*)g_aggOO;
    float4* a1 = (float4*)g_aggRO;
    float4* a2 = (float4*)g_aggAO;
    for (size_t i = tid; i < nA; i += stride) { a0[i] = z4; a1[i] = z4; a2[i] = z4; }

    float4* a3 = (float4*)g_agg2;
    for (size_t i = tid; i < (size_t)N_OBJ * HDIM / 4; i += stride) a3[i] = z4;

    int4* d0 = (int4*)g_dout_oo;
    int4* d1 = (int4*)g_din_oo;
    int4* d2 = (int4*)g_din_ro;
    int4* d3 = (int4*)g_din_ao;
    for (size_t i = tid; i < N_OBJ / 4; i += stride) { d0[i] = zi; d1[i] = zi; d2[i] = zi; d3[i] = zi; }
    int4* d4 = (int4*)g_dout_ao;
    for (size_t i = tid; i < N_ATTR / 4; i += stride) d4[i] = zi;
    int4* d5 = (int4*)g_dout_ro;
    for (size_t i = tid; i < N_ROOM / 4; i += stride) d5[i] = zi;
}

// ---------------- degree counting ----------------
template <int SEL>
__global__ void deg_kernel(const int* __restrict__ src, const int* __restrict__ dst, int E) {
    int* dout = (SEL == 0) ? g_dout_oo : (SEL == 1) ? g_dout_ro : g_dout_ao;
    int* din  = (SEL == 0) ? g_din_oo  : (SEL == 1) ? g_din_ro  : g_din_ao;
    int i = blockIdx.x * blockDim.x + threadIdx.x;
    if (i < E) {
        atomicAdd(&dout[src[i]], 1);
        atomicAdd(&din [dst[i]], 1);
    }
}

// ---------------- vectorized global reduction-add ----------------
__device__ __forceinline__ void red_add_v4(float4* p, float4 v) {
    asm volatile("red.global.add.v4.f32 [%0], {%1, %2, %3, %4};"
                 :: "l"(p), "f"(v.x), "f"(v.y), "f"(v.z), "f"(v.w)
                 : "memory");
}

// ---------------- conv1 aggregation (300-dim), one warp per edge ----------------
template <int SEL>
__global__ void agg_feat(const float* __restrict__ feat,
                         const int* __restrict__ src, const int* __restrict__ dst, int E) {
    const int* degout = (SEL == 0) ? g_dout_oo : (SEL == 1) ? g_dout_ro : g_dout_ao;
    float*     aggp   = (SEL == 0) ? g_aggOO   : (SEL == 1) ? g_aggRO   : g_aggAO;
    int e = (blockIdx.x * blockDim.x + threadIdx.x) >> 5;
    if (e >= E) return;
    int lane = threadIdx.x & 31;
    int s = src[e], d = dst[e];
    float ns = rsqrtf((float)max(degout[s], 1));
    const float4* fs = (const float4*)(feat + (size_t)s * IN_F);
    float4*       ad = (float4*)(aggp + (size_t)d * IN_F);
    for (int j = lane; j < IN_F / 4; j += 32) {
        float4 v = fs[j];
        v.x *= ns; v.y *= ns; v.z *= ns; v.w *= ns;
        red_add_v4(ad + j, v);
    }
}

// ---------------- conv2 aggregation (512-dim), one warp per edge ----------------
__global__ void agg_h(const int* __restrict__ src, const int* __restrict__ dst, int E) {
    int e = (blockIdx.x * blockDim.x + threadIdx.x) >> 5;
    if (e >= E) return;
    int lane = threadIdx.x & 31;
    int s = src[e], d = dst[e];
    float ns = rsqrtf((float)max(g_dout_oo[s], 1));
    const float4* fs = (const float4*)(g_hobj + (size_t)s * HDIM);
    float4*       ad = (float4*)(g_agg2 + (size_t)d * HDIM);
    #pragma unroll
    for (int j = lane; j < HDIM / 4; j += 32) {
        float4 v = fs[j];
        v.x *= ns; v.y *= ns; v.z *= ns; v.w *= ns;
        red_add_v4(ad + j, v);
    }
}

// ---------------- SGEMM with fused GCN epilogue ----------------
// MODE 0: hobj  = relu(aggOO*nd @ W + b) / 3          (K=300)
// MODE 1: hobj += relu(aggRO*nd @ W + b) / 3          (K=300)
// MODE 2: hobj += relu(aggAO*nd @ W + b) / 3          (K=300)
// MODE 3: out[b] = agg2*nd @ W + b2  broadcast x8     (K=512)
#define BM 128
#define BN 128
#define BK 8
#define TM 8
#define TN 8

template <int MODE, int K>
__global__ void __launch_bounds__(256) sgemm(const float* __restrict__ Bw,
                                             const float* __restrict__ bias,
                                             float* __restrict__ outp) {
    const float* A;
    const int*   degin;
    float*       C;
    if      (MODE == 0) { A = g_aggOO; degin = g_din_oo; C = g_hobj; }
    else if (MODE == 1) { A = g_aggRO; degin = g_din_ro; C = g_hobj; }
    else if (MODE == 2) { A = g_aggAO; degin = g_din_ao; C = g_hobj; }
    else                { A = g_agg2;  degin = g_din_oo; C = outp;  }
    const int M = N_OBJ, N = HDIM;

    __shared__ float As[BK][BM];
    __shared__ float Bs[BK][BN];

    int tid  = threadIdx.x;
    int row0 = blockIdx.y * BM;
    int col0 = blockIdx.x * BN;
    int tx = tid & 15, ty = tid >> 4;

    float acc[TM][TN] = {};

    int aR = tid >> 1;            // A tile row 0..127
    int aC = (tid & 1) * 4;       // A tile k-offset 0 or 4
    int bK = tid >> 5;            // B tile k-row 0..7
    int bC = (tid & 31) * 4;      // B tile col 0..124

    const int NT = (K + BK - 1) / BK;
    for (int t = 0; t < NT; t++) {
        int k0 = t * BK;
        // load A tile (transposed into As[k][row]), guard M and K edges
        {
            int gr = row0 + aR;
            float4 v = make_float4(0.f, 0.f, 0.f, 0.f);
            if (gr < M && k0 + aC < K) {
                if (k0 + aC + 3 < K) {
                    v = *(const float4*)(A + (size_t)gr * K + k0 + aC);
                } else {
                    const float* p = A + (size_t)gr * K + k0 + aC;
                    v.x = p[0];
                    if (k0 + aC + 1 < K) v.y = p[1];
                    if (k0 + aC + 2 < K) v.z = p[2];
                }
            }
            As[aC + 0][aR] = v.x; As[aC + 1][aR] = v.y;
            As[aC + 2][aR] = v.z; As[aC + 3][aR] = v.w;
        }
        // load B tile (coalesced float4)
        {
            float4 v = make_float4(0.f, 0.f, 0.f, 0.f);
            if (k0 + bK < K)
                v = *(const float4*)(Bw + (size_t)(k0 + bK) * N + col0 + bC);
            *(float4*)&Bs[bK][bC] = v;
        }
        __syncthreads();
        #pragma unroll
        for (int k = 0; k < BK; k++) {
            float ra[TM], rb[TN];
            #pragma unroll
            for (int i = 0; i < TM; i++) ra[i] = As[k][ty * TM + i];
            #pragma unroll
            for (int j = 0; j < TN; j++) rb[j] = Bs[k][tx * TN + j];
            #pragma unroll
            for (int i = 0; i < TM; i++)
                #pragma unroll
                for (int j = 0; j < TN; j++)
                    acc[i][j] += ra[i] * rb[j];
        }
        __syncthreads();
    }

    // epilogue: apply dst-norm (commutes through GEMM), bias, relu/mean or broadcast
    #pragma unroll
    for (int i = 0; i < TM; i++) {
        int r = row0 + ty * TM + i;
        if (r >= M) break;
        float nd = rsqrtf((float)max(degin[r], 1));
        #pragma unroll
        for (int j = 0; j < TN; j += 4) {
            int c = col0 + tx * TN + j;
            float4 v;
            v.x = acc[i][j + 0] * nd + bias[c + 0];
            v.y = acc[i][j + 1] * nd + bias[c + 1];
            v.z = acc[i][j + 2] * nd + bias[c + 2];
            v.w = acc[i][j + 3] * nd + bias[c + 3];
            if (MODE < 3) {
                const float third = 1.f / 3.f;
                v.x = fmaxf(v.x, 0.f) * third;
                v.y = fmaxf(v.y, 0.f) * third;
                v.z = fmaxf(v.z, 0.f) * third;
                v.w = fmaxf(v.w, 0.f) * third;
                if (MODE > 0) {
                    float4 pr = *(float4*)(C + (size_t)r * N + c);
                    v.x += pr.x; v.y += pr.y; v.z += pr.z; v.w += pr.w;
                }
                *(float4*)(C + (size_t)r * N + c) = v;
            } else {
                #pragma unroll
                for (int b = 0; b < BATCH; b++)
                    *(float4*)(C + (size_t)b * M * N + (size_t)r * N + c) = v;
            }
        }
    }
}

// ---------------- launch ----------------
extern "C" void kernel_launch(void* const* d_in, const int* in_sizes, int n_in,
                              void* d_out, int out_size) {
    const float* feat_obj  = (const float*)d_in[1];
    const float* feat_room = (const float*)d_in[2];
    const float* feat_attr = (const float*)d_in[3];
    const float* W1i = (const float*)d_in[4];
    const float* b1i = (const float*)d_in[5];
    const float* W1b = (const float*)d_in[6];
    const float* b1b = (const float*)d_in[7];
    const float* W2  = (const float*)d_in[8];
    const float* b2  = (const float*)d_in[9];
    const int* src_oo = (const int*)d_in[10];
    const int* dst_oo = (const int*)d_in[11];
    const int* src_ro = (const int*)d_in[12];
    const int* dst_ro = (const int*)d_in[13];
    const int* src_ao = (const int*)d_in[14];
    const int* dst_ao = (const int*)d_in[15];
    float* out = (float*)d_out;

    zero_scratch<<<2048, 256>>>();

    deg_kernel<0><<<(EOO + 255) / 256, 256>>>(src_oo, dst_oo, EOO);
    deg_kernel<1><<<(ERO + 255) / 256, 256>>>(src_ro, dst_ro, ERO);
    deg_kernel<2><<<(EAO + 255) / 256, 256>>>(src_ao, dst_ao, EAO);

    // conv1 aggregation: one warp per edge (8 edges / 256-thread block)
    agg_feat<0><<<(EOO + 7) / 8, 256>>>(feat_obj,  src_oo, dst_oo, EOO);
    agg_feat<1><<<(ERO + 7) / 8, 256>>>(feat_room, src_ro, dst_ro, ERO);
    agg_feat<2><<<(EAO + 7) / 8, 256>>>(feat_attr, src_ao, dst_ao, EAO);

    dim3 grid1(HDIM / BN, (N_OBJ + BM - 1) / BM);
    sgemm<0, IN_F><<<grid1, 256>>>(W1i, b1i, out);
    sgemm<1, IN_F><<<grid1, 256>>>(W1i, b1i, out);
    sgemm<2, IN_F><<<grid1, 256>>>(W1b, b1b, out);

    // conv2 aggregation over object->object edges in H=512
    agg_h<<<(EOO + 7) / 8, 256>>>(src_oo, dst_oo, EOO);

    sgemm<3, HDIM><<<grid1, 256>>>(W2, b2, out);
}

// round 2
// speedup vs baseline: 1.4605x; 1.4605x over previous
#include <cuda_runtime.h>
#include <cuda_bf16.h>
#include <cstdint>

#define N_OBJ  20000
#define N_ROOM 500
#define N_ATTR 2000
#define IN_F   300
#define HDIM   512
#define EOO    640000
#define ERO    50000
#define EAO    100000
#define BATCH  8

#define MP   20096          // N_OBJ padded to 128
#define KP1  304            // IN_F padded to 16
#define KP2  512

// ---------------- scratch (device globals, no allocation) ----------------
__device__ float g_aggOO[(size_t)N_OBJ * IN_F];
__device__ float g_aggRO[(size_t)N_OBJ * IN_F];
__device__ float g_aggAO[(size_t)N_OBJ * IN_F];
__device__ float g_hobj [(size_t)N_OBJ * HDIM];
__device__ float g_agg2 [(size_t)N_OBJ * HDIM];
__device__ int   g_dout_oo[N_OBJ];
__device__ int   g_din_oo [N_OBJ];
__device__ int   g_dout_ro[N_ROOM];
__device__ int   g_din_ro [N_OBJ];
__device__ int   g_dout_ao[N_ATTR];
__device__ int   g_din_ao [N_OBJ];

// bf16 hi/lo split buffers (padded, zero-filled by conversion kernels)
__device__ __nv_bfloat16 g_A1hi[3][(size_t)MP * KP1];
__device__ __nv_bfloat16 g_A1lo[3][(size_t)MP * KP1];
__device__ __nv_bfloat16 g_A2hi[(size_t)MP * KP2];
__device__ __nv_bfloat16 g_A2lo[(size_t)MP * KP2];
__device__ __nv_bfloat16 g_Whi[3][(size_t)KP2 * HDIM];   // 0:W1i 1:W1b 2:W2
__device__ __nv_bfloat16 g_Wlo[3][(size_t)KP2 * HDIM];

// ---------------- zero scratch ----------------
__global__ void zero_scratch() {
    size_t tid    = (size_t)blockIdx.x * blockDim.x + threadIdx.x;
    size_t stride = (size_t)gridDim.x * blockDim.x;
    float4 z4 = make_float4(0.f, 0.f, 0.f, 0.f);
    int4   zi = make_int4(0, 0, 0, 0);

    const size_t nA = (size_t)N_OBJ * IN_F / 4;
    float4* a0 = (float4*)g_aggOO;
    float4* a1 = (float4*)g_aggRO;
    float4* a2 = (float4*)g_aggAO;
    for (size_t i = tid; i < nA; i += stride) { a0[i] = z4; a1[i] = z4; a2[i] = z4; }

    float4* a3 = (float4*)g_agg2;
    for (size_t i = tid; i < (size_t)N_OBJ * HDIM / 4; i += stride) a3[i] = z4;

    int4* d0 = (int4*)g_dout_oo;
    int4* d1 = (int4*)g_din_oo;
    int4* d2 = (int4*)g_din_ro;
    int4* d3 = (int4*)g_din_ao;
    for (size_t i = tid; i < N_OBJ / 4; i += stride) { d0[i] = zi; d1[i] = zi; d2[i] = zi; d3[i] = zi; }
    int4* d4 = (int4*)g_dout_ao;
    for (size_t i = tid; i < N_ATTR / 4; i += stride) d4[i] = zi;
    int4* d5 = (int4*)g_dout_ro;
    for (size_t i = tid; i < N_ROOM / 4; i += stride) d5[i] = zi;
}

// ---------------- degree counting ----------------
template <int SEL>
__global__ void deg_kernel(const int* __restrict__ src, const int* __restrict__ dst, int E) {
    int* dout = (SEL == 0) ? g_dout_oo : (SEL == 1) ? g_dout_ro : g_dout_ao;
    int* din  = (SEL == 0) ? g_din_oo  : (SEL == 1) ? g_din_ro  : g_din_ao;
    int i = blockIdx.x * blockDim.x + threadIdx.x;
    if (i < E) {
        atomicAdd(&dout[src[i]], 1);
        atomicAdd(&din [dst[i]], 1);
    }
}

// ---------------- vectorized global reduction-add ----------------
__device__ __forceinline__ void red_add_v4(float4* p, float4 v) {
    asm volatile("red.global.add.v4.f32 [%0], {%1, %2, %3, %4};"
                 :: "l"(p), "f"(v.x), "f"(v.y), "f"(v.z), "f"(v.w)
                 : "memory");
}

// ---------------- conv1 aggregation (300-dim), one warp per edge ----------------
template <int SEL>
__global__ void agg_feat(const float* __restrict__ feat,
                         const int* __restrict__ src, const int* __restrict__ dst, int E) {
    const int* degout = (SEL == 0) ? g_dout_oo : (SEL == 1) ? g_dout_ro : g_dout_ao;
    float*     aggp   = (SEL == 0) ? g_aggOO   : (SEL == 1) ? g_aggRO   : g_aggAO;
    int e = (blockIdx.x * blockDim.x + threadIdx.x) >> 5;
    if (e >= E) return;
    int lane = threadIdx.x & 31;
    int s = src[e], d = dst[e];
    float ns = rsqrtf((float)max(degout[s], 1));
    const float4* fs = (const float4*)(feat + (size_t)s * IN_F);
    float4*       ad = (float4*)(aggp + (size_t)d * IN_F);
    for (int j = lane; j < IN_F / 4; j += 32) {
        float4 v = fs[j];
        v.x *= ns; v.y *= ns; v.z *= ns; v.w *= ns;
        red_add_v4(ad + j, v);
    }
}

// ---------------- conv2 aggregation (512-dim), one warp per edge ----------------
__global__ void agg_h(const int* __restrict__ src, const int* __restrict__ dst, int E) {
    int e = (blockIdx.x * blockDim.x + threadIdx.x) >> 5;
    if (e >= E) return;
    int lane = threadIdx.x & 31;
    int s = src[e], d = dst[e];
    float ns = rsqrtf((float)max(g_dout_oo[s], 1));
    const float4* fs = (const float4*)(g_hobj + (size_t)s * HDIM);
    float4*       ad = (float4*)(g_agg2 + (size_t)d * HDIM);
    #pragma unroll
    for (int j = lane; j < HDIM / 4; j += 32) {
        float4 v = fs[j];
        v.x *= ns; v.y *= ns; v.z *= ns; v.w *= ns;
        red_add_v4(ad + j, v);
    }
}

// ---------------- fp32 -> bf16 hi/lo split, with padding ----------------
// sel 0..2: conv1 agg matrices (K=300 -> KP1), sel 3: g_agg2 (K=512)
__global__ void conv_a(int sel) {
    const float* src;
    __nv_bfloat16 *hi, *lo;
    int K, KPv;
    if (sel < 3) {
        src = (sel == 0) ? g_aggOO : (sel == 1) ? g_aggRO : g_aggAO;
        hi = g_A1hi[sel]; lo = g_A1lo[sel]; K = IN_F; KPv = KP1;
    } else {
        src = g_agg2; hi = g_A2hi; lo = g_A2lo; K = HDIM; KPv = KP2;
    }
    size_t n = (size_t)MP * KPv;
    size_t stride = (size_t)gridDim.x * blockDim.x;
    for (size_t idx = (size_t)blockIdx.x * blockDim.x + threadIdx.x; idx < n; idx += stride) {
        int r = (int)(idx / KPv);
        int k = (int)(idx % KPv);
        float x = (r < N_OBJ && k < K) ? src[(size_t)r * K + k] : 0.f;
        __nv_bfloat16 h = __float2bfloat16(x);
        float res = x - __bfloat162float(h);
        hi[idx] = h;
        lo[idx] = __float2bfloat16(res);
    }
}

// weight split: src is [K][512] fp32, dst [KPv][512] bf16 (zero pad rows)
__global__ void conv_w(const float* __restrict__ src, int sel, int K) {
    __nv_bfloat16* hi = g_Whi[sel];
    __nv_bfloat16* lo = g_Wlo[sel];
    int KPv = (K == IN_F) ? KP1 : KP2;
    size_t n = (size_t)KPv * HDIM;
    size_t stride = (size_t)gridDim.x * blockDim.x;
    for (size_t idx = (size_t)blockIdx.x * blockDim.x + threadIdx.x; idx < n; idx += stride) {
        int r = (int)(idx / HDIM);
        float x = (r < K) ? src[idx] : 0.f;
        __nv_bfloat16 h = __float2bfloat16(x);
        float res = x - __bfloat162float(h);
        hi[idx] = h;
        lo[idx] = __float2bfloat16(res);
    }
}

// ---------------- bf16x3 tensor-core GEMM with fused GCN epilogue ----------------
// MODE 0: hobj  = relu(A*nd @ W + b) / 3     (KP1)
// MODE 1: hobj += relu(A*nd @ W + b) / 3     (KP1)
// MODE 2: hobj += relu(A*nd @ W + b) / 3     (KP1)
// MODE 3: out[b] = A*nd @ W + b, broadcast 8 (KP2)

__device__ __forceinline__ void cpasync16(void* smem_dst, const void* gmem_src) {
    uint32_t sa = (uint32_t)__cvta_generic_to_shared(smem_dst);
    asm volatile("cp.async.cg.shared.global [%0], [%1], 16;\n" :: "r"(sa), "l"(gmem_src));
}
__device__ __forceinline__ void cp_commit() { asm volatile("cp.async.commit_group;\n" ::: "memory"); }
template <int N>
__device__ __forceinline__ void cp_wait() { asm volatile("cp.async.wait_group %0;\n" :: "n"(N) : "memory"); }

__device__ __forceinline__ void ldsm4(uint32_t* r, const void* p) {
    uint32_t a = (uint32_t)__cvta_generic_to_shared(p);
    asm volatile("ldmatrix.sync.aligned.m8n8.x4.shared.b16 {%0,%1,%2,%3}, [%4];\n"
                 : "=r"(r[0]), "=r"(r[1]), "=r"(r[2]), "=r"(r[3]) : "r"(a));
}
__device__ __forceinline__ void ldsm4t(uint32_t* r, const void* p) {
    uint32_t a = (uint32_t)__cvta_generic_to_shared(p);
    asm volatile("ldmatrix.sync.aligned.m8n8.x4.trans.shared.b16 {%0,%1,%2,%3}, [%4];\n"
                 : "=r"(r[0]), "=r"(r[1]), "=r"(r[2]), "=r"(r[3]) : "r"(a));
}
__device__ __forceinline__ void mma_bf16(float* d, const uint32_t* a, uint32_t b0, uint32_t b1) {
    asm volatile("mma.sync.aligned.m16n8k16.row.col.f32.bf16.bf16.f32 "
                 "{%0,%1,%2,%3}, {%4,%5,%6,%7}, {%8,%9}, {%0,%1,%2,%3};\n"
                 : "+f"(d[0]), "+f"(d[1]), "+f"(d[2]), "+f"(d[3])
                 : "r"(a[0]), "r"(a[1]), "r"(a[2]), "r"(a[3]), "r"(b0), "r"(b1));
}

template <int MODE, int KP>
__global__ void __launch_bounds__(256) gemm_bf16(const float* __restrict__ bias,
                                                 float* __restrict__ outp) {
    const __nv_bfloat16 *Ahi, *Alo, *Bhi, *Blo;
    const int* degin;
    float* C;
    if      (MODE == 0) { Ahi = g_A1hi[0]; Alo = g_A1lo[0]; Bhi = g_Whi[0]; Blo = g_Wlo[0]; degin = g_din_oo; C = g_hobj; }
    else if (MODE == 1) { Ahi = g_A1hi[1]; Alo = g_A1lo[1]; Bhi = g_Whi[0]; Blo = g_Wlo[0]; degin = g_din_ro; C = g_hobj; }
    else if (MODE == 2) { Ahi = g_A1hi[2]; Alo = g_A1lo[2]; Bhi = g_Whi[1]; Blo = g_Wlo[1]; degin = g_din_ao; C = g_hobj; }
    else                { Ahi = g_A2hi;    Alo = g_A2lo;    Bhi = g_Whi[2]; Blo = g_Wlo[2]; degin = g_din_oo; C = outp; }

    const int NT = KP / 16;
    __shared__ __align__(16) __nv_bfloat16 sA[2][2][128][24];   // [stage][hi/lo][m][k pad24]
    __shared__ __align__(16) __nv_bfloat16 sB[2][2][16][136];   // [stage][hi/lo][k][n pad136]

    int tid  = threadIdx.x;
    int warp = tid >> 5, lane = tid & 31;
    int row0 = blockIdx.y * 128, col0 = blockIdx.x * 128;
    int wr = warp >> 2, wc = warp & 3;  // 2x4 warp grid, warp tile 64x32

    float acc[4][4][4] = {};

    // per-thread load assignments
    int aArr0 = 0,        aR0 = tid >> 1,  aC0 = tid & 1;
    int aArr1 = 1,        aR1 = tid >> 1,  aC1 = tid & 1;
    int bArr0 = 0,        bR0 = tid >> 4,  bC0 = tid & 15;
    int bArr1 = 1,        bR1 = tid >> 4,  bC1 = tid & 15;

    auto load_stage = [&](int t, int s) {
        cpasync16(&sA[s][aArr0][aR0][aC0 * 8], Ahi + (size_t)(row0 + aR0) * KP + t * 16 + aC0 * 8);
        cpasync16(&sA[s][aArr1][aR1][aC1 * 8], Alo + (size_t)(row0 + aR1) * KP + t * 16 + aC1 * 8);
        cpasync16(&sB[s][bArr0][bR0][bC0 * 8], Bhi + (size_t)(t * 16 + bR0) * HDIM + col0 + bC0 * 8);
        cpasync16(&sB[s][bArr1][bR1][bC1 * 8], Blo + (size_t)(t * 16 + bR1) * HDIM + col0 + bC1 * 8);
    };

    load_stage(0, 0);
    cp_commit();

    for (int t = 0; t < NT; t++) {
        int s = t & 1;
        if (t + 1 < NT) { load_stage(t + 1, s ^ 1); }
        cp_commit();
        cp_wait<1>();
        __syncthreads();

        uint32_t ahi[4][4], alo[4][4], bhi[2][4], blo[2][4];
        int arow = wr * 64 + (lane & 15);
        int acol = (lane >> 4) * 8;
        #pragma unroll
        for (int m = 0; m < 4; m++) {
            ldsm4(ahi[m], &sA[s][0][arow + m * 16][acol]);
            ldsm4(alo[m], &sA[s][1][arow + m * 16][acol]);
        }
        int brow = lane & 15;
        int bcol = wc * 32 + (lane >> 4) * 8;
        #pragma unroll
        for (int p = 0; p < 2; p++) {
            ldsm4t(bhi[p], &sB[s][0][brow][bcol + p * 16]);
            ldsm4t(blo[p], &sB[s][1][brow][bcol + p * 16]);
        }

        #pragma unroll
        for (int m = 0; m < 4; m++)
            #pragma unroll
            for (int n = 0; n < 4; n++) {
                int p = n >> 1, h = n & 1;
                mma_bf16(acc[m][n], ahi[m], bhi[p][h * 2], bhi[p][h * 2 + 1]);
                mma_bf16(acc[m][n], ahi[m], blo[p][h * 2], blo[p][h * 2 + 1]);
                mma_bf16(acc[m][n], alo[m], bhi[p][h * 2], bhi[p][h * 2 + 1]);
            }
        __syncthreads();
    }

    // epilogue
    #pragma unroll
    for (int m = 0; m < 4; m++) {
        int r1 = row0 + wr * 64 + m * 16 + (lane >> 2);
        int r2 = r1 + 8;
        float nd1 = (r1 < N_OBJ) ? rsqrtf((float)max(degin[r1], 1)) : 0.f;
        float nd2 = (r2 < N_OBJ) ? rsqrtf((float)max(degin[r2], 1)) : 0.f;
        #pragma unroll
        for (int n = 0; n < 4; n++) {
            int c = col0 + wc * 32 + n * 8 + (lane & 3) * 2;
            float bx = bias[c], by = bias[c + 1];
            // row r1 : d0,d1 ; row r2 : d2,d3
            #pragma unroll
            for (int h = 0; h < 2; h++) {
                int r = h ? r2 : r1;
                if (r >= N_OBJ) continue;
                float nd = h ? nd2 : nd1;
                float vx = acc[m][n][h * 2 + 0] * nd + bx;
                float vy = acc[m][n][h * 2 + 1] * nd + by;
                if (MODE < 3) {
                    const float third = 1.f / 3.f;
                    vx = fmaxf(vx, 0.f) * third;
                    vy = fmaxf(vy, 0.f) * third;
                    float* p = C + (size_t)r * HDIM + c;
                    if (MODE > 0) {
                        float2 pr = *(float2*)p;
                        vx += pr.x; vy += pr.y;
                    }
                    *(float2*)p = make_float2(vx, vy);
                } else {
                    #pragma unroll
                    for (int b = 0; b < BATCH; b++) {
                        float* p = C + (size_t)b * N_OBJ * HDIM + (size_t)r * HDIM + c;
                        *(float2*)p = make_float2(vx, vy);
                    }
                }
            }
        }
    }
}

// ---------------- launch ----------------
extern "C" void kernel_launch(void* const* d_in, const int* in_sizes, int n_in,
                              void* d_out, int out_size) {
    const float* feat_obj  = (const float*)d_in[1];
    const float* feat_room = (const float*)d_in[2];
    const float* feat_attr = (const float*)d_in[3];
    const float* W1i = (const float*)d_in[4];
    const float* b1i = (const float*)d_in[5];
    const float* W1b = (const float*)d_in[6];
    const float* b1b = (const float*)d_in[7];
    const float* W2  = (const float*)d_in[8];
    const float* b2  = (const float*)d_in[9];
    const int* src_oo = (const int*)d_in[10];
    const int* dst_oo = (const int*)d_in[11];
    const int* src_ro = (const int*)d_in[12];
    const int* dst_ro = (const int*)d_in[13];
    const int* src_ao = (const int*)d_in[14];
    const int* dst_ao = (const int*)d_in[15];
    float* out = (float*)d_out;

    zero_scratch<<<2048, 256>>>();

    deg_kernel<0><<<(EOO + 255) / 256, 256>>>(src_oo, dst_oo, EOO);
    deg_kernel<1><<<(ERO + 255) / 256, 256>>>(src_ro, dst_ro, ERO);
    deg_kernel<2><<<(EAO + 255) / 256, 256>>>(src_ao, dst_ao, EAO);

    // weight splits (independent of aggregation)
    conv_w<<<256, 256>>>(W1i, 0, IN_F);
    conv_w<<<256, 256>>>(W1b, 1, IN_F);
    conv_w<<<256, 256>>>(W2,  2, HDIM);

    // conv1 aggregation: one warp per edge
    agg_feat<0><<<(EOO + 7) / 8, 256>>>(feat_obj,  src_oo, dst_oo, EOO);
    agg_feat<1><<<(ERO + 7) / 8, 256>>>(feat_room, src_ro, dst_ro, ERO);
    agg_feat<2><<<(EAO + 7) / 8, 256>>>(feat_attr, src_ao, dst_ao, EAO);

    // split aggregated activations into bf16 hi/lo
    conv_a<<<4096, 256>>>(0);
    conv_a<<<4096, 256>>>(1);
    conv_a<<<4096, 256>>>(2);

    dim3 grid(HDIM / 128, (N_OBJ + 127) / 128);
    gemm_bf16<0, KP1><<<grid, 256>>>(b1i, out);
    gemm_bf16<1, KP1><<<grid, 256>>>(b1i, out);
    gemm_bf16<2, KP1><<<grid, 256>>>(b1b, out);

    // conv2 aggregation over object->object edges in H=512
    agg_h<<<(EOO + 7) / 8, 256>>>(src_oo, dst_oo, EOO);
    conv_a<<<4096, 256>>>(3);

    gemm_bf16<3, KP2><<<grid, 256>>>(b2, out);
}

// round 3
// speedup vs baseline: 1.8864x; 1.2916x over previous
#include <cuda_runtime.h>
#include <cuda_bf16.h>
#include <cstdint>

#define N_OBJ  20000
#define N_ROOM 500
#define N_ATTR 2000
#define IN_F   300
#define HDIM   512
#define EOO    640000
#define ERO    50000
#define EAO    100000
#define BATCH  8

#define MP   20096          // N_OBJ padded to 128
#define KP1  304            // IN_F padded to 16
#define KP2  512

// ---------------- scratch (device globals, no allocation) ----------------
__device__ float g_fobj_n [(size_t)N_OBJ  * IN_F];   // src-normalized features
__device__ float g_froom_n[(size_t)N_ROOM * IN_F];
__device__ float g_fattr_n[(size_t)N_ATTR * IN_F];
__device__ float g_hs     [(size_t)N_OBJ  * HDIM];   // h_obj * ns_oo (conv2 input)

__device__ int g_dout_oo[N_OBJ];
__device__ int g_din_oo [N_OBJ];
__device__ int g_dout_ro[N_ROOM];
__device__ int g_din_ro [N_OBJ];
__device__ int g_dout_ao[N_ATTR];
__device__ int g_din_ao [N_OBJ];

__device__ int g_off_oo[N_OBJ + 1];
__device__ int g_off_ro[N_OBJ + 1];
__device__ int g_off_ao[N_OBJ + 1];
__device__ int g_cnt_oo[N_OBJ];
__device__ int g_cnt_ro[N_OBJ];
__device__ int g_cnt_ao[N_OBJ];
__device__ int g_csr_oo[EOO];
__device__ int g_csr_ro[ERO];
__device__ int g_csr_ao[EAO];

// bf16 hi/lo split operands (written directly by aggregation kernels)
__device__ __nv_bfloat16 g_A1hi[3][(size_t)MP * KP1];
__device__ __nv_bfloat16 g_A1lo[3][(size_t)MP * KP1];
__device__ __nv_bfloat16 g_A2hi[(size_t)MP * KP2];
__device__ __nv_bfloat16 g_A2lo[(size_t)MP * KP2];
__device__ __nv_bfloat16 g_Whi[3][(size_t)KP2 * HDIM];   // 0:W1i 1:W1b 2:W2
__device__ __nv_bfloat16 g_Wlo[3][(size_t)KP2 * HDIM];

// ---------------- zero small scratch (degrees + pad rows) ----------------
__global__ void zero_small() {
    int tid    = blockIdx.x * blockDim.x + threadIdx.x;
    int stride = gridDim.x * blockDim.x;
    for (int i = tid; i < N_OBJ; i += stride) {
        g_dout_oo[i] = 0; g_din_oo[i] = 0; g_din_ro[i] = 0; g_din_ao[i] = 0;
    }
    for (int i = tid; i < N_ROOM; i += stride) g_dout_ro[i] = 0;
    for (int i = tid; i < N_ATTR; i += stride) g_dout_ao[i] = 0;
    // pad rows [N_OBJ, MP)
    const __nv_bfloat16 z = __float2bfloat16(0.f);
    int padA1 = (MP - N_OBJ) * KP1;
    for (int i = tid; i < padA1; i += stride) {
        size_t o = (size_t)N_OBJ * KP1 + i;
        g_A1hi[0][o] = z; g_A1lo[0][o] = z;
        g_A1hi[1][o] = z; g_A1lo[1][o] = z;
        g_A1hi[2][o] = z; g_A1lo[2][o] = z;
    }
    int padA2 = (MP - N_OBJ) * KP2;
    for (int i = tid; i < padA2; i += stride) {
        size_t o = (size_t)N_OBJ * KP2 + i;
        g_A2hi[o] = z; g_A2lo[o] = z;
    }
}

// ---------------- degree counting ----------------
template <int SEL>
__global__ void deg_kernel(const int* __restrict__ src, const int* __restrict__ dst, int E) {
    int* dout = (SEL == 0) ? g_dout_oo : (SEL == 1) ? g_dout_ro : g_dout_ao;
    int* din  = (SEL == 0) ? g_din_oo  : (SEL == 1) ? g_din_ro  : g_din_ao;
    int i = blockIdx.x * blockDim.x + threadIdx.x;
    if (i < E) {
        atomicAdd(&dout[src[i]], 1);
        atomicAdd(&din [dst[i]], 1);
    }
}

// ---------------- pre-scale features by src norm ----------------
template <int SEL>
__global__ void fscale(const float* __restrict__ feat) {
    const int* dout; float* out; int n;
    if      (SEL == 0) { dout = g_dout_oo; out = g_fobj_n;  n = N_OBJ;  }
    else if (SEL == 1) { dout = g_dout_ro; out = g_froom_n; n = N_ROOM; }
    else               { dout = g_dout_ao; out = g_fattr_n; n = N_ATTR; }
    size_t tot = (size_t)n * IN_F;
    size_t stride = (size_t)gridDim.x * blockDim.x;
    for (size_t i = (size_t)blockIdx.x * blockDim.x + threadIdx.x; i < tot; i += stride) {
        int r = (int)(i / IN_F);
        float ns = rsqrtf((float)max(dout[r], 1));
        out[i] = feat[i] * ns;
    }
}

// ---------------- exclusive scan of in-degrees -> CSR offsets ----------------
template <int SEL>
__global__ void scan_deg() {
    const int* deg = (SEL == 0) ? g_din_oo : (SEL == 1) ? g_din_ro : g_din_ao;
    int* offs      = (SEL == 0) ? g_off_oo : (SEL == 1) ? g_off_ro : g_off_ao;
    int* cnt       = (SEL == 0) ? g_cnt_oo : (SEL == 1) ? g_cnt_ro : g_cnt_ao;
    __shared__ int part[1025];
    const int n = N_OBJ;
    int t = threadIdx.x;                 // 1024 threads
    int chunk = (n + 1023) / 1024;
    int b = t * chunk, e = min(b + chunk, n);
    int s = 0;
    for (int i = b; i < e; i++) s += deg[i];
    part[t + 1] = s;
    if (t == 0) part[0] = 0;
    __syncthreads();
    for (int off = 1; off < 1024; off <<= 1) {
        int v = part[t + 1];
        if (t + 1 > off) v += part[t + 1 - off];
        __syncthreads();
        part[t + 1] = v;
        __syncthreads();
    }
    int run = part[t];
    for (int i = b; i < e; i++) { offs[i] = run; cnt[i] = run; run += deg[i]; }
    if (t == 0) offs[n] = part[1024];
}

// ---------------- scatter edges into CSR (by dst) ----------------
template <int SEL>
__global__ void scatter_edges(const int* __restrict__ src, const int* __restrict__ dst, int E) {
    int* cnt = (SEL == 0) ? g_cnt_oo : (SEL == 1) ? g_cnt_ro : g_cnt_ao;
    int* csr = (SEL == 0) ? g_csr_oo : (SEL == 1) ? g_csr_ro : g_csr_ao;
    int i = blockIdx.x * blockDim.x + threadIdx.x;
    if (i < E) {
        int pos = atomicAdd(&cnt[dst[i]], 1);
        csr[pos] = src[i];
    }
}

// ---------------- conv1 aggregation: one block per dst row, CSR gather-sum ----
// writes bf16 hi/lo padded operand directly
template <int SEL>
__global__ void __launch_bounds__(128) agg1() {
    const float* feat = (SEL == 0) ? g_fobj_n : (SEL == 1) ? g_froom_n : g_fattr_n;
    const int* offs   = (SEL == 0) ? g_off_oo : (SEL == 1) ? g_off_ro : g_off_ao;
    const int* csr    = (SEL == 0) ? g_csr_oo : (SEL == 1) ? g_csr_ro : g_csr_ao;
    __nv_bfloat16* hi = g_A1hi[SEL];
    __nv_bfloat16* lo = g_A1lo[SEL];

    int row = blockIdx.x;
    int t = threadIdx.x;
    int beg = offs[row], end = offs[row + 1];
    float a0 = 0.f, a1 = 0.f, a2 = 0.f;
    __shared__ int ss[128];

    for (int base = beg; base < end; base += 128) {
        int nB = min(128, end - base);
        __syncthreads();
        if (t < nB) ss[t] = csr[base + t];
        __syncthreads();
        for (int j = 0; j < nB; j++) {
            const float* f = feat + (size_t)ss[j] * IN_F;
            a0 += f[t];
            a1 += f[t + 128];
            if (t < IN_F - 256) a2 += f[t + 256];
        }
    }

    size_t o = (size_t)row * KP1;
    {
        __nv_bfloat16 h = __float2bfloat16(a0);
        hi[o + t] = h; lo[o + t] = __float2bfloat16(a0 - __bfloat162float(h));
    }
    {
        __nv_bfloat16 h = __float2bfloat16(a1);
        hi[o + t + 128] = h; lo[o + t + 128] = __float2bfloat16(a1 - __bfloat162float(h));
    }
    if (t < KP1 - 256) {  // covers real cols 256..299 and zero pad 300..303
        float v = (t < IN_F - 256) ? a2 : 0.f;
        __nv_bfloat16 h = __float2bfloat16(v);
        hi[o + t + 256] = h; lo[o + t + 256] = __float2bfloat16(v - __bfloat162float(h));
    }
}

// ---------------- conv2 aggregation (512-dim) over oo CSR ----------------
__global__ void __launch_bounds__(128) agg2() {
    int row = blockIdx.x;
    int t = threadIdx.x;
    int beg = g_off_oo[row], end = g_off_oo[row + 1];
    float a0 = 0.f, a1 = 0.f, a2 = 0.f, a3 = 0.f;
    __shared__ int ss[128];

    for (int base = beg; base < end; base += 128) {
        int nB = min(128, end - base);
        __syncthreads();
        if (t < nB) ss[t] = g_csr_oo[base + t];
        __syncthreads();
        for (int j = 0; j < nB; j++) {
            const float* f = g_hs + (size_t)ss[j] * HDIM;
            a0 += f[t];
            a1 += f[t + 128];
            a2 += f[t + 256];
            a3 += f[t + 384];
        }
    }

    size_t o = (size_t)row * KP2;
    float vals[4] = {a0, a1, a2, a3};
    #pragma unroll
    for (int q = 0; q < 4; q++) {
        __nv_bfloat16 h = __float2bfloat16(vals[q]);
        g_A2hi[o + t + q * 128] = h;
        g_A2lo[o + t + q * 128] = __float2bfloat16(vals[q] - __bfloat162float(h));
    }
}

// ---------------- weight split ----------------
__global__ void conv_w(const float* __restrict__ src, int sel, int K) {
    __nv_bfloat16* hi = g_Whi[sel];
    __nv_bfloat16* lo = g_Wlo[sel];
    int KPv = (K == IN_F) ? KP1 : KP2;
    size_t n = (size_t)KPv * HDIM;
    size_t stride = (size_t)gridDim.x * blockDim.x;
    for (size_t idx = (size_t)blockIdx.x * blockDim.x + threadIdx.x; idx < n; idx += stride) {
        int r = (int)(idx / HDIM);
        float x = (r < K) ? src[idx] : 0.f;
        __nv_bfloat16 h = __float2bfloat16(x);
        float res = x - __bfloat162float(h);
        hi[idx] = h;
        lo[idx] = __float2bfloat16(res);
    }
}

// ---------------- bf16x3 tensor-core GEMM with fused GCN epilogue ----------------
// MODE 0: hs  = relu(A*nd @ W + b) / 3               (KP1)
// MODE 1: hs += relu(A*nd @ W + b) / 3               (KP1)
// MODE 2: hs  = (hs + relu(A*nd @ W + b)/3) * ns_oo  (KP1)   <- conv2 src-norm folded
// MODE 3: out[b] = A*nd @ W + b, broadcast 8          (KP2)

__device__ __forceinline__ void cpasync16(void* smem_dst, const void* gmem_src) {
    uint32_t sa = (uint32_t)__cvta_generic_to_shared(smem_dst);
    asm volatile("cp.async.cg.shared.global [%0], [%1], 16;\n" :: "r"(sa), "l"(gmem_src));
}
__device__ __forceinline__ void cp_commit() { asm volatile("cp.async.commit_group;\n" ::: "memory"); }
template <int N>
__device__ __forceinline__ void cp_wait() { asm volatile("cp.async.wait_group %0;\n" :: "n"(N) : "memory"); }

__device__ __forceinline__ void ldsm4(uint32_t* r, const void* p) {
    uint32_t a = (uint32_t)__cvta_generic_to_shared(p);
    asm volatile("ldmatrix.sync.aligned.m8n8.x4.shared.b16 {%0,%1,%2,%3}, [%4];\n"
                 : "=r"(r[0]), "=r"(r[1]), "=r"(r[2]), "=r"(r[3]) : "r"(a));
}
__device__ __forceinline__ void ldsm4t(uint32_t* r, const void* p) {
    uint32_t a = (uint32_t)__cvta_generic_to_shared(p);
    asm volatile("ldmatrix.sync.aligned.m8n8.x4.trans.shared.b16 {%0,%1,%2,%3}, [%4];\n"
                 : "=r"(r[0]), "=r"(r[1]), "=r"(r[2]), "=r"(r[3]) : "r"(a));
}
__device__ __forceinline__ void mma_bf16(float* d, const uint32_t* a, uint32_t b0, uint32_t b1) {
    asm volatile("mma.sync.aligned.m16n8k16.row.col.f32.bf16.bf16.f32 "
                 "{%0,%1,%2,%3}, {%4,%5,%6,%7}, {%8,%9}, {%0,%1,%2,%3};\n"
                 : "+f"(d[0]), "+f"(d[1]), "+f"(d[2]), "+f"(d[3])
                 : "r"(a[0]), "r"(a[1]), "r"(a[2]), "r"(a[3]), "r"(b0), "r"(b1));
}

template <int MODE, int KP>
__global__ void __launch_bounds__(256) gemm_bf16(const float* __restrict__ bias,
                                                 float* __restrict__ outp) {
    const __nv_bfloat16 *Ahi, *Alo, *Bhi, *Blo;
    const int* degin;
    float* C;
    if      (MODE == 0) { Ahi = g_A1hi[0]; Alo = g_A1lo[0]; Bhi = g_Whi[0]; Blo = g_Wlo[0]; degin = g_din_oo; C = g_hs; }
    else if (MODE == 1) { Ahi = g_A1hi[1]; Alo = g_A1lo[1]; Bhi = g_Whi[0]; Blo = g_Wlo[0]; degin = g_din_ro; C = g_hs; }
    else if (MODE == 2) { Ahi = g_A1hi[2]; Alo = g_A1lo[2]; Bhi = g_Whi[1]; Blo = g_Wlo[1]; degin = g_din_ao; C = g_hs; }
    else                { Ahi = g_A2hi;    Alo = g_A2lo;    Bhi = g_Whi[2]; Blo = g_Wlo[2]; degin = g_din_oo; C = outp; }

    const int NT = KP / 16;
    __shared__ __align__(16) __nv_bfloat16 sA[2][2][128][24];
    __shared__ __align__(16) __nv_bfloat16 sB[2][2][16][136];

    int tid  = threadIdx.x;
    int warp = tid >> 5, lane = tid & 31;
    int row0 = blockIdx.y * 128, col0 = blockIdx.x * 128;
    int wr = warp >> 2, wc = warp & 3;

    float acc[4][4][4] = {};

    int aR = tid >> 1, aC = tid & 1;
    int bR = tid >> 4, bC = tid & 15;

    auto load_stage = [&](int t, int s) {
        cpasync16(&sA[s][0][aR][aC * 8], Ahi + (size_t)(row0 + aR) * KP + t * 16 + aC * 8);
        cpasync16(&sA[s][1][aR][aC * 8], Alo + (size_t)(row0 + aR) * KP + t * 16 + aC * 8);
        cpasync16(&sB[s][0][bR][bC * 8], Bhi + (size_t)(t * 16 + bR) * HDIM + col0 + bC * 8);
        cpasync16(&sB[s][1][bR][bC * 8], Blo + (size_t)(t * 16 + bR) * HDIM + col0 + bC * 8);
    };

    load_stage(0, 0);
    cp_commit();

    for (int t = 0; t < NT; t++) {
        int s = t & 1;
        if (t + 1 < NT) { load_stage(t + 1, s ^ 1); }
        cp_commit();
        cp_wait<1>();
        __syncthreads();

        uint32_t ahi[4][4], alo[4][4], bhi[2][4], blo[2][4];
        int arow = wr * 64 + (lane & 15);
        int acol = (lane >> 4) * 8;
        #pragma unroll
        for (int m = 0; m < 4; m++) {
            ldsm4(ahi[m], &sA[s][0][arow + m * 16][acol]);
            ldsm4(alo[m], &sA[s][1][arow + m * 16][acol]);
        }
        int brow = lane & 15;
        int bcol = wc * 32 + (lane >> 4) * 8;
        #pragma unroll
        for (int p = 0; p < 2; p++) {
            ldsm4t(bhi[p], &sB[s][0][brow][bcol + p * 16]);
            ldsm4t(blo[p], &sB[s][1][brow][bcol + p * 16]);
        }

        #pragma unroll
        for (int m = 0; m < 4; m++)
            #pragma unroll
            for (int n = 0; n < 4; n++) {
                int p = n >> 1, h = n & 1;
                mma_bf16(acc[m][n], ahi[m], bhi[p][h * 2], bhi[p][h * 2 + 1]);
                mma_bf16(acc[m][n], ahi[m], blo[p][h * 2], blo[p][h * 2 + 1]);
                mma_bf16(acc[m][n], alo[m], bhi[p][h * 2], bhi[p][h * 2 + 1]);
            }
        __syncthreads();
    }

    #pragma unroll
    for (int m = 0; m < 4; m++) {
        int r1 = row0 + wr * 64 + m * 16 + (lane >> 2);
        int r2 = r1 + 8;
        float nd1 = (r1 < N_OBJ) ? rsqrtf((float)max(degin[r1], 1)) : 0.f;
        float nd2 = (r2 < N_OBJ) ? rsqrtf((float)max(degin[r2], 1)) : 0.f;
        float sc1 = 1.f, sc2 = 1.f;
        if (MODE == 2) {
            if (r1 < N_OBJ) sc1 = rsqrtf((float)max(g_dout_oo[r1], 1));
            if (r2 < N_OBJ) sc2 = rsqrtf((float)max(g_dout_oo[r2], 1));
        }
        #pragma unroll
        for (int n = 0; n < 4; n++) {
            int c = col0 + wc * 32 + n * 8 + (lane & 3) * 2;
            float bx = bias[c], by = bias[c + 1];
            #pragma unroll
            for (int h = 0; h < 2; h++) {
                int r = h ? r2 : r1;
                if (r >= N_OBJ) continue;
                float nd = h ? nd2 : nd1;
                float vx = acc[m][n][h * 2 + 0] * nd + bx;
                float vy = acc[m][n][h * 2 + 1] * nd + by;
                if (MODE < 3) {
                    const float third = 1.f / 3.f;
                    vx = fmaxf(vx, 0.f) * third;
                    vy = fmaxf(vy, 0.f) * third;
                    float* p = C + (size_t)r * HDIM + c;
                    if (MODE > 0) {
                        float2 pr = *(float2*)p;
                        vx += pr.x; vy += pr.y;
                    }
                    if (MODE == 2) {
                        float sc = h ? sc2 : sc1;
                        vx *= sc; vy *= sc;
                    }
                    *(float2*)p = make_float2(vx, vy);
                } else {
                    #pragma unroll
                    for (int b = 0; b < BATCH; b++) {
                        float* p = C + (size_t)b * N_OBJ * HDIM + (size_t)r * HDIM + c;
                        *(float2*)p = make_float2(vx, vy);
                    }
                }
            }
        }
    }
}

// ---------------- launch ----------------
extern "C" void kernel_launch(void* const* d_in, const int* in_sizes, int n_in,
                              void* d_out, int out_size) {
    const float* feat_obj  = (const float*)d_in[1];
    const float* feat_room = (const float*)d_in[2];
    const float* feat_attr = (const float*)d_in[3];
    const float* W1i = (const float*)d_in[4];
    const float* b1i = (const float*)d_in[5];
    const float* W1b = (const float*)d_in[6];
    const float* b1b = (const float*)d_in[7];
    const float* W2  = (const float*)d_in[8];
    const float* b2  = (const float*)d_in[9];
    const int* src_oo = (const int*)d_in[10];
    const int* dst_oo = (const int*)d_in[11];
    const int* src_ro = (const int*)d_in[12];
    const int* dst_ro = (const int*)d_in[13];
    const int* src_ao = (const int*)d_in[14];
    const int* dst_ao = (const int*)d_in[15];
    float* out = (float*)d_out;

    zero_small<<<512, 256>>>();

    deg_kernel<0><<<(EOO + 255) / 256, 256>>>(src_oo, dst_oo, EOO);
    deg_kernel<1><<<(ERO + 255) / 256, 256>>>(src_ro, dst_ro, ERO);
    deg_kernel<2><<<(EAO + 255) / 256, 256>>>(src_ao, dst_ao, EAO);

    // pre-scale features by src norm
    fscale<0><<<2048, 256>>>(feat_obj);
    fscale<1><<<128,  256>>>(feat_room);
    fscale<2><<<512,  256>>>(feat_attr);

    // CSR build
    scan_deg<0><<<1, 1024>>>();
    scan_deg<1><<<1, 1024>>>();
    scan_deg<2><<<1, 1024>>>();
    scatter_edges<0><<<(EOO + 255) / 256, 256>>>(src_oo, dst_oo, EOO);
    scatter_edges<1><<<(ERO + 255) / 256, 256>>>(src_ro, dst_ro, ERO);
    scatter_edges<2><<<(EAO + 255) / 256, 256>>>(src_ao, dst_ao, EAO);

    // weight splits (independent)
    conv_w<<<256, 256>>>(W1i, 0, IN_F);
    conv_w<<<256, 256>>>(W1b, 1, IN_F);
    conv_w<<<256, 256>>>(W2,  2, HDIM);

    // conv1 aggregation (CSR gather-sum, writes bf16 hi/lo directly)
    agg1<0><<<N_OBJ, 128>>>();
    agg1<1><<<N_OBJ, 128>>>();
    agg1<2><<<N_OBJ, 128>>>();

    dim3 grid(HDIM / 128, (N_OBJ + 127) / 128);
    gemm_bf16<0, KP1><<<grid, 256>>>(b1i, out);
    gemm_bf16<1, KP1><<<grid, 256>>>(b1i, out);
    gemm_bf16<2, KP1><<<grid, 256>>>(b1b, out);

    // conv2 aggregation over oo CSR in H=512
    agg2<<<N_OBJ, 128>>>();

    gemm_bf16<3, KP2><<<grid, 256>>>(b2, out);
}

// round 4
// speedup vs baseline: 2.1399x; 1.1344x over previous
#include <cuda_runtime.h>
#include <cuda_bf16.h>
#include <cstdint>

#define N_OBJ  20000
#define N_ROOM 500
#define N_ATTR 2000
#define IN_F   300
#define HDIM   512
#define EOO    640000
#define ERO    50000
#define EAO    100000
#define BATCH  8

#define MP   20096          // N_OBJ padded to 128
#define KP1  304            // IN_F padded to 16
#define KP2  512

// ---------------- scratch (device globals, no allocation) ----------------
__device__ float g_hs[(size_t)N_OBJ * HDIM];   // h_obj * ns_oo (conv2 input)

__device__ int g_dout_oo[N_OBJ];
__device__ int g_din_oo [N_OBJ];
__device__ int g_dout_ro[N_ROOM];
__device__ int g_din_ro [N_OBJ];
__device__ int g_dout_ao[N_ATTR];
__device__ int g_din_ao [N_OBJ];

__device__ int g_off_oo[N_OBJ + 1];
__device__ int g_off_ro[N_OBJ + 1];
__device__ int g_off_ao[N_OBJ + 1];
__device__ int g_cnt_oo[N_OBJ];
__device__ int g_cnt_ro[N_OBJ];
__device__ int g_cnt_ao[N_OBJ];
__device__ int g_csr_oo[EOO];
__device__ int g_csr_ro[ERO];
__device__ int g_csr_ao[EAO];

// bf16 hi/lo split operands (written directly by aggregation kernels)
__device__ __nv_bfloat16 g_A1hi[3][(size_t)MP * KP1];
__device__ __nv_bfloat16 g_A1lo[3][(size_t)MP * KP1];
__device__ __nv_bfloat16 g_A2hi[(size_t)MP * KP2];
__device__ __nv_bfloat16 g_A2lo[(size_t)MP * KP2];
__device__ __nv_bfloat16 g_Whi[3][(size_t)KP2 * HDIM];   // 0:W1i 1:W1b 2:W2
__device__ __nv_bfloat16 g_Wlo[3][(size_t)KP2 * HDIM];

// ---------------- zero small scratch (degrees + pad rows) ----------------
__global__ void zero_small() {
    int tid    = blockIdx.x * blockDim.x + threadIdx.x;
    int stride = gridDim.x * blockDim.x;
    for (int i = tid; i < N_OBJ; i += stride) {
        g_dout_oo[i] = 0; g_din_oo[i] = 0; g_din_ro[i] = 0; g_din_ao[i] = 0;
    }
    for (int i = tid; i < N_ROOM; i += stride) g_dout_ro[i] = 0;
    for (int i = tid; i < N_ATTR; i += stride) g_dout_ao[i] = 0;
    const __nv_bfloat16 z = __float2bfloat16(0.f);
    int padA1 = (MP - N_OBJ) * KP1;
    for (int i = tid; i < padA1; i += stride) {
        size_t o = (size_t)N_OBJ * KP1 + i;
        g_A1hi[0][o] = z; g_A1lo[0][o] = z;
        g_A1hi[1][o] = z; g_A1lo[1][o] = z;
        g_A1hi[2][o] = z; g_A1lo[2][o] = z;
    }
    int padA2 = (MP - N_OBJ) * KP2;
    for (int i = tid; i < padA2; i += stride) {
        size_t o = (size_t)N_OBJ * KP2 + i;
        g_A2hi[o] = z; g_A2lo[o] = z;
    }
}

// ---------------- merged degree counting (all 3 relations) ----------------
__global__ void deg_all(const int* __restrict__ src_oo, const int* __restrict__ dst_oo,
                        const int* __restrict__ src_ro, const int* __restrict__ dst_ro,
                        const int* __restrict__ src_ao, const int* __restrict__ dst_ao) {
    int i = blockIdx.x * blockDim.x + threadIdx.x;
    if (i < EOO) {
        atomicAdd(&g_dout_oo[src_oo[i]], 1);
        atomicAdd(&g_din_oo [dst_oo[i]], 1);
    } else if (i < EOO + ERO) {
        int j = i - EOO;
        atomicAdd(&g_dout_ro[src_ro[j]], 1);
        atomicAdd(&g_din_ro [dst_ro[j]], 1);
    } else if (i < EOO + ERO + EAO) {
        int j = i - EOO - ERO;
        atomicAdd(&g_dout_ao[src_ao[j]], 1);
        atomicAdd(&g_din_ao [dst_ao[j]], 1);
    }
}

// ---------------- 3-block exclusive scan (one block per relation) ----------
__global__ void scan3() {
    int sel = blockIdx.x;
    const int* deg = (sel == 0) ? g_din_oo : (sel == 1) ? g_din_ro : g_din_ao;
    int* offs      = (sel == 0) ? g_off_oo : (sel == 1) ? g_off_ro : g_off_ao;
    int* cnt       = (sel == 0) ? g_cnt_oo : (sel == 1) ? g_cnt_ro : g_cnt_ao;
    __shared__ int part[1025];
    const int n = N_OBJ;
    int t = threadIdx.x;                 // 1024 threads
    int chunk = (n + 1023) / 1024;
    int b = t * chunk, e = min(b + chunk, n);
    int s = 0;
    for (int i = b; i < e; i++) s += deg[i];
    part[t + 1] = s;
    if (t == 0) part[0] = 0;
    __syncthreads();
    for (int off = 1; off < 1024; off <<= 1) {
        int v = part[t + 1];
        if (t + 1 > off) v += part[t + 1 - off];
        __syncthreads();
        part[t + 1] = v;
        __syncthreads();
    }
    int run = part[t];
    for (int i = b; i < e; i++) { offs[i] = run; cnt[i] = run; run += deg[i]; }
    if (t == 0) offs[n] = part[1024];
}

// ---------------- merged edge scatter ----------------
__global__ void scatter_all(const int* __restrict__ src_oo, const int* __restrict__ dst_oo,
                            const int* __restrict__ src_ro, const int* __restrict__ dst_ro,
                            const int* __restrict__ src_ao, const int* __restrict__ dst_ao) {
    int i = blockIdx.x * blockDim.x + threadIdx.x;
    if (i < EOO) {
        int pos = atomicAdd(&g_cnt_oo[dst_oo[i]], 1);
        g_csr_oo[pos] = src_oo[i];
    } else if (i < EOO + ERO) {
        int j = i - EOO;
        int pos = atomicAdd(&g_cnt_ro[dst_ro[j]], 1);
        g_csr_ro[pos] = src_ro[j];
    } else if (i < EOO + ERO + EAO) {
        int j = i - EOO - ERO;
        int pos = atomicAdd(&g_cnt_ao[dst_ao[j]], 1);
        g_csr_ao[pos] = src_ao[j];
    }
}

// ---------------- conv1 aggregation: CSR gather-sum, float4, src-norm folded --
// one block per dst row; threads t<75 each own one float4 (4 cols) of the row
template <int SEL>
__global__ void __launch_bounds__(128) agg1(const float* __restrict__ feat) {
    const int* offs   = (SEL == 0) ? g_off_oo  : (SEL == 1) ? g_off_ro  : g_off_ao;
    const int* csr    = (SEL == 0) ? g_csr_oo  : (SEL == 1) ? g_csr_ro  : g_csr_ao;
    const int* degout = (SEL == 0) ? g_dout_oo : (SEL == 1) ? g_dout_ro : g_dout_ao;
    __nv_bfloat16* hi = g_A1hi[SEL];
    __nv_bfloat16* lo = g_A1lo[SEL];

    int row = blockIdx.x;
    int t = threadIdx.x;
    int beg = offs[row], end = offs[row + 1];
    float4 a = make_float4(0.f, 0.f, 0.f, 0.f);
    __shared__ int   ss[128];
    __shared__ float sn[128];

    const int NV = IN_F / 4;            // 75
    for (int base = beg; base < end; base += 128) {
        int nB = min(128, end - base);
        __syncthreads();
        if (t < nB) {
            int s = csr[base + t];
            ss[t] = s;
            sn[t] = rsqrtf((float)max(degout[s], 1));
        }
        __syncthreads();
        int j = 0;
        if (t < NV) {
            for (; j + 4 <= nB; j += 4) {
                const float4* p0 = (const float4*)(feat + (size_t)ss[j + 0] * IN_F);
                const float4* p1 = (const float4*)(feat + (size_t)ss[j + 1] * IN_F);
                const float4* p2 = (const float4*)(feat + (size_t)ss[j + 2] * IN_F);
                const float4* p3 = (const float4*)(feat + (size_t)ss[j + 3] * IN_F);
                float4 v0 = p0[t], v1 = p1[t], v2 = p2[t], v3 = p3[t];
                float n0 = sn[j], n1 = sn[j + 1], n2 = sn[j + 2], n3 = sn[j + 3];
                a.x += v0.x * n0 + v1.x * n1 + v2.x * n2 + v3.x * n3;
                a.y += v0.y * n0 + v1.y * n1 + v2.y * n2 + v3.y * n3;
                a.z += v0.z * n0 + v1.z * n1 + v2.z * n2 + v3.z * n3;
                a.w += v0.w * n0 + v1.w * n1 + v2.w * n2 + v3.w * n3;
            }
            for (; j < nB; j++) {
                const float4* p = (const float4*)(feat + (size_t)ss[j] * IN_F);
                float4 v = p[t];
                float n = sn[j];
                a.x += v.x * n; a.y += v.y * n; a.z += v.z * n; a.w += v.w * n;
            }
        }
    }

    if (t <= NV) {      // t==75 writes the K-pad (cols 300..303) as zero
        if (t == NV) a = make_float4(0.f, 0.f, 0.f, 0.f);
        size_t o = (size_t)row * KP1 + t * 4;
        float vals[4] = {a.x, a.y, a.z, a.w};
        __nv_bfloat16 h[4], l[4];
        #pragma unroll
        for (int q = 0; q < 4; q++) {
            h[q] = __float2bfloat16(vals[q]);
            l[q] = __float2bfloat16(vals[q] - __bfloat162float(h[q]));
        }
        *(__nv_bfloat162*)(hi + o)     = *(__nv_bfloat162*)&h[0];
        *(__nv_bfloat162*)(hi + o + 2) = *(__nv_bfloat162*)&h[2];
        *(__nv_bfloat162*)(lo + o)     = *(__nv_bfloat162*)&l[0];
        *(__nv_bfloat162*)(lo + o + 2) = *(__nv_bfloat162*)&l[2];
    }
}

// ---------------- conv2 aggregation (512-dim) over oo CSR, float4 ----------
__global__ void __launch_bounds__(128) agg2() {
    int row = blockIdx.x;
    int t = threadIdx.x;
    int beg = g_off_oo[row], end = g_off_oo[row + 1];
    float4 a = make_float4(0.f, 0.f, 0.f, 0.f);
    __shared__ int ss[128];

    for (int base = beg; base < end; base += 128) {
        int nB = min(128, end - base);
        __syncthreads();
        if (t < nB) ss[t] = g_csr_oo[base + t];
        __syncthreads();
        int j = 0;
        for (; j + 4 <= nB; j += 4) {
            const float4* p0 = (const float4*)(g_hs + (size_t)ss[j + 0] * HDIM);
            const float4* p1 = (const float4*)(g_hs + (size_t)ss[j + 1] * HDIM);
            const float4* p2 = (const float4*)(g_hs + (size_t)ss[j + 2] * HDIM);
            const float4* p3 = (const float4*)(g_hs + (size_t)ss[j + 3] * HDIM);
            float4 v0 = p0[t], v1 = p1[t], v2 = p2[t], v3 = p3[t];
            a.x += v0.x + v1.x + v2.x + v3.x;
            a.y += v0.y + v1.y + v2.y + v3.y;
            a.z += v0.z + v1.z + v2.z + v3.z;
            a.w += v0.w + v1.w + v2.w + v3.w;
        }
        for (; j < nB; j++) {
            const float4* p = (const float4*)(g_hs + (size_t)ss[j] * HDIM);
            float4 v = p[t];
            a.x += v.x; a.y += v.y; a.z += v.z; a.w += v.w;
        }
    }

    size_t o = (size_t)row * KP2 + t * 4;
    float vals[4] = {a.x, a.y, a.z, a.w};
    __nv_bfloat16 h[4], l[4];
    #pragma unroll
    for (int q = 0; q < 4; q++) {
        h[q] = __float2bfloat16(vals[q]);
        l[q] = __float2bfloat16(vals[q] - __bfloat162float(h[q]));
    }
    *(__nv_bfloat162*)(g_A2hi + o)     = *(__nv_bfloat162*)&h[0];
    *(__nv_bfloat162*)(g_A2hi + o + 2) = *(__nv_bfloat162*)&h[2];
    *(__nv_bfloat162*)(g_A2lo + o)     = *(__nv_bfloat162*)&l[0];
    *(__nv_bfloat162*)(g_A2lo + o + 2) = *(__nv_bfloat162*)&l[2];
}

// ---------------- weight split ----------------
__global__ void conv_w(const float* __restrict__ src, int sel, int K) {
    __nv_bfloat16* hi = g_Whi[sel];
    __nv_bfloat16* lo = g_Wlo[sel];
    int KPv = (K == IN_F) ? KP1 : KP2;
    size_t n = (size_t)KPv * HDIM;
    size_t stride = (size_t)gridDim.x * blockDim.x;
    for (size_t idx = (size_t)blockIdx.x * blockDim.x + threadIdx.x; idx < n; idx += stride) {
        int r = (int)(idx / HDIM);
        float x = (r < K) ? src[idx] : 0.f;
        __nv_bfloat16 h = __float2bfloat16(x);
        float res = x - __bfloat162float(h);
        hi[idx] = h;
        lo[idx] = __float2bfloat16(res);
    }
}

// ---------------- bf16x3 tensor-core GEMM with fused GCN epilogue ----------------
// MODE 0: hs  = relu(A*nd @ W + b) / 3               (KP1)
// MODE 1: hs += relu(A*nd @ W + b) / 3               (KP1)
// MODE 2: hs  = (hs + relu(A*nd @ W + b)/3) * ns_oo  (KP1)
// MODE 3: out[b] = A*nd @ W + b, broadcast 8          (KP2)

__device__ __forceinline__ void cpasync16(void* smem_dst, const void* gmem_src) {
    uint32_t sa = (uint32_t)__cvta_generic_to_shared(smem_dst);
    asm volatile("cp.async.cg.shared.global [%0], [%1], 16;\n" :: "r"(sa), "l"(gmem_src));
}
__device__ __forceinline__ void cp_commit() { asm volatile("cp.async.commit_group;\n" ::: "memory"); }
template <int N>
__device__ __forceinline__ void cp_wait() { asm volatile("cp.async.wait_group %0;\n" :: "n"(N) : "memory"); }

__device__ __forceinline__ void ldsm4(uint32_t* r, const void* p) {
    uint32_t a = (uint32_t)__cvta_generic_to_shared(p);
    asm volatile("ldmatrix.sync.aligned.m8n8.x4.shared.b16 {%0,%1,%2,%3}, [%4];\n"
                 : "=r"(r[0]), "=r"(r[1]), "=r"(r[2]), "=r"(r[3]) : "r"(a));
}
__device__ __forceinline__ void ldsm4t(uint32_t* r, const void* p) {
    uint32_t a = (uint32_t)__cvta_generic_to_shared(p);
    asm volatile("ldmatrix.sync.aligned.m8n8.x4.trans.shared.b16 {%0,%1,%2,%3}, [%4];\n"
                 : "=r"(r[0]), "=r"(r[1]), "=r"(r[2]), "=r"(r[3]) : "r"(a));
}
__device__ __forceinline__ void mma_bf16(float* d, const uint32_t* a, uint32_t b0, uint32_t b1) {
    asm volatile("mma.sync.aligned.m16n8k16.row.col.f32.bf16.bf16.f32 "
                 "{%0,%1,%2,%3}, {%4,%5,%6,%7}, {%8,%9}, {%0,%1,%2,%3};\n"
                 : "+f"(d[0]), "+f"(d[1]), "+f"(d[2]), "+f"(d[3])
                 : "r"(a[0]), "r"(a[1]), "r"(a[2]), "r"(a[3]), "r"(b0), "r"(b1));
}

template <int MODE, int KP>
__global__ void __launch_bounds__(256) gemm_bf16(const float* __restrict__ bias,
                                                 float* __restrict__ outp) {
    const __nv_bfloat16 *Ahi, *Alo, *Bhi, *Blo;
    const int* degin;
    float* C;
    if      (MODE == 0) { Ahi = g_A1hi[0]; Alo = g_A1lo[0]; Bhi = g_Whi[0]; Blo = g_Wlo[0]; degin = g_din_oo; C = g_hs; }
    else if (MODE == 1) { Ahi = g_A1hi[1]; Alo = g_A1lo[1]; Bhi = g_Whi[0]; Blo = g_Wlo[0]; degin = g_din_ro; C = g_hs; }
    else if (MODE == 2) { Ahi = g_A1hi[2]; Alo = g_A1lo[2]; Bhi = g_Whi[1]; Blo = g_Wlo[1]; degin = g_din_ao; C = g_hs; }
    else                { Ahi = g_A2hi;    Alo = g_A2lo;    Bhi = g_Whi[2]; Blo = g_Wlo[2]; degin = g_din_oo; C = outp; }

    const int NT = KP / 16;
    __shared__ __align__(16) __nv_bfloat16 sA[2][2][128][24];
    __shared__ __align__(16) __nv_bfloat16 sB[2][2][16][136];

    int tid  = threadIdx.x;
    int warp = tid >> 5, lane = tid & 31;
    int row0 = blockIdx.y * 128, col0 = blockIdx.x * 128;
    int wr = warp >> 2, wc = warp & 3;

    float acc[4][4][4] = {};

    int aR = tid >> 1, aC = tid & 1;
    int bR = tid >> 4, bC = tid & 15;

    auto load_stage = [&](int t, int s) {
        cpasync16(&sA[s][0][aR][aC * 8], Ahi + (size_t)(row0 + aR) * KP + t * 16 + aC * 8);
        cpasync16(&sA[s][1][aR][aC * 8], Alo + (size_t)(row0 + aR) * KP + t * 16 + aC * 8);
        cpasync16(&sB[s][0][bR][bC * 8], Bhi + (size_t)(t * 16 + bR) * HDIM + col0 + bC * 8);
        cpasync16(&sB[s][1][bR][bC * 8], Blo + (size_t)(t * 16 + bR) * HDIM + col0 + bC * 8);
    };

    load_stage(0, 0);
    cp_commit();

    for (int t = 0; t < NT; t++) {
        int s = t & 1;
        if (t + 1 < NT) { load_stage(t + 1, s ^ 1); }
        cp_commit();
        cp_wait<1>();
        __syncthreads();

        uint32_t ahi[4][4], alo[4][4], bhi[2][4], blo[2][4];
        int arow = wr * 64 + (lane & 15);
        int acol = (lane >> 4) * 8;
        #pragma unroll
        for (int m = 0; m < 4; m++) {
            ldsm4(ahi[m], &sA[s][0][arow + m * 16][acol]);
            ldsm4(alo[m], &sA[s][1][arow + m * 16][acol]);
        }
        int brow = lane & 15;
        int bcol = wc * 32 + (lane >> 4) * 8;
        #pragma unroll
        for (int p = 0; p < 2; p++) {
            ldsm4t(bhi[p], &sB[s][0][brow][bcol + p * 16]);
            ldsm4t(blo[p], &sB[s][1][brow][bcol + p * 16]);
        }

        #pragma unroll
        for (int m = 0; m < 4; m++)
            #pragma unroll
            for (int n = 0; n < 4; n++) {
                int p = n >> 1, h = n & 1;
                mma_bf16(acc[m][n], ahi[m], bhi[p][h * 2], bhi[p][h * 2 + 1]);
                mma_bf16(acc[m][n], ahi[m], blo[p][h * 2], blo[p][h * 2 + 1]);
                mma_bf16(acc[m][n], alo[m], bhi[p][h * 2], bhi[p][h * 2 + 1]);
            }
        __syncthreads();
    }

    #pragma unroll
    for (int m = 0; m < 4; m++) {
        int r1 = row0 + wr * 64 + m * 16 + (lane >> 2);
        int r2 = r1 + 8;
        float nd1 = (r1 < N_OBJ) ? rsqrtf((float)max(degin[r1], 1)) : 0.f;
        float nd2 = (r2 < N_OBJ) ? rsqrtf((float)max(degin[r2], 1)) : 0.f;
        float sc1 = 1.f, sc2 = 1.f;
        if (MODE == 2) {
            if (r1 < N_OBJ) sc1 = rsqrtf((float)max(g_dout_oo[r1], 1));
            if (r2 < N_OBJ) sc2 = rsqrtf((float)max(g_dout_oo[r2], 1));
        }
        #pragma unroll
        for (int n = 0; n < 4; n++) {
            int c = col0 + wc * 32 + n * 8 + (lane & 3) * 2;
            float bx = bias[c], by = bias[c + 1];
            #pragma unroll
            for (int h = 0; h < 2; h++) {
                int r = h ? r2 : r1;
                if (r >= N_OBJ) continue;
                float nd = h ? nd2 : nd1;
                float vx = acc[m][n][h * 2 + 0] * nd + bx;
                float vy = acc[m][n][h * 2 + 1] * nd + by;
                if (MODE < 3) {
                    const float third = 1.f / 3.f;
                    vx = fmaxf(vx, 0.f) * third;
                    vy = fmaxf(vy, 0.f) * third;
                    float* p = C + (size_t)r * HDIM + c;
                    if (MODE > 0) {
                        float2 pr = *(float2*)p;
                        vx += pr.x; vy += pr.y;
                    }
                    if (MODE == 2) {
                        float sc = h ? sc2 : sc1;
                        vx *= sc; vy *= sc;
                    }
                    *(float2*)p = make_float2(vx, vy);
                } else {
                    #pragma unroll
                    for (int b = 0; b < BATCH; b++) {
                        float* p = C + (size_t)b * N_OBJ * HDIM + (size_t)r * HDIM + c;
                        *(float2*)p = make_float2(vx, vy);
                    }
                }
            }
        }
    }
}

// ---------------- launch ----------------
extern "C" void kernel_launch(void* const* d_in, const int* in_sizes, int n_in,
                              void* d_out, int out_size) {
    const float* feat_obj  = (const float*)d_in[1];
    const float* feat_room = (const float*)d_in[2];
    const float* feat_attr = (const float*)d_in[3];
    const float* W1i = (const float*)d_in[4];
    const float* b1i = (const float*)d_in[5];
    const float* W1b = (const float*)d_in[6];
    const float* b1b = (const float*)d_in[7];
    const float* W2  = (const float*)d_in[8];
    const float* b2  = (const float*)d_in[9];
    const int* src_oo = (const int*)d_in[10];
    const int* dst_oo = (const int*)d_in[11];
    const int* src_ro = (const int*)d_in[12];
    const int* dst_ro = (const int*)d_in[13];
    const int* src_ao = (const int*)d_in[14];
    const int* dst_ao = (const int*)d_in[15];
    float* out = (float*)d_out;

    const int ETOT = EOO + ERO + EAO;

    zero_small<<<512, 256>>>();

    deg_all<<<(ETOT + 255) / 256, 256>>>(src_oo, dst_oo, src_ro, dst_ro, src_ao, dst_ao);

    scan3<<<3, 1024>>>();

    scatter_all<<<(ETOT + 255) / 256, 256>>>(src_oo, dst_oo, src_ro, dst_ro, src_ao, dst_ao);

    // weight splits (independent of edges)
    conv_w<<<256, 256>>>(W1i, 0, IN_F);
    conv_w<<<256, 256>>>(W1b, 1, IN_F);
    conv_w<<<256, 256>>>(W2,  2, HDIM);

    // conv1 aggregation (vectorized CSR gather, src-norm folded, bf16 split fused)
    agg1<0><<<N_OBJ, 128>>>(feat_obj);
    agg1<1><<<N_OBJ, 128>>>(feat_room);
    agg1<2><<<N_OBJ, 128>>>(feat_attr);

    dim3 grid(HDIM / 128, (N_OBJ + 127) / 128);
    gemm_bf16<0, KP1><<<grid, 256>>>(b1i, out);
    gemm_bf16<1, KP1><<<grid, 256>>>(b1i, out);
    gemm_bf16<2, KP1><<<grid, 256>>>(b1b, out);

    // conv2 aggregation over oo CSR in H=512
    agg2<<<N_OBJ, 128>>>();

    gemm_bf16<3, KP2><<<grid, 256>>>(b2, out);
}

// round 5
// speedup vs baseline: 2.2653x; 1.0586x over previous
#include <cuda_runtime.h>
#include <cuda_bf16.h>
#include <cstdint>

#define N_OBJ  20000
#define N_ROOM 500
#define N_ATTR 2000
#define IN_F   300
#define HDIM   512
#define EOO    640000
#define ERO    50000
#define EAO    100000
#define BATCH  8

#define MP   20096
#define KP1  304
#define KP2  512
#define NTR  19            // KP1/16
#define TT1  57            // 3*NTR
#define TT2  32            // KP2/16

// ---------------- scratch (device globals, no allocation) ----------------
__device__ float g_hs[(size_t)N_OBJ * HDIM];

__device__ int g_dout_oo[N_OBJ];
__device__ int g_din_oo [N_OBJ];
__device__ int g_dout_ro[N_ROOM];
__device__ int g_din_ro [N_OBJ];
__device__ int g_dout_ao[N_ATTR];
__device__ int g_din_ao [N_OBJ];

__device__ int g_off_oo[N_OBJ + 1];
__device__ int g_off_ro[N_OBJ + 1];
__device__ int g_off_ao[N_OBJ + 1];
__device__ int g_cnt_oo[N_OBJ];
__device__ int g_cnt_ro[N_OBJ];
__device__ int g_cnt_ao[N_OBJ];
__device__ int g_csr_oo[EOO];
__device__ int g_csr_ro[ERO];
__device__ int g_csr_ao[EAO];

__device__ __nv_bfloat16 g_A1hi[3][(size_t)MP * KP1];
__device__ __nv_bfloat16 g_A1lo[3][(size_t)MP * KP1];
__device__ __nv_bfloat16 g_A2hi[(size_t)MP * KP2];
__device__ __nv_bfloat16 g_A2lo[(size_t)MP * KP2];
__device__ __nv_bfloat16 g_Whi[3][(size_t)KP2 * HDIM];   // 0:W1i 1:W1b 2:W2
__device__ __nv_bfloat16 g_Wlo[3][(size_t)KP2 * HDIM];

// ---------------- prep: zero degrees + pad rows + weight hi/lo splits ----
__global__ void prep(const float* __restrict__ W1i, const float* __restrict__ W1b,
                     const float* __restrict__ W2) {
    int tid    = blockIdx.x * blockDim.x + threadIdx.x;
    int stride = gridDim.x * blockDim.x;
    for (int i = tid; i < N_OBJ; i += stride) {
        g_dout_oo[i] = 0; g_din_oo[i] = 0; g_din_ro[i] = 0; g_din_ao[i] = 0;
    }
    for (int i = tid; i < N_ROOM; i += stride) g_dout_ro[i] = 0;
    for (int i = tid; i < N_ATTR; i += stride) g_dout_ao[i] = 0;
    const __nv_bfloat16 z = __float2bfloat16(0.f);
    int padA1 = (MP - N_OBJ) * KP1;
    for (int i = tid; i < padA1; i += stride) {
        size_t o = (size_t)N_OBJ * KP1 + i;
        g_A1hi[0][o] = z; g_A1lo[0][o] = z;
        g_A1hi[1][o] = z; g_A1lo[1][o] = z;
        g_A1hi[2][o] = z; g_A1lo[2][o] = z;
    }
    int padA2 = (MP - N_OBJ) * KP2;
    for (int i = tid; i < padA2; i += stride) {
        size_t o = (size_t)N_OBJ * KP2 + i;
        g_A2hi[o] = z; g_A2lo[o] = z;
    }
    // weight splits: W1i, W1b -> [KP1][512] (rows >=300 zero), W2 -> [512][512]
    const int n1 = KP1 * HDIM;
    for (int idx = tid; idx < n1; idx += stride) {
        int r = idx / HDIM;
        float x0 = (r < IN_F) ? W1i[idx] : 0.f;
        float x1 = (r < IN_F) ? W1b[idx] : 0.f;
        __nv_bfloat16 h0 = __float2bfloat16(x0);
        __nv_bfloat16 h1 = __float2bfloat16(x1);
        g_Whi[0][idx] = h0; g_Wlo[0][idx] = __float2bfloat16(x0 - __bfloat162float(h0));
        g_Whi[1][idx] = h1; g_Wlo[1][idx] = __float2bfloat16(x1 - __bfloat162float(h1));
    }
    const int n2 = KP2 * HDIM;
    for (int idx = tid; idx < n2; idx += stride) {
        float x = W2[idx];
        __nv_bfloat16 h = __float2bfloat16(x);
        g_Whi[2][idx] = h; g_Wlo[2][idx] = __float2bfloat16(x - __bfloat162float(h));
    }
}

// ---------------- merged degree counting ----------------
__global__ void deg_all(const int* __restrict__ src_oo, const int* __restrict__ dst_oo,
                        const int* __restrict__ src_ro, const int* __restrict__ dst_ro,
                        const int* __restrict__ src_ao, const int* __restrict__ dst_ao) {
    int i = blockIdx.x * blockDim.x + threadIdx.x;
    if (i < EOO) {
        atomicAdd(&g_dout_oo[src_oo[i]], 1);
        atomicAdd(&g_din_oo [dst_oo[i]], 1);
    } else if (i < EOO + ERO) {
        int j = i - EOO;
        atomicAdd(&g_dout_ro[src_ro[j]], 1);
        atomicAdd(&g_din_ro [dst_ro[j]], 1);
    } else if (i < EOO + ERO + EAO) {
        int j = i - EOO - ERO;
        atomicAdd(&g_dout_ao[src_ao[j]], 1);
        atomicAdd(&g_din_ao [dst_ao[j]], 1);
    }
}

// ---------------- 3-block exclusive scan ----------------
__global__ void scan3() {
    int sel = blockIdx.x;
    const int* deg = (sel == 0) ? g_din_oo : (sel == 1) ? g_din_ro : g_din_ao;
    int* offs      = (sel == 0) ? g_off_oo : (sel == 1) ? g_off_ro : g_off_ao;
    int* cnt       = (sel == 0) ? g_cnt_oo : (sel == 1) ? g_cnt_ro : g_cnt_ao;
    __shared__ int part[1025];
    const int n = N_OBJ;
    int t = threadIdx.x;
    int chunk = (n + 1023) / 1024;
    int b = t * chunk, e = min(b + chunk, n);
    int s = 0;
    for (int i = b; i < e; i++) s += deg[i];
    part[t + 1] = s;
    if (t == 0) part[0] = 0;
    __syncthreads();
    for (int off = 1; off < 1024; off <<= 1) {
        int v = part[t + 1];
        if (t + 1 > off) v += part[t + 1 - off];
        __syncthreads();
        part[t + 1] = v;
        __syncthreads();
    }
    int run = part[t];
    for (int i = b; i < e; i++) { offs[i] = run; cnt[i] = run; run += deg[i]; }
    if (t == 0) offs[n] = part[1024];
}

// ---------------- merged edge scatter ----------------
__global__ void scatter_all(const int* __restrict__ src_oo, const int* __restrict__ dst_oo,
                            const int* __restrict__ src_ro, const int* __restrict__ dst_ro,
                            const int* __restrict__ src_ao, const int* __restrict__ dst_ao) {
    int i = blockIdx.x * blockDim.x + threadIdx.x;
    if (i < EOO) {
        int pos = atomicAdd(&g_cnt_oo[dst_oo[i]], 1);
        g_csr_oo[pos] = src_oo[i];
    } else if (i < EOO + ERO) {
        int j = i - EOO;
        int pos = atomicAdd(&g_cnt_ro[dst_ro[j]], 1);
        g_csr_ro[pos] = src_ro[j];
    } else if (i < EOO + ERO + EAO) {
        int j = i - EOO - ERO;
        int pos = atomicAdd(&g_cnt_ao[dst_ao[j]], 1);
        g_csr_ao[pos] = src_ao[j];
    }
}

// ---------------- conv1 aggregation (all 3 relations via blockIdx.y) -------
__global__ void __launch_bounds__(128) agg1_all(const float* __restrict__ fo,
                                                const float* __restrict__ fr,
                                                const float* __restrict__ fa) {
    int sel = blockIdx.y;
    const float* feat = (sel == 0) ? fo : (sel == 1) ? fr : fa;
    const int* offs   = (sel == 0) ? g_off_oo  : (sel == 1) ? g_off_ro  : g_off_ao;
    const int* csr    = (sel == 0) ? g_csr_oo  : (sel == 1) ? g_csr_ro  : g_csr_ao;
    const int* degout = (sel == 0) ? g_dout_oo : (sel == 1) ? g_dout_ro : g_dout_ao;
    __nv_bfloat16* hi = g_A1hi[sel];
    __nv_bfloat16* lo = g_A1lo[sel];

    int row = blockIdx.x;
    int t = threadIdx.x;
    int beg = offs[row], end = offs[row + 1];
    float4 a = make_float4(0.f, 0.f, 0.f, 0.f);
    __shared__ int   ss[128];
    __shared__ float sn[128];

    const int NV = IN_F / 4;            // 75
    for (int base = beg; base < end; base += 128) {
        int nB = min(128, end - base);
        __syncthreads();
        if (t < nB) {
            int s = csr[base + t];
            ss[t] = s;
            sn[t] = rsqrtf((float)max(degout[s], 1));
        }
        __syncthreads();
        int j = 0;
        if (t < NV) {
            for (; j + 4 <= nB; j += 4) {
                const float4* p0 = (const float4*)(feat + (size_t)ss[j + 0] * IN_F);
                const float4* p1 = (const float4*)(feat + (size_t)ss[j + 1] * IN_F);
                const float4* p2 = (const float4*)(feat + (size_t)ss[j + 2] * IN_F);
                const float4* p3 = (const float4*)(feat + (size_t)ss[j + 3] * IN_F);
                float4 v0 = p0[t], v1 = p1[t], v2 = p2[t], v3 = p3[t];
                float n0 = sn[j], n1 = sn[j + 1], n2 = sn[j + 2], n3 = sn[j + 3];
                a.x += v0.x * n0 + v1.x * n1 + v2.x * n2 + v3.x * n3;
                a.y += v0.y * n0 + v1.y * n1 + v2.y * n2 + v3.y * n3;
                a.z += v0.z * n0 + v1.z * n1 + v2.z * n2 + v3.z * n3;
                a.w += v0.w * n0 + v1.w * n1 + v2.w * n2 + v3.w * n3;
            }
            for (; j < nB; j++) {
                const float4* p = (const float4*)(feat + (size_t)ss[j] * IN_F);
                float4 v = p[t];
                float n = sn[j];
                a.x += v.x * n; a.y += v.y * n; a.z += v.z * n; a.w += v.w * n;
            }
        }
    }

    if (t <= NV) {
        if (t == NV) a = make_float4(0.f, 0.f, 0.f, 0.f);
        size_t o = (size_t)row * KP1 + t * 4;
        float vals[4] = {a.x, a.y, a.z, a.w};
        __nv_bfloat16 h[4], l[4];
        #pragma unroll
        for (int q = 0; q < 4; q++) {
            h[q] = __float2bfloat16(vals[q]);
            l[q] = __float2bfloat16(vals[q] - __bfloat162float(h[q]));
        }
        *(__nv_bfloat162*)(hi + o)     = *(__nv_bfloat162*)&h[0];
        *(__nv_bfloat162*)(hi + o + 2) = *(__nv_bfloat162*)&h[2];
        *(__nv_bfloat162*)(lo + o)     = *(__nv_bfloat162*)&l[0];
        *(__nv_bfloat162*)(lo + o + 2) = *(__nv_bfloat162*)&l[2];
    }
}

// ---------------- conv2 aggregation ----------------
__global__ void __launch_bounds__(128) agg2() {
    int row = blockIdx.x;
    int t = threadIdx.x;
    int beg = g_off_oo[row], end = g_off_oo[row + 1];
    float4 a = make_float4(0.f, 0.f, 0.f, 0.f);
    __shared__ int ss[128];

    for (int base = beg; base < end; base += 128) {
        int nB = min(128, end - base);
        __syncthreads();
        if (t < nB) ss[t] = g_csr_oo[base + t];
        __syncthreads();
        int j = 0;
        for (; j + 4 <= nB; j += 4) {
            const float4* p0 = (const float4*)(g_hs + (size_t)ss[j + 0] * HDIM);
            const float4* p1 = (const float4*)(g_hs + (size_t)ss[j + 1] * HDIM);
            const float4* p2 = (const float4*)(g_hs + (size_t)ss[j + 2] * HDIM);
            const float4* p3 = (const float4*)(g_hs + (size_t)ss[j + 3] * HDIM);
            float4 v0 = p0[t], v1 = p1[t], v2 = p2[t], v3 = p3[t];
            a.x += v0.x + v1.x + v2.x + v3.x;
            a.y += v0.y + v1.y + v2.y + v3.y;
            a.z += v0.z + v1.z + v2.z + v3.z;
            a.w += v0.w + v1.w + v2.w + v3.w;
        }
        for (; j < nB; j++) {
            const float4* p = (const float4*)(g_hs + (size_t)ss[j] * HDIM);
            float4 v = p[t];
            a.x += v.x; a.y += v.y; a.z += v.z; a.w += v.w;
        }
    }

    size_t o = (size_t)row * KP2 + t * 4;
    float vals[4] = {a.x, a.y, a.z, a.w};
    __nv_bfloat16 h[4], l[4];
    #pragma unroll
    for (int q = 0; q < 4; q++) {
        h[q] = __float2bfloat16(vals[q]);
        l[q] = __float2bfloat16(vals[q] - __bfloat162float(h[q]));
    }
    *(__nv_bfloat162*)(g_A2hi + o)     = *(__nv_bfloat162*)&h[0];
    *(__nv_bfloat162*)(g_A2hi + o + 2) = *(__nv_bfloat162*)&h[2];
    *(__nv_bfloat162*)(g_A2lo + o)     = *(__nv_bfloat162*)&l[0];
    *(__nv_bfloat162*)(g_A2lo + o + 2) = *(__nv_bfloat162*)&l[2];
}

// ---------------- GEMM primitives ----------------
__device__ __forceinline__ void cpasync16(void* smem_dst, const void* gmem_src) {
    uint32_t sa = (uint32_t)__cvta_generic_to_shared(smem_dst);
    asm volatile("cp.async.cg.shared.global [%0], [%1], 16;\n" :: "r"(sa), "l"(gmem_src));
}
__device__ __forceinline__ void cp_commit() { asm volatile("cp.async.commit_group;\n" ::: "memory"); }
template <int N>
__device__ __forceinline__ void cp_wait() { asm volatile("cp.async.wait_group %0;\n" :: "n"(N) : "memory"); }

__device__ __forceinline__ void ldsm4(uint32_t* r, const void* p) {
    uint32_t a = (uint32_t)__cvta_generic_to_shared(p);
    asm volatile("ldmatrix.sync.aligned.m8n8.x4.shared.b16 {%0,%1,%2,%3}, [%4];\n"
                 : "=r"(r[0]), "=r"(r[1]), "=r"(r[2]), "=r"(r[3]) : "r"(a));
}
__device__ __forceinline__ void ldsm4t(uint32_t* r, const void* p) {
    uint32_t a = (uint32_t)__cvta_generic_to_shared(p);
    asm volatile("ldmatrix.sync.aligned.m8n8.x4.trans.shared.b16 {%0,%1,%2,%3}, [%4];\n"
                 : "=r"(r[0]), "=r"(r[1]), "=r"(r[2]), "=r"(r[3]) : "r"(a));
}
__device__ __forceinline__ void mma_bf16(float* d, const uint32_t* a, uint32_t b0, uint32_t b1) {
    asm volatile("mma.sync.aligned.m16n8k16.row.col.f32.bf16.bf16.f32 "
                 "{%0,%1,%2,%3}, {%4,%5,%6,%7}, {%8,%9}, {%0,%1,%2,%3};\n"
                 : "+f"(d[0]), "+f"(d[1]), "+f"(d[2]), "+f"(d[3])
                 : "r"(a[0]), "r"(a[1]), "r"(a[2]), "r"(a[3]), "r"(b0), "r"(b1));
}

// smem stage types
typedef __nv_bfloat16 (*SA_t)[2][128][24];   // [stage][hi/lo][m][kpad]
typedef __nv_bfloat16 (*SB_t)[2][16][136];   // [stage][hi/lo][k][npad]
#define SMEM_A_BYTES (3 * 2 * 128 * 24 * 2)
#define SMEM_B_BYTES (3 * 2 * 16 * 136 * 2)
#define SMEM_BYTES   (SMEM_A_BYTES + SMEM_B_BYTES)

// ---------------- merged conv1 GEMM: hs = (sum_rel relu(A_rel@W+b)/3) * ns_oo
__global__ void __launch_bounds__(256, 1) gemm1(const float* __restrict__ b1i,
                                                const float* __restrict__ b1b) {
    extern __shared__ __align__(16) char smem[];
    SA_t sA = (SA_t)smem;
    SB_t sB = (SB_t)(smem + SMEM_A_BYTES);

    int tid = threadIdx.x;
    int warp = tid >> 5, lane = tid & 31;
    int row0 = blockIdx.y * 128, col0 = blockIdx.x * 128;
    int wr = warp >> 2, wc = warp & 3;

    float acc[4][4][4] = {};
    float accsum[4][4][4] = {};

    int aR = tid >> 1, aC = tid & 1;
    int bR = tid >> 4, bC = tid & 15;

    auto load_stage = [&](int t, int s) {
        int rel = (t < NTR) ? 0 : (t < 2 * NTR) ? 1 : 2;
        int tt = t - rel * NTR;
        int wsel = (rel == 2) ? 1 : 0;
        cpasync16(&sA[s][0][aR][aC * 8], g_A1hi[rel] + (size_t)(row0 + aR) * KP1 + tt * 16 + aC * 8);
        cpasync16(&sA[s][1][aR][aC * 8], g_A1lo[rel] + (size_t)(row0 + aR) * KP1 + tt * 16 + aC * 8);
        cpasync16(&sB[s][0][bR][bC * 8], g_Whi[wsel] + (size_t)(tt * 16 + bR) * HDIM + col0 + bC * 8);
        cpasync16(&sB[s][1][bR][bC * 8], g_Wlo[wsel] + (size_t)(tt * 16 + bR) * HDIM + col0 + bC * 8);
    };

    load_stage(0, 0); cp_commit();
    load_stage(1, 1); cp_commit();

    int s = 0;
    for (int t = 0; t < TT1; t++) {
        cp_wait<1>();
        __syncthreads();
        int tp = t + 2;
        if (tp < TT1) load_stage(tp, tp % 3);
        cp_commit();

        uint32_t ahi[4][4], alo[4][4], bhi[2][4], blo[2][4];
        int arow = wr * 64 + (lane & 15);
        int acol = (lane >> 4) * 8;
        #pragma unroll
        for (int m = 0; m < 4; m++) {
            ldsm4(ahi[m], &sA[s][0][arow + m * 16][acol]);
            ldsm4(alo[m], &sA[s][1][arow + m * 16][acol]);
        }
        int brow = lane & 15;
        int bcol = wc * 32 + (lane >> 4) * 8;
        #pragma unroll
        for (int p = 0; p < 2; p++) {
            ldsm4t(bhi[p], &sB[s][0][brow][bcol + p * 16]);
            ldsm4t(blo[p], &sB[s][1][brow][bcol + p * 16]);
        }
        #pragma unroll
        for (int m = 0; m < 4; m++)
            #pragma unroll
            for (int n = 0; n < 4; n++) {
                int p = n >> 1, h = n & 1;
                mma_bf16(acc[m][n], ahi[m], bhi[p][h * 2], bhi[p][h * 2 + 1]);
                mma_bf16(acc[m][n], ahi[m], blo[p][h * 2], blo[p][h * 2 + 1]);
                mma_bf16(acc[m][n], alo[m], bhi[p][h * 2], bhi[p][h * 2 + 1]);
            }

        int rel = (t < NTR) ? 0 : (t < 2 * NTR) ? 1 : 2;
        if (t == rel * NTR + NTR - 1) {
            const int* degin = (rel == 0) ? g_din_oo : (rel == 1) ? g_din_ro : g_din_ao;
            const float* bias = (rel == 2) ? b1b : b1i;
            const float third = 1.f / 3.f;
            #pragma unroll
            for (int m = 0; m < 4; m++) {
                int r1 = row0 + wr * 64 + m * 16 + (lane >> 2);
                int r2 = r1 + 8;
                float nd1 = (r1 < N_OBJ) ? rsqrtf((float)max(degin[r1], 1)) : 0.f;
                float nd2 = (r2 < N_OBJ) ? rsqrtf((float)max(degin[r2], 1)) : 0.f;
                #pragma unroll
                for (int n = 0; n < 4; n++) {
                    int c = col0 + wc * 32 + n * 8 + (lane & 3) * 2;
                    float bx = bias[c], by = bias[c + 1];
                    accsum[m][n][0] += fmaxf(acc[m][n][0] * nd1 + bx, 0.f) * third;
                    accsum[m][n][1] += fmaxf(acc[m][n][1] * nd1 + by, 0.f) * third;
                    accsum[m][n][2] += fmaxf(acc[m][n][2] * nd2 + bx, 0.f) * third;
                    accsum[m][n][3] += fmaxf(acc[m][n][3] * nd2 + by, 0.f) * third;
                    acc[m][n][0] = 0.f; acc[m][n][1] = 0.f;
                    acc[m][n][2] = 0.f; acc[m][n][3] = 0.f;
                }
            }
        }
        s++; if (s == 3) s = 0;
    }

    // final write: hs = accsum * ns_oo
    #pragma unroll
    for (int m = 0; m < 4; m++) {
        int r1 = row0 + wr * 64 + m * 16 + (lane >> 2);
        int r2 = r1 + 8;
        float sc1 = (r1 < N_OBJ) ? rsqrtf((float)max(g_dout_oo[r1], 1)) : 0.f;
        float sc2 = (r2 < N_OBJ) ? rsqrtf((float)max(g_dout_oo[r2], 1)) : 0.f;
        #pragma unroll
        for (int n = 0; n < 4; n++) {
            int c = col0 + wc * 32 + n * 8 + (lane & 3) * 2;
            if (r1 < N_OBJ)
                *(float2*)(g_hs + (size_t)r1 * HDIM + c) =
                    make_float2(accsum[m][n][0] * sc1, accsum[m][n][1] * sc1);
            if (r2 < N_OBJ)
                *(float2*)(g_hs + (size_t)r2 * HDIM + c) =
                    make_float2(accsum[m][n][2] * sc2, accsum[m][n][3] * sc2);
        }
    }
}

// ---------------- conv2 GEMM: out[b] = A2@W2*nd + b2, broadcast x8 ---------
__global__ void __launch_bounds__(256, 1) gemm2(const float* __restrict__ bias,
                                                float* __restrict__ outp) {
    extern __shared__ __align__(16) char smem[];
    SA_t sA = (SA_t)smem;
    SB_t sB = (SB_t)(smem + SMEM_A_BYTES);

    int tid = threadIdx.x;
    int warp = tid >> 5, lane = tid & 31;
    int row0 = blockIdx.y * 128, col0 = blockIdx.x * 128;
    int wr = warp >> 2, wc = warp & 3;

    float acc[4][4][4] = {};

    int aR = tid >> 1, aC = tid & 1;
    int bR = tid >> 4, bC = tid & 15;

    auto load_stage = [&](int t, int s) {
        cpasync16(&sA[s][0][aR][aC * 8], g_A2hi + (size_t)(row0 + aR) * KP2 + t * 16 + aC * 8);
        cpasync16(&sA[s][1][aR][aC * 8], g_A2lo + (size_t)(row0 + aR) * KP2 + t * 16 + aC * 8);
        cpasync16(&sB[s][0][bR][bC * 8], g_Whi[2] + (size_t)(t * 16 + bR) * HDIM + col0 + bC * 8);
        cpasync16(&sB[s][1][bR][bC * 8], g_Wlo[2] + (size_t)(t * 16 + bR) * HDIM + col0 + bC * 8);
    };

    load_stage(0, 0); cp_commit();
    load_stage(1, 1); cp_commit();

    int s = 0;
    for (int t = 0; t < TT2; t++) {
        cp_wait<1>();
        __syncthreads();
        int tp = t + 2;
        if (tp < TT2) load_stage(tp, tp % 3);
        cp_commit();

        uint32_t ahi[4][4], alo[4][4], bhi[2][4], blo[2][4];
        int arow = wr * 64 + (lane & 15);
        int acol = (lane >> 4) * 8;
        #pragma unroll
        for (int m = 0; m < 4; m++) {
            ldsm4(ahi[m], &sA[s][0][arow + m * 16][acol]);
            ldsm4(alo[m], &sA[s][1][arow + m * 16][acol]);
        }
        int brow = lane & 15;
        int bcol = wc * 32 + (lane >> 4) * 8;
        #pragma unroll
        for (int p = 0; p < 2; p++) {
            ldsm4t(bhi[p], &sB[s][0][brow][bcol + p * 16]);
            ldsm4t(blo[p], &sB[s][1][brow][bcol + p * 16]);
        }
        #pragma unroll
        for (int m = 0; m < 4; m++)
            #pragma unroll
            for (int n = 0; n < 4; n++) {
                int p = n >> 1, h = n & 1;
                mma_bf16(acc[m][n], ahi[m], bhi[p][h * 2], bhi[p][h * 2 + 1]);
                mma_bf16(acc[m][n], ahi[m], blo[p][h * 2], blo[p][h * 2 + 1]);
                mma_bf16(acc[m][n], alo[m], bhi[p][h * 2], bhi[p][h * 2 + 1]);
            }
        s++; if (s == 3) s = 0;
    }

    #pragma unroll
    for (int m = 0; m < 4; m++) {
        int r1 = row0 + wr * 64 + m * 16 + (lane >> 2);
        int r2 = r1 + 8;
        float nd1 = (r1 < N_OBJ) ? rsqrtf((float)max(g_din_oo[r1], 1)) : 0.f;
        float nd2 = (r2 < N_OBJ) ? rsqrtf((float)max(g_din_oo[r2], 1)) : 0.f;
        #pragma unroll
        for (int n = 0; n < 4; n++) {
            int c = col0 + wc * 32 + n * 8 + (lane & 3) * 2;
            float bx = bias[c], by = bias[c + 1];
            float v1x = acc[m][n][0] * nd1 + bx;
            float v1y = acc[m][n][1] * nd1 + by;
            float v2x = acc[m][n][2] * nd2 + bx;
            float v2y = acc[m][n][3] * nd2 + by;
            #pragma unroll
            for (int b = 0; b < BATCH; b++) {
                if (r1 < N_OBJ)
                    *(float2*)(outp + (size_t)b * N_OBJ * HDIM + (size_t)r1 * HDIM + c) =
                        make_float2(v1x, v1y);
                if (r2 < N_OBJ)
                    *(float2*)(outp + (size_t)b * N_OBJ * HDIM + (size_t)r2 * HDIM + c) =
                        make_float2(v2x, v2y);
            }
        }
    }
}

// ---------------- launch ----------------
extern "C" void kernel_launch(void* const* d_in, const int* in_sizes, int n_in,
                              void* d_out, int out_size) {
    const float* feat_obj  = (const float*)d_in[1];
    const float* feat_room = (const float*)d_in[2];
    const float* feat_attr = (const float*)d_in[3];
    const float* W1i = (const float*)d_in[4];
    const float* b1i = (const float*)d_in[5];
    const float* W1b = (const float*)d_in[6];
    const float* b1b = (const float*)d_in[7];
    const float* W2  = (const float*)d_in[8];
    const float* b2  = (const float*)d_in[9];
    const int* src_oo = (const int*)d_in[10];
    const int* dst_oo = (const int*)d_in[11];
    const int* src_ro = (const int*)d_in[12];
    const int* dst_ro = (const int*)d_in[13];
    const int* src_ao = (const int*)d_in[14];
    const int* dst_ao = (const int*)d_in[15];
    float* out = (float*)d_out;

    static bool attr_set = false;
    if (!attr_set) {
        cudaFuncSetAttribute(gemm1, cudaFuncAttributeMaxDynamicSharedMemorySize, SMEM_BYTES);
        cudaFuncSetAttribute(gemm2, cudaFuncAttributeMaxDynamicSharedMemorySize, SMEM_BYTES);
        attr_set = true;
    }

    const int ETOT = EOO + ERO + EAO;

    prep<<<512, 256>>>(W1i, W1b, W2);
    deg_all<<<(ETOT + 255) / 256, 256>>>(src_oo, dst_oo, src_ro, dst_ro, src_ao, dst_ao);
    scan3<<<3, 1024>>>();
    scatter_all<<<(ETOT + 255) / 256, 256>>>(src_oo, dst_oo, src_ro, dst_ro, src_ao, dst_ao);

    agg1_all<<<dim3(N_OBJ, 3), 128>>>(feat_obj, feat_room, feat_attr);

    dim3 grid(HDIM / 128, (N_OBJ + 127) / 128);
    gemm1<<<grid, 256, SMEM_BYTES>>>(b1i, b1b);

    agg2<<<N_OBJ, 128>>>();

    gemm2<<<grid, 256, SMEM_BYTES>>>(b2, out);
}

// round 7
// speedup vs baseline: 2.8181x; 1.2440x over previous
#include <cuda_runtime.h>
#include <cuda_fp16.h>
#include <cstdint>

#define N_OBJ  20000
#define N_ROOM 500
#define N_ATTR 2000
#define IN_F   300
#define HDIM   512
#define EOO    640000
#define ERO    50000
#define EAO    100000
#define BATCH  8

#define MP   20096
#define KP1  304
#define KP2  512
#define NTR  19            // KP1/16
#define TT1  57            // 3*NTR
#define TT2  32            // KP2/16

// ---------------- scratch (device globals, no allocation) ----------------
__device__ __half g_hs[(size_t)N_OBJ * HDIM];     // fp16 h_obj * ns_oo

__device__ int g_dout_oo[N_OBJ];
__device__ int g_din_oo [N_OBJ];
__device__ int g_dout_ro[N_ROOM];
__device__ int g_din_ro [N_OBJ];
__device__ int g_dout_ao[N_ATTR];
__device__ int g_din_ao [N_OBJ];

__device__ int g_off_oo[N_OBJ + 1];
__device__ int g_off_ro[N_OBJ + 1];
__device__ int g_off_ao[N_OBJ + 1];
__device__ int g_cnt_oo[N_OBJ];
__device__ int g_cnt_ro[N_OBJ];
__device__ int g_cnt_ao[N_OBJ];
__device__ int g_csr_oo[EOO];
__device__ int g_csr_ro[ERO];
__device__ int g_csr_ao[EAO];

__device__ __half g_A1hi[3][(size_t)MP * KP1];
__device__ __half g_A1lo[3][(size_t)MP * KP1];
__device__ __half g_A2hi[(size_t)MP * KP2];
__device__ __half g_A2lo[(size_t)MP * KP2];
__device__ __half g_W[3][(size_t)KP2 * HDIM];     // single fp16: 0:W1i 1:W1b 2:W2

// ---------------- prep: zero degrees + pad rows + weight fp16 convert ----
__global__ void prep(const float* __restrict__ W1i, const float* __restrict__ W1b,
                     const float* __restrict__ W2) {
    int tid    = blockIdx.x * blockDim.x + threadIdx.x;
    int stride = gridDim.x * blockDim.x;
    for (int i = tid; i < N_OBJ; i += stride) {
        g_dout_oo[i] = 0; g_din_oo[i] = 0; g_din_ro[i] = 0; g_din_ao[i] = 0;
    }
    for (int i = tid; i < N_ROOM; i += stride) g_dout_ro[i] = 0;
    for (int i = tid; i < N_ATTR; i += stride) g_dout_ao[i] = 0;
    const __half z = __float2half(0.f);
    int padA1 = (MP - N_OBJ) * KP1;
    for (int i = tid; i < padA1; i += stride) {
        size_t o = (size_t)N_OBJ * KP1 + i;
        g_A1hi[0][o] = z; g_A1lo[0][o] = z;
        g_A1hi[1][o] = z; g_A1lo[1][o] = z;
        g_A1hi[2][o] = z; g_A1lo[2][o] = z;
    }
    int padA2 = (MP - N_OBJ) * KP2;
    for (int i = tid; i < padA2; i += stride) {
        size_t o = (size_t)N_OBJ * KP2 + i;
        g_A2hi[o] = z; g_A2lo[o] = z;
    }
    const int n1 = KP1 * HDIM;
    for (int idx = tid; idx < n1; idx += stride) {
        int r = idx / HDIM;
        g_W[0][idx] = __float2half_rn((r < IN_F) ? W1i[idx] : 0.f);
        g_W[1][idx] = __float2half_rn((r < IN_F) ? W1b[idx] : 0.f);
    }
    const int n2 = KP2 * HDIM;
    for (int idx = tid; idx < n2; idx += stride)
        g_W[2][idx] = __float2half_rn(W2[idx]);
}

// ---------------- merged degree counting ----------------
__global__ void deg_all(const int* __restrict__ src_oo, const int* __restrict__ dst_oo,
                        const int* __restrict__ src_ro, const int* __restrict__ dst_ro,
                        const int* __restrict__ src_ao, const int* __restrict__ dst_ao) {
    int i = blockIdx.x * blockDim.x + threadIdx.x;
    if (i < EOO) {
        atomicAdd(&g_dout_oo[src_oo[i]], 1);
        atomicAdd(&g_din_oo [dst_oo[i]], 1);
    } else if (i < EOO + ERO) {
        int j = i - EOO;
        atomicAdd(&g_dout_ro[src_ro[j]], 1);
        atomicAdd(&g_din_ro [dst_ro[j]], 1);
    } else if (i < EOO + ERO + EAO) {
        int j = i - EOO - ERO;
        atomicAdd(&g_dout_ao[src_ao[j]], 1);
        atomicAdd(&g_din_ao [dst_ao[j]], 1);
    }
}

// ---------------- 3-block exclusive scan ----------------
__global__ void scan3() {
    int sel = blockIdx.x;
    const int* deg = (sel == 0) ? g_din_oo : (sel == 1) ? g_din_ro : g_din_ao;
    int* offs      = (sel == 0) ? g_off_oo : (sel == 1) ? g_off_ro : g_off_ao;
    int* cnt       = (sel == 0) ? g_cnt_oo : (sel == 1) ? g_cnt_ro : g_cnt_ao;
    __shared__ int part[1025];
    const int n = N_OBJ;
    int t = threadIdx.x;
    int chunk = (n + 1023) / 1024;
    int b = t * chunk, e = min(b + chunk, n);
    int s = 0;
    for (int i = b; i < e; i++) s += deg[i];
    part[t + 1] = s;
    if (t == 0) part[0] = 0;
    __syncthreads();
    for (int off = 1; off < 1024; off <<= 1) {
        int v = part[t + 1];
        if (t + 1 > off) v += part[t + 1 - off];
        __syncthreads();
        part[t + 1] = v;
        __syncthreads();
    }
    int run = part[t];
    for (int i = b; i < e; i++) { offs[i] = run; cnt[i] = run; run += deg[i]; }
    if (t == 0) offs[n] = part[1024];
}

// ---------------- merged edge scatter ----------------
__global__ void scatter_all(const int* __restrict__ src_oo, const int* __restrict__ dst_oo,
                            const int* __restrict__ src_ro, const int* __restrict__ dst_ro,
                            const int* __restrict__ src_ao, const int* __restrict__ dst_ao) {
    int i = blockIdx.x * blockDim.x + threadIdx.x;
    if (i < EOO) {
        int pos = atomicAdd(&g_cnt_oo[dst_oo[i]], 1);
        g_csr_oo[pos] = src_oo[i];
    } else if (i < EOO + ERO) {
        int j = i - EOO;
        int pos = atomicAdd(&g_cnt_ro[dst_ro[j]], 1);
        g_csr_ro[pos] = src_ro[j];
    } else if (i < EOO + ERO + EAO) {
        int j = i - EOO - ERO;
        int pos = atomicAdd(&g_cnt_ao[dst_ao[j]], 1);
        g_csr_ao[pos] = src_ao[j];
    }
}

// ---------------- conv1 aggregation (all 3 relations via blockIdx.y) -------
__global__ void __launch_bounds__(128) agg1_all(const float* __restrict__ fo,
                                                const float* __restrict__ fr,
                                                const float* __restrict__ fa) {
    int sel = blockIdx.y;
    const float* feat = (sel == 0) ? fo : (sel == 1) ? fr : fa;
    const int* offs   = (sel == 0) ? g_off_oo  : (sel == 1) ? g_off_ro  : g_off_ao;
    const int* csr    = (sel == 0) ? g_csr_oo  : (sel == 1) ? g_csr_ro  : g_csr_ao;
    const int* degout = (sel == 0) ? g_dout_oo : (sel == 1) ? g_dout_ro : g_dout_ao;
    __half* hi = g_A1hi[sel];
    __half* lo = g_A1lo[sel];

    int row = blockIdx.x;
    int t = threadIdx.x;
    int beg = offs[row], end = offs[row + 1];
    float4 a = make_float4(0.f, 0.f, 0.f, 0.f);
    __shared__ int   ss[128];
    __shared__ float sn[128];

    const int NV = IN_F / 4;            // 75
    for (int base = beg; base < end; base += 128) {
        int nB = min(128, end - base);
        __syncthreads();
        if (t < nB) {
            int s = csr[base + t];
            ss[t] = s;
            sn[t] = rsqrtf((float)max(degout[s], 1));
        }
        __syncthreads();
        int j = 0;
        if (t < NV) {
            for (; j + 4 <= nB; j += 4) {
                const float4* p0 = (const float4*)(feat + (size_t)ss[j + 0] * IN_F);
                const float4* p1 = (const float4*)(feat + (size_t)ss[j + 1] * IN_F);
                const float4* p2 = (const float4*)(feat + (size_t)ss[j + 2] * IN_F);
                const float4* p3 = (const float4*)(feat + (size_t)ss[j + 3] * IN_F);
                float4 v0 = p0[t], v1 = p1[t], v2 = p2[t], v3 = p3[t];
                float n0 = sn[j], n1 = sn[j + 1], n2 = sn[j + 2], n3 = sn[j + 3];
                a.x += v0.x * n0 + v1.x * n1 + v2.x * n2 + v3.x * n3;
                a.y += v0.y * n0 + v1.y * n1 + v2.y * n2 + v3.y * n3;
                a.z += v0.z * n0 + v1.z * n1 + v2.z * n2 + v3.z * n3;
                a.w += v0.w * n0 + v1.w * n1 + v2.w * n2 + v3.w * n3;
            }
            for (; j < nB; j++) {
                const float4* p = (const float4*)(feat + (size_t)ss[j] * IN_F);
                float4 v = p[t];
                float n = sn[j];
                a.x += v.x * n; a.y += v.y * n; a.z += v.z * n; a.w += v.w * n;
            }
        }
    }

    if (t <= NV) {
        if (t == NV) a = make_float4(0.f, 0.f, 0.f, 0.f);
        size_t o = (size_t)row * KP1 + t * 4;
        float vals[4] = {a.x, a.y, a.z, a.w};
        __half h[4], l[4];
        #pragma unroll
        for (int q = 0; q < 4; q++) {
            h[q] = __float2half_rn(vals[q]);
            l[q] = __float2half_rn(vals[q] - __half2float(h[q]));
        }
        *(__half2*)(hi + o)     = *(__half2*)&h[0];
        *(__half2*)(hi + o + 2) = *(__half2*)&h[2];
        *(__half2*)(lo + o)     = *(__half2*)&l[0];
        *(__half2*)(lo + o + 2) = *(__half2*)&l[2];
    }
}

// ---------------- conv2 aggregation (fp16 g_hs rows) ----------------
__global__ void __launch_bounds__(128) agg2() {
    int row = blockIdx.x;
    int t = threadIdx.x;
    int beg = g_off_oo[row], end = g_off_oo[row + 1];
    float4 a = make_float4(0.f, 0.f, 0.f, 0.f);
    __shared__ int ss[128];

    for (int base = beg; base < end; base += 128) {
        int nB = min(128, end - base);
        __syncthreads();
        if (t < nB) ss[t] = g_csr_oo[base + t];
        __syncthreads();
        int j = 0;
        for (; j + 4 <= nB; j += 4) {
            const uint2* p0 = (const uint2*)(g_hs + (size_t)ss[j + 0] * HDIM);
            const uint2* p1 = (const uint2*)(g_hs + (size_t)ss[j + 1] * HDIM);
            const uint2* p2 = (const uint2*)(g_hs + (size_t)ss[j + 2] * HDIM);
            const uint2* p3 = (const uint2*)(g_hs + (size_t)ss[j + 3] * HDIM);
            uint2 u0 = p0[t], u1 = p1[t], u2 = p2[t], u3 = p3[t];
            float2 c0 = __half22float2(*(__half2*)&u0.x), d0 = __half22float2(*(__half2*)&u0.y);
            float2 c1 = __half22float2(*(__half2*)&u1.x), d1 = __half22float2(*(__half2*)&u1.y);
            float2 c2 = __half22float2(*(__half2*)&u2.x), d2 = __half22float2(*(__half2*)&u2.y);
            float2 c3 = __half22float2(*(__half2*)&u3.x), d3 = __half22float2(*(__half2*)&u3.y);
            a.x += c0.x + c1.x + c2.x + c3.x;
            a.y += c0.y + c1.y + c2.y + c3.y;
            a.z += d0.x + d1.x + d2.x + d3.x;
            a.w += d0.y + d1.y + d2.y + d3.y;
        }
        for (; j < nB; j++) {
            uint2 u = ((const uint2*)(g_hs + (size_t)ss[j] * HDIM))[t];
            float2 c = __half22float2(*(__half2*)&u.x), d = __half22float2(*(__half2*)&u.y);
            a.x += c.x; a.y += c.y; a.z += d.x; a.w += d.y;
        }
    }

    size_t o = (size_t)row * KP2 + t * 4;
    float vals[4] = {a.x, a.y, a.z, a.w};
    __half h[4], l[4];
    #pragma unroll
    for (int q = 0; q < 4; q++) {
        h[q] = __float2half_rn(vals[q]);
        l[q] = __float2half_rn(vals[q] - __half2float(h[q]));
    }
    *(__half2*)(g_A2hi + o)     = *(__half2*)&h[0];
    *(__half2*)(g_A2hi + o + 2) = *(__half2*)&h[2];
    *(__half2*)(g_A2lo + o)     = *(__half2*)&l[0];
    *(__half2*)(g_A2lo + o + 2) = *(__half2*)&l[2];
}

// ---------------- GEMM primitives ----------------
__device__ __forceinline__ void cpasync16(void* smem_dst, const void* gmem_src) {
    uint32_t sa = (uint32_t)__cvta_generic_to_shared(smem_dst);
    asm volatile("cp.async.cg.shared.global [%0], [%1], 16;\n" :: "r"(sa), "l"(gmem_src));
}
__device__ __forceinline__ void cp_commit() { asm volatile("cp.async.commit_group;\n" ::: "memory"); }
template <int N>
__device__ __forceinline__ void cp_wait() { asm volatile("cp.async.wait_group %0;\n" :: "n"(N) : "memory"); }

__device__ __forceinline__ void ldsm4(uint32_t* r, const void* p) {
    uint32_t a = (uint32_t)__cvta_generic_to_shared(p);
    asm volatile("ldmatrix.sync.aligned.m8n8.x4.shared.b16 {%0,%1,%2,%3}, [%4];\n"
                 : "=r"(r[0]), "=r"(r[1]), "=r"(r[2]), "=r"(r[3]) : "r"(a));
}
__device__ __forceinline__ void ldsm4t(uint32_t* r, const void* p) {
    uint32_t a = (uint32_t)__cvta_generic_to_shared(p);
    asm volatile("ldmatrix.sync.aligned.m8n8.x4.trans.shared.b16 {%0,%1,%2,%3}, [%4];\n"
                 : "=r"(r[0]), "=r"(r[1]), "=r"(r[2]), "=r"(r[3]) : "r"(a));
}
__device__ __forceinline__ void mma_fp16(float* d, const uint32_t* a, uint32_t b0, uint32_t b1) {
    asm volatile("mma.sync.aligned.m16n8k16.row.col.f32.f16.f16.f32 "
                 "{%0,%1,%2,%3}, {%4,%5,%6,%7}, {%8,%9}, {%0,%1,%2,%3};\n"
                 : "+f"(d[0]), "+f"(d[1]), "+f"(d[2]), "+f"(d[3])
                 : "r"(a[0]), "r"(a[1]), "r"(a[2]), "r"(a[3]), "r"(b0), "r"(b1));
}

// smem stage types: A hi/lo, B single
typedef __half (*SA_t)[2][128][24];   // [stage][hi/lo][m][kpad]
typedef __half (*SB_t)[16][136];      // [stage][k][npad]
#define SMEM_A_BYTES (3 * 2 * 128 * 24 * 2)
#define SMEM_B_BYTES (3 * 16 * 136 * 2)
#define SMEM_BYTES   (SMEM_A_BYTES + SMEM_B_BYTES)

// ---------------- merged conv1 GEMM: hs = (sum_rel relu(A_rel@W+b)/3) * ns_oo
__global__ void __launch_bounds__(256, 1) gemm1(const float* __restrict__ b1i,
                                                const float* __restrict__ b1b) {
    extern __shared__ __align__(16) char smem[];
    SA_t sA = (SA_t)smem;
    SB_t sB = (SB_t)(smem + SMEM_A_BYTES);

    int tid = threadIdx.x;
    int warp = tid >> 5, lane = tid & 31;
    int row0 = blockIdx.y * 128, col0 = blockIdx.x * 128;
    int wr = warp >> 2, wc = warp & 3;

    float acc[4][4][4] = {};
    float accsum[4][4][4] = {};

    int aR = tid >> 1, aC = tid & 1;
    int bR = tid >> 4, bC = tid & 15;

    auto load_stage = [&](int t, int s) {
        int rel = (t < NTR) ? 0 : (t < 2 * NTR) ? 1 : 2;
        int tt = t - rel * NTR;
        int wsel = (rel == 2) ? 1 : 0;
        cpasync16(&sA[s][0][aR][aC * 8], g_A1hi[rel] + (size_t)(row0 + aR) * KP1 + tt * 16 + aC * 8);
        cpasync16(&sA[s][1][aR][aC * 8], g_A1lo[rel] + (size_t)(row0 + aR) * KP1 + tt * 16 + aC * 8);
        cpasync16(&sB[s][bR][bC * 8], g_W[wsel] + (size_t)(tt * 16 + bR) * HDIM + col0 + bC * 8);
    };

    load_stage(0, 0); cp_commit();
    load_stage(1, 1); cp_commit();

    int s = 0;
    for (int t = 0; t < TT1; t++) {
        cp_wait<1>();
        __syncthreads();
        int tp = t + 2;
        if (tp < TT1) load_stage(tp, tp % 3);
        cp_commit();

        uint32_t ahi[4][4], alo[4][4], bb[2][4];
        int arow = wr * 64 + (lane & 15);
        int acol = (lane >> 4) * 8;
        #pragma unroll
        for (int m = 0; m < 4; m++) {
            ldsm4(ahi[m], &sA[s][0][arow + m * 16][acol]);
            ldsm4(alo[m], &sA[s][1][arow + m * 16][acol]);
        }
        int brow = lane & 15;
        int bcol = wc * 32 + (lane >> 4) * 8;
        #pragma unroll
        for (int p = 0; p < 2; p++)
            ldsm4t(bb[p], &sB[s][brow][bcol + p * 16]);

        #pragma unroll
        for (int m = 0; m < 4; m++)
            #pragma unroll
            for (int n = 0; n < 4; n++) {
                int p = n >> 1, h = n & 1;
                mma_fp16(acc[m][n], ahi[m], bb[p][h * 2], bb[p][h * 2 + 1]);
                mma_fp16(acc[m][n], alo[m], bb[p][h * 2], bb[p][h * 2 + 1]);
            }

        int rel = (t < NTR) ? 0 : (t < 2 * NTR) ? 1 : 2;
        if (t == rel * NTR + NTR - 1) {
            const int* degin = (rel == 0) ? g_din_oo : (rel == 1) ? g_din_ro : g_din_ao;
            const float* bias = (rel == 2) ? b1b : b1i;
            const float third = 1.f / 3.f;
            #pragma unroll
            for (int m = 0; m < 4; m++) {
                int r1 = row0 + wr * 64 + m * 16 + (lane >> 2);
                int r2 = r1 + 8;
                float nd1 = (r1 < N_OBJ) ? rsqrtf((float)max(degin[r1], 1)) : 0.f;
                float nd2 = (r2 < N_OBJ) ? rsqrtf((float)max(degin[r2], 1)) : 0.f;
                #pragma unroll
                for (int n = 0; n < 4; n++) {
                    int c = col0 + wc * 32 + n * 8 + (lane & 3) * 2;
                    float bx = bias[c], by = bias[c + 1];
                    accsum[m][n][0] += fmaxf(acc[m][n][0] * nd1 + bx, 0.f) * third;
                    accsum[m][n][1] += fmaxf(acc[m][n][1] * nd1 + by, 0.f) * third;
                    accsum[m][n][2] += fmaxf(acc[m][n][2] * nd2 + bx, 0.f) * third;
                    accsum[m][n][3] += fmaxf(acc[m][n][3] * nd2 + by, 0.f) * third;
                    acc[m][n][0] = 0.f; acc[m][n][1] = 0.f;
                    acc[m][n][2] = 0.f; acc[m][n][3] = 0.f;
                }
            }
        }
        s++; if (s == 3) s = 0;
    }

    // final write: hs = accsum * ns_oo  (fp16)
    #pragma unroll
    for (int m = 0; m < 4; m++) {
        int r1 = row0 + wr * 64 + m * 16 + (lane >> 2);
        int r2 = r1 + 8;
        float sc1 = (r1 < N_OBJ) ? rsqrtf((float)max(g_dout_oo[r1], 1)) : 0.f;
        float sc2 = (r2 < N_OBJ) ? rsqrtf((float)max(g_dout_oo[r2], 1)) : 0.f;
        #pragma unroll
        for (int n = 0; n < 4; n++) {
            int c = col0 + wc * 32 + n * 8 + (lane & 3) * 2;
            if (r1 < N_OBJ)
                *(__half2*)(g_hs + (size_t)r1 * HDIM + c) =
                    __floats2half2_rn(accsum[m][n][0] * sc1, accsum[m][n][1] * sc1);
            if (r2 < N_OBJ)
                *(__half2*)(g_hs + (size_t)r2 * HDIM + c) =
                    __floats2half2_rn(accsum[m][n][2] * sc2, accsum[m][n][3] * sc2);
        }
    }
}

// ---------------- conv2 GEMM: out[b] = A2@W2*nd + b2, broadcast x8 ---------
__global__ void __launch_bounds__(256, 1) gemm2(const float* __restrict__ bias,
                                                float* __restrict__ outp) {
    extern __shared__ __align__(16) char smem[];
    SA_t sA = (SA_t)smem;
    SB_t sB = (SB_t)(smem + SMEM_A_BYTES);

    int tid = threadIdx.x;
    int warp = tid >> 5, lane = tid & 31;
    int row0 = blockIdx.y * 128, col0 = blockIdx.x * 128;
    int wr = warp >> 2, wc = warp & 3;

    float acc[4][4][4] = {};

    int aR = tid >> 1, aC = tid & 1;
    int bR = tid >> 4, bC = tid & 15;

    auto load_stage = [&](int t, int s) {
        cpasync16(&sA[s][0][aR][aC * 8], g_A2hi + (size_t)(row0 + aR) * KP2 + t * 16 + aC * 8);
        cpasync16(&sA[s][1][aR][aC * 8], g_A2lo + (size_t)(row0 + aR) * KP2 + t * 16 + aC * 8);
        cpasync16(&sB[s][bR][bC * 8], g_W[2] + (size_t)(t * 16 + bR) * HDIM + col0 + bC * 8);
    };

    load_stage(0, 0); cp_commit();
    load_stage(1, 1); cp_commit();

    int s = 0;
    for (int t = 0; t < TT2; t++) {
        cp_wait<1>();
        __syncthreads();
        int tp = t + 2;
        if (tp < TT2) load_stage(tp, tp % 3);
        cp_commit();

        uint32_t ahi[4][4], alo[4][4], bb[2][4];
        int arow = wr * 64 + (lane & 15);
        int acol = (lane >> 4) * 8;
        #pragma unroll
        for (int m = 0; m < 4; m++) {
            ldsm4(ahi[m], &sA[s][0][arow + m * 16][acol]);
            ldsm4(alo[m], &sA[s][1][arow + m * 16][acol]);
        }
        int brow = lane & 15;
        int bcol = wc * 32 + (lane >> 4) * 8;
        #pragma unroll
        for (int p = 0; p < 2; p++)
            ldsm4t(bb[p], &sB[s][brow][bcol + p * 16]);

        #pragma unroll
        for (int m = 0; m < 4; m++)
            #pragma unroll
            for (int n = 0; n < 4; n++) {
                int p = n >> 1, h = n & 1;
                mma_fp16(acc[m][n], ahi[m], bb[p][h * 2], bb[p][h * 2 + 1]);
                mma_fp16(acc[m][n], alo[m], bb[p][h * 2], bb[p][h * 2 + 1]);
            }
        s++; if (s == 3) s = 0;
    }

    #pragma unroll
    for (int m = 0; m < 4; m++) {
        int r1 = row0 + wr * 64 + m * 16 + (lane >> 2);
        int r2 = r1 + 8;
        float nd1 = (r1 < N_OBJ) ? rsqrtf((float)max(g_din_oo[r1], 1)) : 0.f;
        float nd2 = (r2 < N_OBJ) ? rsqrtf((float)max(g_din_oo[r2], 1)) : 0.f;
        #pragma unroll
        for (int n = 0; n < 4; n++) {
            int c = col0 + wc * 32 + n * 8 + (lane & 3) * 2;
            float bx = bias[c], by = bias[c + 1];
            float v1x = acc[m][n][0] * nd1 + bx;
            float v1y = acc[m][n][1] * nd1 + by;
            float v2x = acc[m][n][2] * nd2 + bx;
            float v2y = acc[m][n][3] * nd2 + by;
            #pragma unroll
            for (int b = 0; b < BATCH; b++) {
                if (r1 < N_OBJ)
                    *(float2*)(outp + (size_t)b * N_OBJ * HDIM + (size_t)r1 * HDIM + c) =
                        make_float2(v1x, v1y);
                if (r2 < N_OBJ)
                    *(float2*)(outp + (size_t)b * N_OBJ * HDIM + (size_t)r2 * HDIM + c) =
                        make_float2(v2x, v2y);
            }
        }
    }
}

// ---------------- launch ----------------
extern "C" void kernel_launch(void* const* d_in, const int* in_sizes, int n_in,
                              void* d_out, int out_size) {
    const float* feat_obj  = (const float*)d_in[1];
    const float* feat_room = (const float*)d_in[2];
    const float* feat_attr = (const float*)d_in[3];
    const float* W1i = (const float*)d_in[4];
    const float* b1i = (const float*)d_in[5];
    const float* W1b = (const float*)d_in[6];
    const float* b1b = (const float*)d_in[7];
    const float* W2  = (const float*)d_in[8];
    const float* b2  = (const float*)d_in[9];
    const int* src_oo = (const int*)d_in[10];
    const int* dst_oo = (const int*)d_in[11];
    const int* src_ro = (const int*)d_in[12];
    const int* dst_ro = (const int*)d_in[13];
    const int* src_ao = (const int*)d_in[14];
    const int* dst_ao = (const int*)d_in[15];
    float* out = (float*)d_out;

    static bool attr_set = false;
    if (!attr_set) {
        cudaFuncSetAttribute(gemm1, cudaFuncAttributeMaxDynamicSharedMemorySize, SMEM_BYTES);
        cudaFuncSetAttribute(gemm2, cudaFuncAttributeMaxDynamicSharedMemorySize, SMEM_BYTES);
        attr_set = true;
    }

    const int ETOT = EOO + ERO + EAO;

    prep<<<512, 256>>>(W1i, W1b, W2);
    deg_all<<<(ETOT + 255) / 256, 256>>>(src_oo, dst_oo, src_ro, dst_ro, src_ao, dst_ao);
    scan3<<<3, 1024>>>();
    scatter_all<<<(ETOT + 255) / 256, 256>>>(src_oo, dst_oo, src_ro, dst_ro, src_ao, dst_ao);

    agg1_all<<<dim3(N_OBJ, 3), 128>>>(feat_obj, feat_room, feat_attr);

    dim3 grid(HDIM / 128, (N_OBJ + 127) / 128);
    gemm1<<<grid, 256, SMEM_BYTES>>>(b1i, b1b);

    agg2<<<N_OBJ, 128>>>();

    gemm2<<<grid, 256, SMEM_BYTES>>>(b2, out);
}

// round 9
// speedup vs baseline: 3.4037x; 1.2078x over previous
#include <cuda_runtime.h>
#include <cuda_fp16.h>
#include <cstdint>

#define N_OBJ  20000
#define N_ROOM 500
#define N_ATTR 2000
#define IN_F   300
#define HDIM   512
#define EOO    640000
#define ERO    50000
#define EAO    100000
#define BATCH  8

#define MP   20096
#define KP1  304
#define KP2  512
#define NTR  19            // KP1/16
#define TT1  57            // 3*NTR
#define TT2  32            // KP2/16

// ---------------- scratch (device globals, no allocation) ----------------
__device__ __half g_hs[(size_t)N_OBJ * HDIM];     // fp16 h_obj * ns_oo

__device__ __half g_fo16[(size_t)N_OBJ  * IN_F];  // fp16 feature tables
__device__ __half g_fr16[(size_t)N_ROOM * IN_F];
__device__ __half g_fa16[(size_t)N_ATTR * IN_F];

__device__ int g_dout_oo[N_OBJ];
__device__ int g_din_oo [N_OBJ];
__device__ int g_dout_ro[N_ROOM];
__device__ int g_din_ro [N_OBJ];
__device__ int g_dout_ao[N_ATTR];
__device__ int g_din_ao [N_OBJ];

__device__ int g_off_oo[N_OBJ + 1];
__device__ int g_off_ro[N_OBJ + 1];
__device__ int g_off_ao[N_OBJ + 1];
__device__ int g_cnt_oo[N_OBJ];
__device__ int g_cnt_ro[N_OBJ];
__device__ int g_cnt_ao[N_OBJ];
__device__ int g_csr_oo[EOO];
__device__ int g_csr_ro[ERO];
__device__ int g_csr_ao[EAO];

__device__ __half g_A1[3][(size_t)MP * KP1];      // single fp16 activations
__device__ __half g_A2[(size_t)MP * KP2];
__device__ __half g_W[3][(size_t)KP2 * HDIM];     // 0:W1i 1:W1b 2:W2

// ---------------- prep: zero degs + pad rows + fp16 converts ----------
__global__ void prep(const float* __restrict__ W1i, const float* __restrict__ W1b,
                     const float* __restrict__ W2,
                     const float* __restrict__ fo, const float* __restrict__ fr,
                     const float* __restrict__ fa) {
    int tid    = blockIdx.x * blockDim.x + threadIdx.x;
    int stride = gridDim.x * blockDim.x;
    for (int i = tid; i < N_OBJ; i += stride) {
        g_dout_oo[i] = 0; g_din_oo[i] = 0; g_din_ro[i] = 0; g_din_ao[i] = 0;
    }
    for (int i = tid; i < N_ROOM; i += stride) g_dout_ro[i] = 0;
    for (int i = tid; i < N_ATTR; i += stride) g_dout_ao[i] = 0;
    const __half z = __float2half(0.f);
    int padA1 = (MP - N_OBJ) * KP1;
    for (int i = tid; i < padA1; i += stride) {
        size_t o = (size_t)N_OBJ * KP1 + i;
        g_A1[0][o] = z; g_A1[1][o] = z; g_A1[2][o] = z;
    }
    int padA2 = (MP - N_OBJ) * KP2;
    for (int i = tid; i < padA2; i += stride)
        g_A2[(size_t)N_OBJ * KP2 + i] = z;

    const int n1 = KP1 * HDIM;
    for (int idx = tid; idx < n1; idx += stride) {
        int r = idx / HDIM;
        g_W[0][idx] = __float2half_rn((r < IN_F) ? W1i[idx] : 0.f);
        g_W[1][idx] = __float2half_rn((r < IN_F) ? W1b[idx] : 0.f);
    }
    const int n2 = KP2 * HDIM;
    for (int idx = tid; idx < n2; idx += stride)
        g_W[2][idx] = __float2half_rn(W2[idx]);

    // feature tables -> fp16
    const int nfo = N_OBJ * IN_F;
    for (int idx = tid; idx < nfo; idx += stride) g_fo16[idx] = __float2half_rn(fo[idx]);
    const int nfr = N_ROOM * IN_F;
    for (int idx = tid; idx < nfr; idx += stride) g_fr16[idx] = __float2half_rn(fr[idx]);
    const int nfa = N_ATTR * IN_F;
    for (int idx = tid; idx < nfa; idx += stride) g_fa16[idx] = __float2half_rn(fa[idx]);
}

// ---------------- merged degree counting ----------------
__global__ void deg_all(const int* __restrict__ src_oo, const int* __restrict__ dst_oo,
                        const int* __restrict__ src_ro, const int* __restrict__ dst_ro,
                        const int* __restrict__ src_ao, const int* __restrict__ dst_ao) {
    int i = blockIdx.x * blockDim.x + threadIdx.x;
    if (i < EOO) {
        atomicAdd(&g_dout_oo[src_oo[i]], 1);
        atomicAdd(&g_din_oo [dst_oo[i]], 1);
    } else if (i < EOO + ERO) {
        int j = i - EOO;
        atomicAdd(&g_dout_ro[src_ro[j]], 1);
        atomicAdd(&g_din_ro [dst_ro[j]], 1);
    } else if (i < EOO + ERO + EAO) {
        int j = i - EOO - ERO;
        atomicAdd(&g_dout_ao[src_ao[j]], 1);
        atomicAdd(&g_din_ao [dst_ao[j]], 1);
    }
}

// ---------------- 3-block exclusive scan ----------------
__global__ void scan3() {
    int sel = blockIdx.x;
    const int* deg = (sel == 0) ? g_din_oo : (sel == 1) ? g_din_ro : g_din_ao;
    int* offs      = (sel == 0) ? g_off_oo : (sel == 1) ? g_off_ro : g_off_ao;
    int* cnt       = (sel == 0) ? g_cnt_oo : (sel == 1) ? g_cnt_ro : g_cnt_ao;
    __shared__ int part[1025];
    const int n = N_OBJ;
    int t = threadIdx.x;
    int chunk = (n + 1023) / 1024;
    int b = t * chunk, e = min(b + chunk, n);
    int s = 0;
    for (int i = b; i < e; i++) s += deg[i];
    part[t + 1] = s;
    if (t == 0) part[0] = 0;
    __syncthreads();
    for (int off = 1; off < 1024; off <<= 1) {
        int v = part[t + 1];
        if (t + 1 > off) v += part[t + 1 - off];
        __syncthreads();
        part[t + 1] = v;
        __syncthreads();
    }
    int run = part[t];
    for (int i = b; i < e; i++) { offs[i] = run; cnt[i] = run; run += deg[i]; }
    if (t == 0) offs[n] = part[1024];
}

// ---------------- merged edge scatter ----------------
__global__ void scatter_all(const int* __restrict__ src_oo, const int* __restrict__ dst_oo,
                            const int* __restrict__ src_ro, const int* __restrict__ dst_ro,
                            const int* __restrict__ src_ao, const int* __restrict__ dst_ao) {
    int i = blockIdx.x * blockDim.x + threadIdx.x;
    if (i < EOO) {
        int pos = atomicAdd(&g_cnt_oo[dst_oo[i]], 1);
        g_csr_oo[pos] = src_oo[i];
    } else if (i < EOO + ERO) {
        int j = i - EOO;
        int pos = atomicAdd(&g_cnt_ro[dst_ro[j]], 1);
        g_csr_ro[pos] = src_ro[j];
    } else if (i < EOO + ERO + EAO) {
        int j = i - EOO - ERO;
        int pos = atomicAdd(&g_cnt_ao[dst_ao[j]], 1);
        g_csr_ao[pos] = src_ao[j];
    }
}

// ---------------- conv1 aggregation (fp16 features, fp32 accum) -------
__global__ void __launch_bounds__(128) agg1_all() {
    int sel = blockIdx.y;
    const __half* feat = (sel == 0) ? g_fo16 : (sel == 1) ? g_fr16 : g_fa16;
    const int* offs   = (sel == 0) ? g_off_oo  : (sel == 1) ? g_off_ro  : g_off_ao;
    const int* csr    = (sel == 0) ? g_csr_oo  : (sel == 1) ? g_csr_ro  : g_csr_ao;
    const int* degout = (sel == 0) ? g_dout_oo : (sel == 1) ? g_dout_ro : g_dout_ao;
    __half* A = g_A1[sel];

    int row = blockIdx.x;
    int t = threadIdx.x;
    int beg = offs[row], end = offs[row + 1];
    float4 a = make_float4(0.f, 0.f, 0.f, 0.f);
    __shared__ int   ss[128];
    __shared__ float sn[128];

    const int NV = IN_F / 4;            // 75 uint2-chunks of 4 halves
    for (int base = beg; base < end; base += 128) {
        int nB = min(128, end - base);
        __syncthreads();
        if (t < nB) {
            int s = csr[base + t];
            ss[t] = s;
            sn[t] = rsqrtf((float)max(degout[s], 1));
        }
        __syncthreads();
        int j = 0;
        if (t < NV) {
            for (; j + 4 <= nB; j += 4) {
                const uint2* p0 = (const uint2*)(feat + (size_t)ss[j + 0] * IN_F);
                const uint2* p1 = (const uint2*)(feat + (size_t)ss[j + 1] * IN_F);
                const uint2* p2 = (const uint2*)(feat + (size_t)ss[j + 2] * IN_F);
                const uint2* p3 = (const uint2*)(feat + (size_t)ss[j + 3] * IN_F);
                uint2 u0 = p0[t], u1 = p1[t], u2 = p2[t], u3 = p3[t];
                float n0 = sn[j], n1 = sn[j + 1], n2 = sn[j + 2], n3 = sn[j + 3];
                float2 c0 = __half22float2(*(__half2*)&u0.x), d0 = __half22float2(*(__half2*)&u0.y);
                float2 c1 = __half22float2(*(__half2*)&u1.x), d1 = __half22float2(*(__half2*)&u1.y);
                float2 c2 = __half22float2(*(__half2*)&u2.x), d2 = __half22float2(*(__half2*)&u2.y);
                float2 c3 = __half22float2(*(__half2*)&u3.x), d3 = __half22float2(*(__half2*)&u3.y);
                a.x += c0.x * n0 + c1.x * n1 + c2.x * n2 + c3.x * n3;
                a.y += c0.y * n0 + c1.y * n1 + c2.y * n2 + c3.y * n3;
                a.z += d0.x * n0 + d1.x * n1 + d2.x * n2 + d3.x * n3;
                a.w += d0.y * n0 + d1.y * n1 + d2.y * n2 + d3.y * n3;
            }
            for (; j < nB; j++) {
                uint2 u = ((const uint2*)(feat + (size_t)ss[j] * IN_F))[t];
                float n = sn[j];
                float2 c = __half22float2(*(__half2*)&u.x), d = __half22float2(*(__half2*)&u.y);
                a.x += c.x * n; a.y += c.y * n; a.z += d.x * n; a.w += d.y * n;
            }
        }
    }

    if (t <= NV) {
        if (t == NV) a = make_float4(0.f, 0.f, 0.f, 0.f);
        size_t o = (size_t)row * KP1 + t * 4;
        *(__half2*)(A + o)     = __floats2half2_rn(a.x, a.y);
        *(__half2*)(A + o + 2) = __floats2half2_rn(a.z, a.w);
    }
}

// ---------------- conv2 aggregation (fp16 g_hs, fp32 accum) ----------------
__global__ void __launch_bounds__(128) agg2() {
    int row = blockIdx.x;
    int t = threadIdx.x;
    int beg = g_off_oo[row], end = g_off_oo[row + 1];
    float4 a = make_float4(0.f, 0.f, 0.f, 0.f);
    __shared__ int ss[128];

    for (int base = beg; base < end; base += 128) {
        int nB = min(128, end - base);
        __syncthreads();
        if (t < nB) ss[t] = g_csr_oo[base + t];
        __syncthreads();
        int j = 0;
        for (; j + 4 <= nB; j += 4) {
            const uint2* p0 = (const uint2*)(g_hs + (size_t)ss[j + 0] * HDIM);
            const uint2* p1 = (const uint2*)(g_hs + (size_t)ss[j + 1] * HDIM);
            const uint2* p2 = (const uint2*)(g_hs + (size_t)ss[j + 2] * HDIM);
            const uint2* p3 = (const uint2*)(g_hs + (size_t)ss[j + 3] * HDIM);
            uint2 u0 = p0[t], u1 = p1[t], u2 = p2[t], u3 = p3[t];
            float2 c0 = __half22float2(*(__half2*)&u0.x), d0 = __half22float2(*(__half2*)&u0.y);
            float2 c1 = __half22float2(*(__half2*)&u1.x), d1 = __half22float2(*(__half2*)&u1.y);
            float2 c2 = __half22float2(*(__half2*)&u2.x), d2 = __half22float2(*(__half2*)&u2.y);
            float2 c3 = __half22float2(*(__half2*)&u3.x), d3 = __half22float2(*(__half2*)&u3.y);
            a.x += c0.x + c1.x + c2.x + c3.x;
            a.y += c0.y + c1.y + c2.y + c3.y;
            a.z += d0.x + d1.x + d2.x + d3.x;
            a.w += d0.y + d1.y + d2.y + d3.y;
        }
        for (; j < nB; j++) {
            uint2 u = ((const uint2*)(g_hs + (size_t)ss[j] * HDIM))[t];
            float2 c = __half22float2(*(__half2*)&u.x), d = __half22float2(*(__half2*)&u.y);
            a.x += c.x; a.y += c.y; a.z += d.x; a.w += d.y;
        }
    }

    size_t o = (size_t)row * KP2 + t * 4;
    *(__half2*)(g_A2 + o)     = __floats2half2_rn(a.x, a.y);
    *(__half2*)(g_A2 + o + 2) = __floats2half2_rn(a.z, a.w);
}

// ---------------- GEMM primitives ----------------
__device__ __forceinline__ void cpasync16(void* smem_dst, const void* gmem_src) {
    uint32_t sa = (uint32_t)__cvta_generic_to_shared(smem_dst);
    asm volatile("cp.async.cg.shared.global [%0], [%1], 16;\n" :: "r"(sa), "l"(gmem_src));
}
__device__ __forceinline__ void cp_commit() { asm volatile("cp.async.commit_group;\n" ::: "memory"); }
template <int N>
__device__ __forceinline__ void cp_wait() { asm volatile("cp.async.wait_group %0;\n" :: "n"(N) : "memory"); }

__device__ __forceinline__ void ldsm4(uint32_t* r, const void* p) {
    uint32_t a = (uint32_t)__cvta_generic_to_shared(p);
    asm volatile("ldmatrix.sync.aligned.m8n8.x4.shared.b16 {%0,%1,%2,%3}, [%4];\n"
                 : "=r"(r[0]), "=r"(r[1]), "=r"(r[2]), "=r"(r[3]) : "r"(a));
}
__device__ __forceinline__ void ldsm4t(uint32_t* r, const void* p) {
    uint32_t a = (uint32_t)__cvta_generic_to_shared(p);
    asm volatile("ldmatrix.sync.aligned.m8n8.x4.trans.shared.b16 {%0,%1,%2,%3}, [%4];\n"
                 : "=r"(r[0]), "=r"(r[1]), "=r"(r[2]), "=r"(r[3]) : "r"(a));
}
__device__ __forceinline__ void mma_fp16(float* d, const uint32_t* a, uint32_t b0, uint32_t b1) {
    asm volatile("mma.sync.aligned.m16n8k16.row.col.f32.f16.f16.f32 "
                 "{%0,%1,%2,%3}, {%4,%5,%6,%7}, {%8,%9}, {%0,%1,%2,%3};\n"
                 : "+f"(d[0]), "+f"(d[1]), "+f"(d[2]), "+f"(d[3])
                 : "r"(a[0]), "r"(a[1]), "r"(a[2]), "r"(a[3]), "r"(b0), "r"(b1));
}

// smem stage types: single-precision-level fp16 A and B
typedef __half (*SA_t)[128][24];      // [stage][m][kpad]
typedef __half (*SB_t)[16][136];      // [stage][k][npad]
#define SMEM_A_BYTES (3 * 128 * 24 * 2)
#define SMEM_B_BYTES (3 * 16 * 136 * 2)
#define SMEM_BYTES   (SMEM_A_BYTES + SMEM_B_BYTES)

// ---------------- merged conv1 GEMM: hs = (sum_rel relu(A_rel@W+b)/3) * ns_oo
__global__ void __launch_bounds__(256, 1) gemm1(const float* __restrict__ b1i,
                                                const float* __restrict__ b1b) {
    extern __shared__ __align__(16) char smem[];
    SA_t sA = (SA_t)smem;
    SB_t sB = (SB_t)(smem + SMEM_A_BYTES);

    int tid = threadIdx.x;
    int warp = tid >> 5, lane = tid & 31;
    int row0 = blockIdx.y * 128, col0 = blockIdx.x * 128;
    int wr = warp >> 2, wc = warp & 3;

    float acc[4][4][4] = {};
    float accsum[4][4][4] = {};

    int aR = tid >> 1, aC = tid & 1;
    int bR = tid >> 4, bC = tid & 15;

    auto load_stage = [&](int t, int s) {
        int rel = (t < NTR) ? 0 : (t < 2 * NTR) ? 1 : 2;
        int tt = t - rel * NTR;
        int wsel = (rel == 2) ? 1 : 0;
        cpasync16(&sA[s][aR][aC * 8], g_A1[rel] + (size_t)(row0 + aR) * KP1 + tt * 16 + aC * 8);
        cpasync16(&sB[s][bR][bC * 8], g_W[wsel] + (size_t)(tt * 16 + bR) * HDIM + col0 + bC * 8);
    };

    load_stage(0, 0); cp_commit();
    load_stage(1, 1); cp_commit();

    int s = 0;
    for (int t = 0; t < TT1; t++) {
        cp_wait<1>();
        __syncthreads();
        int tp = t + 2;
        if (tp < TT1) load_stage(tp, tp % 3);
        cp_commit();

        uint32_t aa[4][4], bb[2][4];
        int arow = wr * 64 + (lane & 15);
        int acol = (lane >> 4) * 8;
        #pragma unroll
        for (int m = 0; m < 4; m++)
            ldsm4(aa[m], &sA[s][arow + m * 16][acol]);
        int brow = lane & 15;
        int bcol = wc * 32 + (lane >> 4) * 8;
        #pragma unroll
        for (int p = 0; p < 2; p++)
            ldsm4t(bb[p], &sB[s][brow][bcol + p * 16]);

        #pragma unroll
        for (int m = 0; m < 4; m++)
            #pragma unroll
            for (int n = 0; n < 4; n++) {
                int p = n >> 1, h = n & 1;
                mma_fp16(acc[m][n], aa[m], bb[p][h * 2], bb[p][h * 2 + 1]);
            }

        int rel = (t < NTR) ? 0 : (t < 2 * NTR) ? 1 : 2;
        if (t == rel * NTR + NTR - 1) {
            const int* degin = (rel == 0) ? g_din_oo : (rel == 1) ? g_din_ro : g_din_ao;
            const float* bias = (rel == 2) ? b1b : b1i;
            const float third = 1.f / 3.f;
            #pragma unroll
            for (int m = 0; m < 4; m++) {
                int r1 = row0 + wr * 64 + m * 16 + (lane >> 2);
                int r2 = r1 + 8;
                float nd1 = (r1 < N_OBJ) ? rsqrtf((float)max(degin[r1], 1)) : 0.f;
                float nd2 = (r2 < N_OBJ) ? rsqrtf((float)max(degin[r2], 1)) : 0.f;
                #pragma unroll
                for (int n = 0; n < 4; n++) {
                    int c = col0 + wc * 32 + n * 8 + (lane & 3) * 2;
                    float bx = bias[c], by = bias[c + 1];
                    accsum[m][n][0] += fmaxf(acc[m][n][0] * nd1 + bx, 0.f) * third;
                    accsum[m][n][1] += fmaxf(acc[m][n][1] * nd1 + by, 0.f) * third;
                    accsum[m][n][2] += fmaxf(acc[m][n][2] * nd2 + bx, 0.f) * third;
                    accsum[m][n][3] += fmaxf(acc[m][n][3] * nd2 + by, 0.f) * third;
                    acc[m][n][0] = 0.f; acc[m][n][1] = 0.f;
                    acc[m][n][2] = 0.f; acc[m][n][3] = 0.f;
                }
            }
        }
        s++; if (s == 3) s = 0;
    }

    // final write: hs = accsum * ns_oo  (fp16)
    #pragma unroll
    for (int m = 0; m < 4; m++) {
        int r1 = row0 + wr * 64 + m * 16 + (lane >> 2);
        int r2 = r1 + 8;
        float sc1 = (r1 < N_OBJ) ? rsqrtf((float)max(g_dout_oo[r1], 1)) : 0.f;
        float sc2 = (r2 < N_OBJ) ? rsqrtf((float)max(g_dout_oo[r2], 1)) : 0.f;
        #pragma unroll
        for (int n = 0; n < 4; n++) {
            int c = col0 + wc * 32 + n * 8 + (lane & 3) * 2;
            if (r1 < N_OBJ)
                *(__half2*)(g_hs + (size_t)r1 * HDIM + c) =
                    __floats2half2_rn(accsum[m][n][0] * sc1, accsum[m][n][1] * sc1);
            if (r2 < N_OBJ)
                *(__half2*)(g_hs + (size_t)r2 * HDIM + c) =
                    __floats2half2_rn(accsum[m][n][2] * sc2, accsum[m][n][3] * sc2);
        }
    }
}

// ---------------- conv2 GEMM: out[b] = A2@W2*nd + b2, broadcast x8 ---------
__global__ void __launch_bounds__(256, 1) gemm2(const float* __restrict__ bias,
                                                float* __restrict__ outp) {
    extern __shared__ __align__(16) char smem[];
    SA_t sA = (SA_t)smem;
    SB_t sB = (SB_t)(smem + SMEM_A_BYTES);

    int tid = threadIdx.x;
    int warp = tid >> 5, lane = tid & 31;
    int row0 = blockIdx.y * 128, col0 = blockIdx.x * 128;
    int wr = warp >> 2, wc = warp & 3;

    float acc[4][4][4] = {};

    int aR = tid >> 1, aC = tid & 1;
    int bR = tid >> 4, bC = tid & 15;

    auto load_stage = [&](int t, int s) {
        cpasync16(&sA[s][aR][aC * 8], g_A2 + (size_t)(row0 + aR) * KP2 + t * 16 + aC * 8);
        cpasync16(&sB[s][bR][bC * 8], g_W[2] + (size_t)(t * 16 + bR) * HDIM + col0 + bC * 8);
    };

    load_stage(0, 0); cp_commit();
    load_stage(1, 1); cp_commit();

    int s = 0;
    for (int t = 0; t < TT2; t++) {
        cp_wait<1>();
        __syncthreads();
        int tp = t + 2;
        if (tp < TT2) load_stage(tp, tp % 3);
        cp_commit();

        uint32_t aa[4][4], bb[2][4];
        int arow = wr * 64 + (lane & 15);
        int acol = (lane >> 4) * 8;
        #pragma unroll
        for (int m = 0; m < 4; m++)
            ldsm4(aa[m], &sA[s][arow + m * 16][acol]);
        int brow = lane & 15;
        int bcol = wc * 32 + (lane >> 4) * 8;
        #pragma unroll
        for (int p = 0; p < 2; p++)
            ldsm4t(bb[p], &sB[s][brow][bcol + p * 16]);

        #pragma unroll
        for (int m = 0; m < 4; m++)
            #pragma unroll
            for (int n = 0; n < 4; n++) {
                int p = n >> 1, h = n & 1;
                mma_fp16(acc[m][n], aa[m], bb[p][h * 2], bb[p][h * 2 + 1]);
            }
        s++; if (s == 3) s = 0;
    }

    #pragma unroll
    for (int m = 0; m < 4; m++) {
        int r1 = row0 + wr * 64 + m * 16 + (lane >> 2);
        int r2 = r1 + 8;
        float nd1 = (r1 < N_OBJ) ? rsqrtf((float)max(g_din_oo[r1], 1)) : 0.f;
        float nd2 = (r2 < N_OBJ) ? rsqrtf((float)max(g_din_oo[r2], 1)) : 0.f;
        #pragma unroll
        for (int n = 0; n < 4; n++) {
            int c = col0 + wc * 32 + n * 8 + (lane & 3) * 2;
            float bx = bias[c], by = bias[c + 1];
            float v1x = acc[m][n][0] * nd1 + bx;
            float v1y = acc[m][n][1] * nd1 + by;
            float v2x = acc[m][n][2] * nd2 + bx;
            float v2y = acc[m][n][3] * nd2 + by;
            #pragma unroll
            for (int b = 0; b < BATCH; b++) {
                if (r1 < N_OBJ)
                    *(float2*)(outp + (size_t)b * N_OBJ * HDIM + (size_t)r1 * HDIM + c) =
                        make_float2(v1x, v1y);
                if (r2 < N_OBJ)
                    *(float2*)(outp + (size_t)b * N_OBJ * HDIM + (size_t)r2 * HDIM + c) =
                        make_float2(v2x, v2y);
            }
        }
    }
}

// ---------------- launch ----------------
extern "C" void kernel_launch(void* const* d_in, const int* in_sizes, int n_in,
                              void* d_out, int out_size) {
    const float* feat_obj  = (const float*)d_in[1];
    const float* feat_room = (const float*)d_in[2];
    const float* feat_attr = (const float*)d_in[3];
    const float* W1i = (const float*)d_in[4];
    const float* b1i = (const float*)d_in[5];
    const float* W1b = (const float*)d_in[6];
    const float* b1b = (const float*)d_in[7];
    const float* W2  = (const float*)d_in[8];
    const float* b2  = (const float*)d_in[9];
    const int* src_oo = (const int*)d_in[10];
    const int* dst_oo = (const int*)d_in[11];
    const int* src_ro = (const int*)d_in[12];
    const int* dst_ro = (const int*)d_in[13];
    const int* src_ao = (const int*)d_in[14];
    const int* dst_ao = (const int*)d_in[15];
    float* out = (float*)d_out;

    static bool attr_set = false;
    if (!attr_set) {
        cudaFuncSetAttribute(gemm1, cudaFuncAttributeMaxDynamicSharedMemorySize, SMEM_BYTES);
        cudaFuncSetAttribute(gemm2, cudaFuncAttributeMaxDynamicSharedMemorySize, SMEM_BYTES);
        attr_set = true;
    }

    const int ETOT = EOO + ERO + EAO;

    prep<<<1024, 256>>>(W1i, W1b, W2, feat_obj, feat_room, feat_attr);
    deg_all<<<(ETOT + 255) / 256, 256>>>(src_oo, dst_oo, src_ro, dst_ro, src_ao, dst_ao);
    scan3<<<3, 1024>>>();
    scatter_all<<<(ETOT + 255) / 256, 256>>>(src_oo, dst_oo, src_ro, dst_ro, src_ao, dst_ao);

    agg1_all<<<dim3(N_OBJ, 3), 128>>>();

    dim3 grid(HDIM / 128, (N_OBJ + 127) / 128);
    gemm1<<<grid, 256, SMEM_BYTES>>>(b1i, b1b);

    agg2<<<N_OBJ, 128>>>();

    gemm2<<<grid, 256, SMEM_BYTES>>>(b2, out);
}

// round 10
// speedup vs baseline: 3.5503x; 1.0431x over previous
#include <cuda_runtime.h>
#include <cuda_fp16.h>
#include <cstdint>

#define N_OBJ  20000
#define N_ROOM 500
#define N_ATTR 2000
#define IN_F   300
#define HDIM   512
#define EOO    640000
#define ERO    50000
#define EAO    100000
#define BATCH  8

#define MP   20096
#define KP1  320           // conv1 K padded to 32-multiple
#define KP2  512
#define TT1  30            // 3 relations * 10 chunks of BK=32
#define TT2  16            // 512/32

// ---------------- scratch (device globals, no allocation) ----------------
__device__ __half g_hs[(size_t)N_OBJ * HDIM];     // fp16 h_obj * ns_oo

__device__ __half g_fo16[(size_t)N_OBJ  * IN_F];  // fp16 feature tables
__device__ __half g_fr16[(size_t)N_ROOM * IN_F];
__device__ __half g_fa16[(size_t)N_ATTR * IN_F];

__device__ int g_dout_oo[N_OBJ];
__device__ int g_din_oo [N_OBJ];
__device__ int g_dout_ro[N_ROOM];
__device__ int g_din_ro [N_OBJ];
__device__ int g_dout_ao[N_ATTR];
__device__ int g_din_ao [N_OBJ];

__device__ int g_off_oo[N_OBJ + 1];
__device__ int g_off_ro[N_OBJ + 1];
__device__ int g_off_ao[N_OBJ + 1];
__device__ int g_cnt_oo[N_OBJ];
__device__ int g_cnt_ro[N_OBJ];
__device__ int g_cnt_ao[N_OBJ];
__device__ int g_csr_oo[EOO];
__device__ int g_csr_ro[ERO];
__device__ int g_csr_ao[EAO];

__device__ __half g_A1[3][(size_t)MP * KP1];      // single fp16 activations
__device__ __half g_A2[(size_t)MP * KP2];
__device__ __half g_W[3][(size_t)KP2 * HDIM];     // 0:W1i 1:W1b 2:W2

// ---------------- prep: zero degs + pads + fp16 converts ----------
__global__ void prep(const float* __restrict__ W1i, const float* __restrict__ W1b,
                     const float* __restrict__ W2,
                     const float* __restrict__ fo, const float* __restrict__ fr,
                     const float* __restrict__ fa) {
    int tid    = blockIdx.x * blockDim.x + threadIdx.x;
    int stride = gridDim.x * blockDim.x;
    for (int i = tid; i < N_OBJ; i += stride) {
        g_dout_oo[i] = 0; g_din_oo[i] = 0; g_din_ro[i] = 0; g_din_ao[i] = 0;
    }
    for (int i = tid; i < N_ROOM; i += stride) g_dout_ro[i] = 0;
    for (int i = tid; i < N_ATTR; i += stride) g_dout_ao[i] = 0;
    const __half z = __float2half(0.f);
    // K-pad cols 304..319 of every row (agg1 writes only 0..303)
    for (int i = tid; i < MP * 16; i += stride) {
        int r = i / 16, c = 304 + (i % 16);
        size_t o = (size_t)r * KP1 + c;
        g_A1[0][o] = z; g_A1[1][o] = z; g_A1[2][o] = z;
    }
    // M-pad rows
    int padA1 = (MP - N_OBJ) * KP1;
    for (int i = tid; i < padA1; i += stride) {
        size_t o = (size_t)N_OBJ * KP1 + i;
        g_A1[0][o] = z; g_A1[1][o] = z; g_A1[2][o] = z;
    }
    int padA2 = (MP - N_OBJ) * KP2;
    for (int i = tid; i < padA2; i += stride)
        g_A2[(size_t)N_OBJ * KP2 + i] = z;

    const int n1 = KP1 * HDIM;     // weight rows 0..319 (>=300 zero)
    for (int idx = tid; idx < n1; idx += stride) {
        int r = idx / HDIM;
        g_W[0][idx] = __float2half_rn((r < IN_F) ? W1i[idx] : 0.f);
        g_W[1][idx] = __float2half_rn((r < IN_F) ? W1b[idx] : 0.f);
    }
    const int n2 = KP2 * HDIM;
    for (int idx = tid; idx < n2; idx += stride)
        g_W[2][idx] = __float2half_rn(W2[idx]);

    const int nfo = N_OBJ * IN_F;
    for (int idx = tid; idx < nfo; idx += stride) g_fo16[idx] = __float2half_rn(fo[idx]);
    const int nfr = N_ROOM * IN_F;
    for (int idx = tid; idx < nfr; idx += stride) g_fr16[idx] = __float2half_rn(fr[idx]);
    const int nfa = N_ATTR * IN_F;
    for (int idx = tid; idx < nfa; idx += stride) g_fa16[idx] = __float2half_rn(fa[idx]);
}

// ---------------- merged degree counting ----------------
__global__ void deg_all(const int* __restrict__ src_oo, const int* __restrict__ dst_oo,
                        const int* __restrict__ src_ro, const int* __restrict__ dst_ro,
                        const int* __restrict__ src_ao, const int* __restrict__ dst_ao) {
    int i = blockIdx.x * blockDim.x + threadIdx.x;
    if (i < EOO) {
        atomicAdd(&g_dout_oo[src_oo[i]], 1);
        atomicAdd(&g_din_oo [dst_oo[i]], 1);
    } else if (i < EOO + ERO) {
        int j = i - EOO;
        atomicAdd(&g_dout_ro[src_ro[j]], 1);
        atomicAdd(&g_din_ro [dst_ro[j]], 1);
    } else if (i < EOO + ERO + EAO) {
        int j = i - EOO - ERO;
        atomicAdd(&g_dout_ao[src_ao[j]], 1);
        atomicAdd(&g_din_ao [dst_ao[j]], 1);
    }
}

// ---------------- 3-block exclusive scan ----------------
__global__ void scan3() {
    int sel = blockIdx.x;
    const int* deg = (sel == 0) ? g_din_oo : (sel == 1) ? g_din_ro : g_din_ao;
    int* offs      = (sel == 0) ? g_off_oo : (sel == 1) ? g_off_ro : g_off_ao;
    int* cnt       = (sel == 0) ? g_cnt_oo : (sel == 1) ? g_cnt_ro : g_cnt_ao;
    __shared__ int part[1025];
    const int n = N_OBJ;
    int t = threadIdx.x;
    int chunk = (n + 1023) / 1024;
    int b = t * chunk, e = min(b + chunk, n);
    int s = 0;
    for (int i = b; i < e; i++) s += deg[i];
    part[t + 1] = s;
    if (t == 0) part[0] = 0;
    __syncthreads();
    for (int off = 1; off < 1024; off <<= 1) {
        int v = part[t + 1];
        if (t + 1 > off) v += part[t + 1 - off];
        __syncthreads();
        part[t + 1] = v;
        __syncthreads();
    }
    int run = part[t];
    for (int i = b; i < e; i++) { offs[i] = run; cnt[i] = run; run += deg[i]; }
    if (t == 0) offs[n] = part[1024];
}

// ---------------- merged edge scatter ----------------
__global__ void scatter_all(const int* __restrict__ src_oo, const int* __restrict__ dst_oo,
                            const int* __restrict__ src_ro, const int* __restrict__ dst_ro,
                            const int* __restrict__ src_ao, const int* __restrict__ dst_ao) {
    int i = blockIdx.x * blockDim.x + threadIdx.x;
    if (i < EOO) {
        int pos = atomicAdd(&g_cnt_oo[dst_oo[i]], 1);
        g_csr_oo[pos] = src_oo[i];
    } else if (i < EOO + ERO) {
        int j = i - EOO;
        int pos = atomicAdd(&g_cnt_ro[dst_ro[j]], 1);
        g_csr_ro[pos] = src_ro[j];
    } else if (i < EOO + ERO + EAO) {
        int j = i - EOO - ERO;
        int pos = atomicAdd(&g_cnt_ao[dst_ao[j]], 1);
        g_csr_ao[pos] = src_ao[j];
    }
}

// ---------------- conv1 aggregation (fp16 features, fp32 accum) -------
__global__ void __launch_bounds__(128) agg1_all() {
    int sel = blockIdx.y;
    const __half* feat = (sel == 0) ? g_fo16 : (sel == 1) ? g_fr16 : g_fa16;
    const int* offs   = (sel == 0) ? g_off_oo  : (sel == 1) ? g_off_ro  : g_off_ao;
    const int* csr    = (sel == 0) ? g_csr_oo  : (sel == 1) ? g_csr_ro  : g_csr_ao;
    const int* degout = (sel == 0) ? g_dout_oo : (sel == 1) ? g_dout_ro : g_dout_ao;
    __half* A = g_A1[sel];

    int row = blockIdx.x;
    int t = threadIdx.x;
    int beg = offs[row], end = offs[row + 1];
    float4 a = make_float4(0.f, 0.f, 0.f, 0.f);
    __shared__ int   ss[128];
    __shared__ float sn[128];

    const int NV = IN_F / 4;            // 75 uint2-chunks of 4 halves
    for (int base = beg; base < end; base += 128) {
        int nB = min(128, end - base);
        __syncthreads();
        if (t < nB) {
            int s = csr[base + t];
            ss[t] = s;
            sn[t] = rsqrtf((float)max(degout[s], 1));
        }
        __syncthreads();
        int j = 0;
        if (t < NV) {
            for (; j + 4 <= nB; j += 4) {
                const uint2* p0 = (const uint2*)(feat + (size_t)ss[j + 0] * IN_F);
                const uint2* p1 = (const uint2*)(feat + (size_t)ss[j + 1] * IN_F);
                const uint2* p2 = (const uint2*)(feat + (size_t)ss[j + 2] * IN_F);
                const uint2* p3 = (const uint2*)(feat + (size_t)ss[j + 3] * IN_F);
                uint2 u0 = p0[t], u1 = p1[t], u2 = p2[t], u3 = p3[t];
                float n0 = sn[j], n1 = sn[j + 1], n2 = sn[j + 2], n3 = sn[j + 3];
                float2 c0 = __half22float2(*(__half2*)&u0.x), d0 = __half22float2(*(__half2*)&u0.y);
                float2 c1 = __half22float2(*(__half2*)&u1.x), d1 = __half22float2(*(__half2*)&u1.y);
                float2 c2 = __half22float2(*(__half2*)&u2.x), d2 = __half22float2(*(__half2*)&u2.y);
                float2 c3 = __half22float2(*(__half2*)&u3.x), d3 = __half22float2(*(__half2*)&u3.y);
                a.x += c0.x * n0 + c1.x * n1 + c2.x * n2 + c3.x * n3;
                a.y += c0.y * n0 + c1.y * n1 + c2.y * n2 + c3.y * n3;
                a.z += d0.x * n0 + d1.x * n1 + d2.x * n2 + d3.x * n3;
                a.w += d0.y * n0 + d1.y * n1 + d2.y * n2 + d3.y * n3;
            }
            for (; j < nB; j++) {
                uint2 u = ((const uint2*)(feat + (size_t)ss[j] * IN_F))[t];
                float n = sn[j];
                float2 c = __half22float2(*(__half2*)&u.x), d = __half22float2(*(__half2*)&u.y);
                a.x += c.x * n; a.y += c.y * n; a.z += d.x * n; a.w += d.y * n;
            }
        }
    }

    if (t <= NV) {
        if (t == NV) a = make_float4(0.f, 0.f, 0.f, 0.f);
        size_t o = (size_t)row * KP1 + t * 4;
        *(__half2*)(A + o)     = __floats2half2_rn(a.x, a.y);
        *(__half2*)(A + o + 2) = __floats2half2_rn(a.z, a.w);
    }
}

// ---------------- conv2 aggregation (fp16 g_hs, fp32 accum) ----------------
__global__ void __launch_bounds__(128) agg2() {
    int row = blockIdx.x;
    int t = threadIdx.x;
    int beg = g_off_oo[row], end = g_off_oo[row + 1];
    float4 a = make_float4(0.f, 0.f, 0.f, 0.f);
    __shared__ int ss[128];

    for (int base = beg; base < end; base += 128) {
        int nB = min(128, end - base);
        __syncthreads();
        if (t < nB) ss[t] = g_csr_oo[base + t];
        __syncthreads();
        int j = 0;
        for (; j + 4 <= nB; j += 4) {
            const uint2* p0 = (const uint2*)(g_hs + (size_t)ss[j + 0] * HDIM);
            const uint2* p1 = (const uint2*)(g_hs + (size_t)ss[j + 1] * HDIM);
            const uint2* p2 = (const uint2*)(g_hs + (size_t)ss[j + 2] * HDIM);
            const uint2* p3 = (const uint2*)(g_hs + (size_t)ss[j + 3] * HDIM);
            uint2 u0 = p0[t], u1 = p1[t], u2 = p2[t], u3 = p3[t];
            float2 c0 = __half22float2(*(__half2*)&u0.x), d0 = __half22float2(*(__half2*)&u0.y);
            float2 c1 = __half22float2(*(__half2*)&u1.x), d1 = __half22float2(*(__half2*)&u1.y);
            float2 c2 = __half22float2(*(__half2*)&u2.x), d2 = __half22float2(*(__half2*)&u2.y);
            float2 c3 = __half22float2(*(__half2*)&u3.x), d3 = __half22float2(*(__half2*)&u3.y);
            a.x += c0.x + c1.x + c2.x + c3.x;
            a.y += c0.y + c1.y + c2.y + c3.y;
            a.z += d0.x + d1.x + d2.x + d3.x;
            a.w += d0.y + d1.y + d2.y + d3.y;
        }
        for (; j < nB; j++) {
            uint2 u = ((const uint2*)(g_hs + (size_t)ss[j] * HDIM))[t];
            float2 c = __half22float2(*(__half2*)&u.x), d = __half22float2(*(__half2*)&u.y);
            a.x += c.x; a.y += c.y; a.z += d.x; a.w += d.y;
        }
    }

    size_t o = (size_t)row * KP2 + t * 4;
    *(__half2*)(g_A2 + o)     = __floats2half2_rn(a.x, a.y);
    *(__half2*)(g_A2 + o + 2) = __floats2half2_rn(a.z, a.w);
}

// ---------------- GEMM primitives ----------------
__device__ __forceinline__ void cpasync16(void* smem_dst, const void* gmem_src) {
    uint32_t sa = (uint32_t)__cvta_generic_to_shared(smem_dst);
    asm volatile("cp.async.cg.shared.global [%0], [%1], 16;\n" :: "r"(sa), "l"(gmem_src));
}
__device__ __forceinline__ void cp_commit() { asm volatile("cp.async.commit_group;\n" ::: "memory"); }
template <int N>
__device__ __forceinline__ void cp_wait() { asm volatile("cp.async.wait_group %0;\n" :: "n"(N) : "memory"); }

__device__ __forceinline__ void ldsm4(uint32_t* r, const void* p) {
    uint32_t a = (uint32_t)__cvta_generic_to_shared(p);
    asm volatile("ldmatrix.sync.aligned.m8n8.x4.shared.b16 {%0,%1,%2,%3}, [%4];\n"
                 : "=r"(r[0]), "=r"(r[1]), "=r"(r[2]), "=r"(r[3]) : "r"(a));
}
__device__ __forceinline__ void ldsm4t(uint32_t* r, const void* p) {
    uint32_t a = (uint32_t)__cvta_generic_to_shared(p);
    asm volatile("ldmatrix.sync.aligned.m8n8.x4.trans.shared.b16 {%0,%1,%2,%3}, [%4];\n"
                 : "=r"(r[0]), "=r"(r[1]), "=r"(r[2]), "=r"(r[3]) : "r"(a));
}
__device__ __forceinline__ void mma_fp16(float* d, const uint32_t* a, uint32_t b0, uint32_t b1) {
    asm volatile("mma.sync.aligned.m16n8k16.row.col.f32.f16.f16.f32 "
                 "{%0,%1,%2,%3}, {%4,%5,%6,%7}, {%8,%9}, {%0,%1,%2,%3};\n"
                 : "+f"(d[0]), "+f"(d[1]), "+f"(d[2]), "+f"(d[3])
                 : "r"(a[0]), "r"(a[1]), "r"(a[2]), "r"(a[3]), "r"(b0), "r"(b1));
}

// smem stage types: BK=32
typedef __half (*SA_t)[128][40];      // [stage][m][kpad 32+8]
typedef __half (*SB_t)[32][136];      // [stage][k][npad]
#define SMEM_A_BYTES (3 * 128 * 40 * 2)
#define SMEM_B_BYTES (3 * 32 * 136 * 2)
#define SMEM_BYTES   (SMEM_A_BYTES + SMEM_B_BYTES)

// ---------------- merged conv1 GEMM: hs = (sum_rel relu(A_rel@W+b)/3) * ns_oo
__global__ void __launch_bounds__(256, 1) gemm1(const float* __restrict__ b1i,
                                                const float* __restrict__ b1b) {
    extern __shared__ __align__(16) char smem[];
    SA_t sA = (SA_t)smem;
    SB_t sB = (SB_t)(smem + SMEM_A_BYTES);

    int tid = threadIdx.x;
    int warp = tid >> 5, lane = tid & 31;
    int row0 = blockIdx.y * 128, col0 = blockIdx.x * 128;
    int wr = warp >> 2, wc = warp & 3;

    float acc[4][4][4] = {};
    float accsum[4][4][4] = {};

    int aR = tid >> 2, aC = tid & 3;      // A: 64 rows/pass x 4x16B
    int bR = tid >> 4, bC = tid & 15;     // B: 16 rows/pass x 16x16B

    auto load_stage = [&](int t, int s) {
        int rel = t / 10;
        int tt  = t % 10;
        int wsel = (rel == 2) ? 1 : 0;
        const __half* Ap = g_A1[rel];
        int kb = tt * 32;
        #pragma unroll
        for (int rr = 0; rr < 2; rr++) {
            cpasync16(&sA[s][aR + rr * 64][aC * 8],
                      Ap + (size_t)(row0 + aR + rr * 64) * KP1 + kb + aC * 8);
            cpasync16(&sB[s][bR + rr * 16][bC * 8],
                      g_W[wsel] + (size_t)(kb + bR + rr * 16) * HDIM + col0 + bC * 8);
        }
    };

    load_stage(0, 0); cp_commit();
    load_stage(1, 1); cp_commit();

    int s = 0;
    for (int t = 0; t < TT1; t++) {
        cp_wait<1>();
        __syncthreads();
        int tp = t + 2;
        if (tp < TT1) load_stage(tp, tp % 3);
        cp_commit();

        int arow = wr * 64 + (lane & 15);
        int acol8 = (lane >> 4) * 8;
        int brow = lane & 15;
        int bcol = wc * 32 + (lane >> 4) * 8;
        #pragma unroll
        for (int ksub = 0; ksub < 2; ksub++) {
            uint32_t aa[4][4], bb[2][4];
            #pragma unroll
            for (int m = 0; m < 4; m++)
                ldsm4(aa[m], &sA[s][arow + m * 16][ksub * 16 + acol8]);
            #pragma unroll
            for (int p = 0; p < 2; p++)
                ldsm4t(bb[p], &sB[s][ksub * 16 + brow][bcol + p * 16]);
            #pragma unroll
            for (int m = 0; m < 4; m++)
                #pragma unroll
                for (int n = 0; n < 4; n++) {
                    int p = n >> 1, h = n & 1;
                    mma_fp16(acc[m][n], aa[m], bb[p][h * 2], bb[p][h * 2 + 1]);
                }
        }

        if (t % 10 == 9) {
            int rel = t / 10;
            const int* degin = (rel == 0) ? g_din_oo : (rel == 1) ? g_din_ro : g_din_ao;
            const float* bias = (rel == 2) ? b1b : b1i;
            const float third = 1.f / 3.f;
            #pragma unroll
            for (int m = 0; m < 4; m++) {
                int r1 = row0 + wr * 64 + m * 16 + (lane >> 2);
                int r2 = r1 + 8;
                float nd1 = (r1 < N_OBJ) ? rsqrtf((float)max(degin[r1], 1)) : 0.f;
                float nd2 = (r2 < N_OBJ) ? rsqrtf((float)max(degin[r2], 1)) : 0.f;
                #pragma unroll
                for (int n = 0; n < 4; n++) {
                    int c = col0 + wc * 32 + n * 8 + (lane & 3) * 2;
                    float bx = bias[c], by = bias[c + 1];
                    accsum[m][n][0] += fmaxf(acc[m][n][0] * nd1 + bx, 0.f) * third;
                    accsum[m][n][1] += fmaxf(acc[m][n][1] * nd1 + by, 0.f) * third;
                    accsum[m][n][2] += fmaxf(acc[m][n][2] * nd2 + bx, 0.f) * third;
                    accsum[m][n][3] += fmaxf(acc[m][n][3] * nd2 + by, 0.f) * third;
                    acc[m][n][0] = 0.f; acc[m][n][1] = 0.f;
                    acc[m][n][2] = 0.f; acc[m][n][3] = 0.f;
                }
            }
        }
        s++; if (s == 3) s = 0;
    }

    // final write: hs = accsum * ns_oo  (fp16)
    #pragma unroll
    for (int m = 0; m < 4; m++) {
        int r1 = row0 + wr * 64 + m * 16 + (lane >> 2);
        int r2 = r1 + 8;
        float sc1 = (r1 < N_OBJ) ? rsqrtf((float)max(g_dout_oo[r1], 1)) : 0.f;
        float sc2 = (r2 < N_OBJ) ? rsqrtf((float)max(g_dout_oo[r2], 1)) : 0.f;
        #pragma unroll
        for (int n = 0; n < 4; n++) {
            int c = col0 + wc * 32 + n * 8 + (lane & 3) * 2;
            if (r1 < N_OBJ)
                *(__half2*)(g_hs + (size_t)r1 * HDIM + c) =
                    __floats2half2_rn(accsum[m][n][0] * sc1, accsum[m][n][1] * sc1);
            if (r2 < N_OBJ)
                *(__half2*)(g_hs + (size_t)r2 * HDIM + c) =
                    __floats2half2_rn(accsum[m][n][2] * sc2, accsum[m][n][3] * sc2);
        }
    }
}

// ---------------- conv2 GEMM: out[b] = A2@W2*nd + b2, broadcast x8 ---------
__global__ void __launch_bounds__(256, 1) gemm2(const float* __restrict__ bias,
                                                float* __restrict__ outp) {
    extern __shared__ __align__(16) char smem[];
    SA_t sA = (SA_t)smem;
    SB_t sB = (SB_t)(smem + SMEM_A_BYTES);

    int tid = threadIdx.x;
    int warp = tid >> 5, lane = tid & 31;
    int row0 = blockIdx.y * 128, col0 = blockIdx.x * 128;
    int wr = warp >> 2, wc = warp & 3;

    float acc[4][4][4] = {};

    int aR = tid >> 2, aC = tid & 3;
    int bR = tid >> 4, bC = tid & 15;

    auto load_stage = [&](int t, int s) {
        int kb = t * 32;
        #pragma unroll
        for (int rr = 0; rr < 2; rr++) {
            cpasync16(&sA[s][aR + rr * 64][aC * 8],
                      g_A2 + (size_t)(row0 + aR + rr * 64) * KP2 + kb + aC * 8);
            cpasync16(&sB[s][bR + rr * 16][bC * 8],
                      g_W[2] + (size_t)(kb + bR + rr * 16) * HDIM + col0 + bC * 8);
        }
    };

    load_stage(0, 0); cp_commit();
    load_stage(1, 1); cp_commit();

    int s = 0;
    for (int t = 0; t < TT2; t++) {
        cp_wait<1>();
        __syncthreads();
        int tp = t + 2;
        if (tp < TT2) load_stage(tp, tp % 3);
        cp_commit();

        int arow = wr * 64 + (lane & 15);
        int acol8 = (lane >> 4) * 8;
        int brow = lane & 15;
        int bcol = wc * 32 + (lane >> 4) * 8;
        #pragma unroll
        for (int ksub = 0; ksub < 2; ksub++) {
            uint32_t aa[4][4], bb[2][4];
            #pragma unroll
            for (int m = 0; m < 4; m++)
                ldsm4(aa[m], &sA[s][arow + m * 16][ksub * 16 + acol8]);
            #pragma unroll
            for (int p = 0; p < 2; p++)
                ldsm4t(bb[p], &sB[s][ksub * 16 + brow][bcol + p * 16]);
            #pragma unroll
            for (int m = 0; m < 4; m++)
                #pragma unroll
                for (int n = 0; n < 4; n++) {
                    int p = n >> 1, h = n & 1;
                    mma_fp16(acc[m][n], aa[m], bb[p][h * 2], bb[p][h * 2 + 1]);
                }
        }
        s++; if (s == 3) s = 0;
    }

    #pragma unroll
    for (int m = 0; m < 4; m++) {
        int r1 = row0 + wr * 64 + m * 16 + (lane >> 2);
        int r2 = r1 + 8;
        float nd1 = (r1 < N_OBJ) ? rsqrtf((float)max(g_din_oo[r1], 1)) : 0.f;
        float nd2 = (r2 < N_OBJ) ? rsqrtf((float)max(g_din_oo[r2], 1)) : 0.f;
        #pragma unroll
        for (int n = 0; n < 4; n++) {
            int c = col0 + wc * 32 + n * 8 + (lane & 3) * 2;
            float bx = bias[c], by = bias[c + 1];
            float v1x = acc[m][n][0] * nd1 + bx;
            float v1y = acc[m][n][1] * nd1 + by;
            float v2x = acc[m][n][2] * nd2 + bx;
            float v2y = acc[m][n][3] * nd2 + by;
            #pragma unroll
            for (int b = 0; b < BATCH; b++) {
                if (r1 < N_OBJ)
                    *(float2*)(outp + (size_t)b * N_OBJ * HDIM + (size_t)r1 * HDIM + c) =
                        make_float2(v1x, v1y);
                if (r2 < N_OBJ)
                    *(float2*)(outp + (size_t)b * N_OBJ * HDIM + (size_t)r2 * HDIM + c) =
                        make_float2(v2x, v2y);
            }
        }
    }
}

// ---------------- launch ----------------
extern "C" void kernel_launch(void* const* d_in, const int* in_sizes, int n_in,
                              void* d_out, int out_size) {
    const float* feat_obj  = (const float*)d_in[1];
    const float* feat_room = (const float*)d_in[2];
    const float* feat_attr = (const float*)d_in[3];
    const float* W1i = (const float*)d_in[4];
    const float* b1i = (const float*)d_in[5];
    const float* W1b = (const float*)d_in[6];
    const float* b1b = (const float*)d_in[7];
    const float* W2  = (const float*)d_in[8];
    const float* b2  = (const float*)d_in[9];
    const int* src_oo = (const int*)d_in[10];
    const int* dst_oo = (const int*)d_in[11];
    const int* src_ro = (const int*)d_in[12];
    const int* dst_ro = (const int*)d_in[13];
    const int* src_ao = (const int*)d_in[14];
    const int* dst_ao = (const int*)d_in[15];
    float* out = (float*)d_out;

    static cudaStream_t s_side = nullptr;
    static cudaEvent_t ev_fork = nullptr, ev_join = nullptr;
    if (!s_side) {
        cudaStreamCreateWithFlags(&s_side, cudaStreamNonBlocking);
        cudaEventCreateWithFlags(&ev_fork, cudaEventDisableTiming);
        cudaEventCreateWithFlags(&ev_join, cudaEventDisableTiming);
        cudaFuncSetAttribute(gemm1, cudaFuncAttributeMaxDynamicSharedMemorySize, SMEM_BYTES);
        cudaFuncSetAttribute(gemm2, cudaFuncAttributeMaxDynamicSharedMemorySize, SMEM_BYTES);
    }

    const int ETOT = EOO + ERO + EAO;

    // fork: prep (fp16 converts) runs concurrently with CSR build
    cudaEventRecord(ev_fork, 0);
    cudaStreamWaitEvent(s_side, ev_fork, 0);
    prep<<<1024, 256, 0, s_side>>>(W1i, W1b, W2, feat_obj, feat_room, feat_attr);
    cudaEventRecord(ev_join, s_side);

    deg_all<<<(ETOT + 255) / 256, 256>>>(src_oo, dst_oo, src_ro, dst_ro, src_ao, dst_ao);
    scan3<<<3, 1024>>>();
    scatter_all<<<(ETOT + 255) / 256, 256>>>(src_oo, dst_oo, src_ro, dst_ro, src_ao, dst_ao);

    // join before agg1 (needs fp16 features + zeroed degrees from prep)
    cudaStreamWaitEvent(0, ev_join, 0);

    agg1_all<<<dim3(N_OBJ, 3), 128>>>();

    dim3 grid(HDIM / 128, (N_OBJ + 127) / 128);
    gemm1<<<grid, 256, SMEM_BYTES>>>(b1i, b1b);

    agg2<<<N_OBJ, 128>>>();

    gemm2<<<grid, 256, SMEM_BYTES>>>(b2, out);
}

// round 12
// speedup vs baseline: 4.1682x; 1.1740x over previous
#include <cuda_runtime.h>
#include <cuda_fp16.h>
#include <cstdint>

#define N_OBJ  20000
#define N_ROOM 500
#define N_ATTR 2000
#define IN_F   300
#define HDIM   512
#define EOO    640000
#define ERO    50000
#define EAO    100000
#define BATCH  8

#define MP   20096
#define KP1  320           // conv1 K padded to 32-multiple
#define KP2  512
#define TT1  30            // 3 relations * 10 chunks of BK=32
#define TT2  16            // 512/32

// ---------------- scratch (device globals, no allocation) ----------------
__device__ __half g_hs[(size_t)N_OBJ * HDIM];     // fp16 h_obj * ns_oo

__device__ __half g_fo16[(size_t)N_OBJ  * IN_F];  // fp16 feature tables
__device__ __half g_fr16[(size_t)N_ROOM * IN_F];
__device__ __half g_fa16[(size_t)N_ATTR * IN_F];

__device__ int g_dout_oo[N_OBJ];
__device__ int g_din_oo [N_OBJ];
__device__ int g_dout_ro[N_ROOM];
__device__ int g_din_ro [N_OBJ];
__device__ int g_dout_ao[N_ATTR];
__device__ int g_din_ao [N_OBJ];

__device__ int g_off_oo[N_OBJ + 1];
__device__ int g_off_ro[N_OBJ + 1];
__device__ int g_off_ao[N_OBJ + 1];
__device__ int g_cnt_oo[N_OBJ];
__device__ int g_cnt_ro[N_OBJ];
__device__ int g_cnt_ao[N_OBJ];
__device__ int g_csr_oo[EOO];
__device__ int g_csr_ro[ERO];
__device__ int g_csr_ao[EAO];

__device__ __half g_A1[3][(size_t)MP * KP1];      // single fp16 activations
__device__ __half g_A2[(size_t)MP * KP2];
__device__ __half g_W[3][(size_t)KP2 * HDIM];     // 0:W1i 1:W1b 2:W2

// ---------------- prep: zero degs + pads + fp16 converts ----------
__global__ void prep(const float* __restrict__ W1i, const float* __restrict__ W1b,
                     const float* __restrict__ W2,
                     const float* __restrict__ fo, const float* __restrict__ fr,
                     const float* __restrict__ fa) {
    int tid    = blockIdx.x * blockDim.x + threadIdx.x;
    int stride = gridDim.x * blockDim.x;
    for (int i = tid; i < N_OBJ; i += stride) {
        g_dout_oo[i] = 0; g_din_oo[i] = 0; g_din_ro[i] = 0; g_din_ao[i] = 0;
    }
    for (int i = tid; i < N_ROOM; i += stride) g_dout_ro[i] = 0;
    for (int i = tid; i < N_ATTR; i += stride) g_dout_ao[i] = 0;
    const __half z = __float2half(0.f);
    // K-pad cols 304..319 (agg1 writes only 0..303)
    for (int i = tid; i < MP * 16; i += stride) {
        int r = i / 16, c = 304 + (i % 16);
        size_t o = (size_t)r * KP1 + c;
        g_A1[0][o] = z; g_A1[1][o] = z; g_A1[2][o] = z;
    }
    int padA1 = (MP - N_OBJ) * KP1;
    for (int i = tid; i < padA1; i += stride) {
        size_t o = (size_t)N_OBJ * KP1 + i;
        g_A1[0][o] = z; g_A1[1][o] = z; g_A1[2][o] = z;
    }
    int padA2 = (MP - N_OBJ) * KP2;
    for (int i = tid; i < padA2; i += stride)
        g_A2[(size_t)N_OBJ * KP2 + i] = z;

    const int n1 = KP1 * HDIM;
    for (int idx = tid; idx < n1; idx += stride) {
        int r = idx / HDIM;
        g_W[0][idx] = __float2half_rn((r < IN_F) ? W1i[idx] : 0.f);
        g_W[1][idx] = __float2half_rn((r < IN_F) ? W1b[idx] : 0.f);
    }
    const int n2 = KP2 * HDIM;
    for (int idx = tid; idx < n2; idx += stride)
        g_W[2][idx] = __float2half_rn(W2[idx]);

    const int nfo = N_OBJ * IN_F;
    for (int idx = tid; idx < nfo; idx += stride) g_fo16[idx] = __float2half_rn(fo[idx]);
    const int nfr = N_ROOM * IN_F;
    for (int idx = tid; idx < nfr; idx += stride) g_fr16[idx] = __float2half_rn(fr[idx]);
    const int nfa = N_ATTR * IN_F;
    for (int idx = tid; idx < nfa; idx += stride) g_fa16[idx] = __float2half_rn(fa[idx]);
}

// ---------------- merged degree counting ----------------
__global__ void deg_all(const int* __restrict__ src_oo, const int* __restrict__ dst_oo,
                        const int* __restrict__ src_ro, const int* __restrict__ dst_ro,
                        const int* __restrict__ src_ao, const int* __restrict__ dst_ao) {
    int i = blockIdx.x * blockDim.x + threadIdx.x;
    if (i < EOO) {
        atomicAdd(&g_dout_oo[src_oo[i]], 1);
        atomicAdd(&g_din_oo [dst_oo[i]], 1);
    } else if (i < EOO + ERO) {
        int j = i - EOO;
        atomicAdd(&g_dout_ro[src_ro[j]], 1);
        atomicAdd(&g_din_ro [dst_ro[j]], 1);
    } else if (i < EOO + ERO + EAO) {
        int j = i - EOO - ERO;
        atomicAdd(&g_dout_ao[src_ao[j]], 1);
        atomicAdd(&g_din_ao [dst_ao[j]], 1);
    }
}

// ---------------- 3-block exclusive scan ----------------
__global__ void scan3() {
    int sel = blockIdx.x;
    const int* deg = (sel == 0) ? g_din_oo : (sel == 1) ? g_din_ro : g_din_ao;
    int* offs      = (sel == 0) ? g_off_oo : (sel == 1) ? g_off_ro : g_off_ao;
    int* cnt       = (sel == 0) ? g_cnt_oo : (sel == 1) ? g_cnt_ro : g_cnt_ao;
    __shared__ int part[1025];
    const int n = N_OBJ;
    int t = threadIdx.x;
    int chunk = (n + 1023) / 1024;
    int b = t * chunk, e = min(b + chunk, n);
    int s = 0;
    for (int i = b; i < e; i++) s += deg[i];
    part[t + 1] = s;
    if (t == 0) part[0] = 0;
    __syncthreads();
    for (int off = 1; off < 1024; off <<= 1) {
        int v = part[t + 1];
        if (t + 1 > off) v += part[t + 1 - off];
        __syncthreads();
        part[t + 1] = v;
        __syncthreads();
    }
    int run = part[t];
    for (int i = b; i < e; i++) { offs[i] = run; cnt[i] = run; run += deg[i]; }
    if (t == 0) offs[n] = part[1024];
}

// ---------------- merged edge scatter ----------------
__global__ void scatter_all(const int* __restrict__ src_oo, const int* __restrict__ dst_oo,
                            const int* __restrict__ src_ro, const int* __restrict__ dst_ro,
                            const int* __restrict__ src_ao, const int* __restrict__ dst_ao) {
    int i = blockIdx.x * blockDim.x + threadIdx.x;
    if (i < EOO) {
        int pos = atomicAdd(&g_cnt_oo[dst_oo[i]], 1);
        g_csr_oo[pos] = src_oo[i];
    } else if (i < EOO + ERO) {
        int j = i - EOO;
        int pos = atomicAdd(&g_cnt_ro[dst_ro[j]], 1);
        g_csr_ro[pos] = src_ro[j];
    } else if (i < EOO + ERO + EAO) {
        int j = i - EOO - ERO;
        int pos = atomicAdd(&g_cnt_ao[dst_ao[j]], 1);
        g_csr_ao[pos] = src_ao[j];
    }
}

// ---------------- conv1 aggregation (fp16 features, fp32 accum) -------
__global__ void __launch_bounds__(128) agg1_all() {
    int sel = blockIdx.y;
    const __half* feat = (sel == 0) ? g_fo16 : (sel == 1) ? g_fr16 : g_fa16;
    const int* offs   = (sel == 0) ? g_off_oo  : (sel == 1) ? g_off_ro  : g_off_ao;
    const int* csr    = (sel == 0) ? g_csr_oo  : (sel == 1) ? g_csr_ro  : g_csr_ao;
    const int* degout = (sel == 0) ? g_dout_oo : (sel == 1) ? g_dout_ro : g_dout_ao;
    __half* A = g_A1[sel];

    int row = blockIdx.x;
    int t = threadIdx.x;
    int beg = offs[row], end = offs[row + 1];
    float4 a = make_float4(0.f, 0.f, 0.f, 0.f);
    __shared__ int   ss[128];
    __shared__ float sn[128];

    const int NV = IN_F / 4;            // 75
    for (int base = beg; base < end; base += 128) {
        int nB = min(128, end - base);
        __syncthreads();
        if (t < nB) {
            int s = csr[base + t];
            ss[t] = s;
            sn[t] = rsqrtf((float)max(degout[s], 1));
        }
        __syncthreads();
        int j = 0;
        if (t < NV) {
            for (; j + 4 <= nB; j += 4) {
                const uint2* p0 = (const uint2*)(feat + (size_t)ss[j + 0] * IN_F);
                const uint2* p1 = (const uint2*)(feat + (size_t)ss[j + 1] * IN_F);
                const uint2* p2 = (const uint2*)(feat + (size_t)ss[j + 2] * IN_F);
                const uint2* p3 = (const uint2*)(feat + (size_t)ss[j + 3] * IN_F);
                uint2 u0 = p0[t], u1 = p1[t], u2 = p2[t], u3 = p3[t];
                float n0 = sn[j], n1 = sn[j + 1], n2 = sn[j + 2], n3 = sn[j + 3];
                float2 c0 = __half22float2(*(__half2*)&u0.x), d0 = __half22float2(*(__half2*)&u0.y);
                float2 c1 = __half22float2(*(__half2*)&u1.x), d1 = __half22float2(*(__half2*)&u1.y);
                float2 c2 = __half22float2(*(__half2*)&u2.x), d2 = __half22float2(*(__half2*)&u2.y);
                float2 c3 = __half22float2(*(__half2*)&u3.x), d3 = __half22float2(*(__half2*)&u3.y);
                a.x += c0.x * n0 + c1.x * n1 + c2.x * n2 + c3.x * n3;
                a.y += c0.y * n0 + c1.y * n1 + c2.y * n2 + c3.y * n3;
                a.z += d0.x * n0 + d1.x * n1 + d2.x * n2 + d3.x * n3;
                a.w += d0.y * n0 + d1.y * n1 + d2.y * n2 + d3.y * n3;
            }
            for (; j < nB; j++) {
                uint2 u = ((const uint2*)(feat + (size_t)ss[j] * IN_F))[t];
                float n = sn[j];
                float2 c = __half22float2(*(__half2*)&u.x), d = __half22float2(*(__half2*)&u.y);
                a.x += c.x * n; a.y += c.y * n; a.z += d.x * n; a.w += d.y * n;
            }
        }
    }

    if (t <= NV) {
        if (t == NV) a = make_float4(0.f, 0.f, 0.f, 0.f);
        size_t o = (size_t)row * KP1 + t * 4;
        *(__half2*)(A + o)     = __floats2half2_rn(a.x, a.y);
        *(__half2*)(A + o + 2) = __floats2half2_rn(a.z, a.w);
    }
}

// ---------------- conv2 aggregation (fp16 g_hs, fp32 accum) ----------------
__global__ void __launch_bounds__(128) agg2() {
    int row = blockIdx.x;
    int t = threadIdx.x;
    int beg = g_off_oo[row], end = g_off_oo[row + 1];
    float4 a = make_float4(0.f, 0.f, 0.f, 0.f);
    __shared__ int ss[128];

    for (int base = beg; base < end; base += 128) {
        int nB = min(128, end - base);
        __syncthreads();
        if (t < nB) ss[t] = g_csr_oo[base + t];
        __syncthreads();
        int j = 0;
        for (; j + 4 <= nB; j += 4) {
            const uint2* p0 = (const uint2*)(g_hs + (size_t)ss[j + 0] * HDIM);
            const uint2* p1 = (const uint2*)(g_hs + (size_t)ss[j + 1] * HDIM);
            const uint2* p2 = (const uint2*)(g_hs + (size_t)ss[j + 2] * HDIM);
            const uint2* p3 = (const uint2*)(g_hs + (size_t)ss[j + 3] * HDIM);
            uint2 u0 = p0[t], u1 = p1[t], u2 = p2[t], u3 = p3[t];
            float2 c0 = __half22float2(*(__half2*)&u0.x), d0 = __half22float2(*(__half2*)&u0.y);
            float2 c1 = __half22float2(*(__half2*)&u1.x), d1 = __half22float2(*(__half2*)&u1.y);
            float2 c2 = __half22float2(*(__half2*)&u2.x), d2 = __half22float2(*(__half2*)&u2.y);
            float2 c3 = __half22float2(*(__half2*)&u3.x), d3 = __half22float2(*(__half2*)&u3.y);
            a.x += c0.x + c1.x + c2.x + c3.x;
            a.y += c0.y + c1.y + c2.y + c3.y;
            a.z += d0.x + d1.x + d2.x + d3.x;
            a.w += d0.y + d1.y + d2.y + d3.y;
        }
        for (; j < nB; j++) {
            uint2 u = ((const uint2*)(g_hs + (size_t)ss[j] * HDIM))[t];
            float2 c = __half22float2(*(__half2*)&u.x), d = __half22float2(*(__half2*)&u.y);
            a.x += c.x; a.y += c.y; a.z += d.x; a.w += d.y;
        }
    }

    size_t o = (size_t)row * KP2 + t * 4;
    *(__half2*)(g_A2 + o)     = __floats2half2_rn(a.x, a.y);
    *(__half2*)(g_A2 + o + 2) = __floats2half2_rn(a.z, a.w);
}

// ---------------- GEMM primitives ----------------
__device__ __forceinline__ void cpasync16(void* smem_dst, const void* gmem_src) {
    uint32_t sa = (uint32_t)__cvta_generic_to_shared(smem_dst);
    asm volatile("cp.async.cg.shared.global [%0], [%1], 16;\n" :: "r"(sa), "l"(gmem_src));
}
__device__ __forceinline__ void cp_commit() { asm volatile("cp.async.commit_group;\n" ::: "memory"); }
template <int N>
__device__ __forceinline__ void cp_wait() { asm volatile("cp.async.wait_group %0;\n" :: "n"(N) : "memory"); }

__device__ __forceinline__ void ldsm4(uint32_t* r, const void* p) {
    uint32_t a = (uint32_t)__cvta_generic_to_shared(p);
    asm volatile("ldmatrix.sync.aligned.m8n8.x4.shared.b16 {%0,%1,%2,%3}, [%4];\n"
                 : "=r"(r[0]), "=r"(r[1]), "=r"(r[2]), "=r"(r[3]) : "r"(a));
}
__device__ __forceinline__ void ldsm4t(uint32_t* r, const void* p) {
    uint32_t a = (uint32_t)__cvta_generic_to_shared(p);
    asm volatile("ldmatrix.sync.aligned.m8n8.x4.trans.shared.b16 {%0,%1,%2,%3}, [%4];\n"
                 : "=r"(r[0]), "=r"(r[1]), "=r"(r[2]), "=r"(r[3]) : "r"(a));
}
__device__ __forceinline__ void mma_fp16(float* d, const uint32_t* a, uint32_t b0, uint32_t b1) {
    asm volatile("mma.sync.aligned.m16n8k16.row.col.f32.f16.f16.f32 "
                 "{%0,%1,%2,%3}, {%4,%5,%6,%7}, {%8,%9}, {%0,%1,%2,%3};\n"
                 : "+f"(d[0]), "+f"(d[1]), "+f"(d[2]), "+f"(d[3])
                 : "r"(a[0]), "r"(a[1]), "r"(a[2]), "r"(a[3]), "r"(b0), "r"(b1));
}

// smem stage types
typedef __half (*SA1_t)[64][40];      // gemm1: [stage][m=64][kpad 40]
typedef __half (*SA2_t)[128][40];     // gemm2: [stage][m=128][kpad 40]
typedef __half (*SB_t)[32][136];      // [stage][k][npad]
#define SMEM_A1_BYTES (3 * 64 * 40 * 2)
#define SMEM_A2_BYTES (3 * 128 * 40 * 2)
#define SMEM_B_BYTES  (3 * 32 * 136 * 2)
#define SMEM1_BYTES   (SMEM_A1_BYTES + SMEM_B_BYTES)
#define SMEM2_BYTES   (SMEM_A2_BYTES + SMEM_B_BYTES)

// ---------------- merged conv1 GEMM (64x128 tile, occupancy 2) ----------
// hs = (sum_rel relu(A_rel@W+b)/3) * ns_oo
__global__ void __launch_bounds__(256, 2) gemm1(const float* __restrict__ b1i,
                                                const float* __restrict__ b1b) {
    extern __shared__ __align__(16) char smem[];
    SA1_t sA = (SA1_t)smem;
    SB_t  sB = (SB_t)(smem + SMEM_A1_BYTES);

    int tid = threadIdx.x;
    int warp = tid >> 5, lane = tid & 31;
    int row0 = blockIdx.y * 64, col0 = blockIdx.x * 128;
    int wr = warp >> 2, wc = warp & 3;   // 2x4 warps, warp tile 32x32

    float acc[2][4][4] = {};
    float accsum[2][4][4] = {};

    int aR = tid >> 2, aC = tid & 3;      // A: 64 rows x 4x16B, one pass
    int bR = tid >> 4, bC = tid & 15;     // B: 16 rows/pass x 16x16B, two passes

    auto load_stage = [&](int t, int s) {
        int rel = t / 10;
        int tt  = t % 10;
        int wsel = (rel == 2) ? 1 : 0;
        const __half* Ap = g_A1[rel];
        int kb = tt * 32;
        cpasync16(&sA[s][aR][aC * 8],
                  Ap + (size_t)(row0 + aR) * KP1 + kb + aC * 8);
        #pragma unroll
        for (int rr = 0; rr < 2; rr++)
            cpasync16(&sB[s][bR + rr * 16][bC * 8],
                      g_W[wsel] + (size_t)(kb + bR + rr * 16) * HDIM + col0 + bC * 8);
    };

    load_stage(0, 0); cp_commit();
    load_stage(1, 1); cp_commit();

    int s = 0;
    for (int t = 0; t < TT1; t++) {
        cp_wait<1>();
        __syncthreads();
        int tp = t + 2;
        if (tp < TT1) load_stage(tp, tp % 3);
        cp_commit();

        int arow = wr * 32 + (lane & 15);
        int acol8 = (lane >> 4) * 8;
        int brow = lane & 15;
        int bcol = wc * 32 + (lane >> 4) * 8;
        #pragma unroll
        for (int ksub = 0; ksub < 2; ksub++) {
            uint32_t aa[2][4], bb[2][4];
            #pragma unroll
            for (int m = 0; m < 2; m++)
                ldsm4(aa[m], &sA[s][arow + m * 16][ksub * 16 + acol8]);
            #pragma unroll
            for (int p = 0; p < 2; p++)
                ldsm4t(bb[p], &sB[s][ksub * 16 + brow][bcol + p * 16]);
            #pragma unroll
            for (int m = 0; m < 2; m++)
                #pragma unroll
                for (int n = 0; n < 4; n++) {
                    int p = n >> 1, h = n & 1;
                    mma_fp16(acc[m][n], aa[m], bb[p][h * 2], bb[p][h * 2 + 1]);
                }
        }

        if (t % 10 == 9) {
            int rel = t / 10;
            const int* degin = (rel == 0) ? g_din_oo : (rel == 1) ? g_din_ro : g_din_ao;
            const float* bias = (rel == 2) ? b1b : b1i;
            const float third = 1.f / 3.f;
            #pragma unroll
            for (int m = 0; m < 2; m++) {
                int r1 = row0 + wr * 32 + m * 16 + (lane >> 2);
                int r2 = r1 + 8;
                float nd1 = (r1 < N_OBJ) ? rsqrtf((float)max(degin[r1], 1)) : 0.f;
                float nd2 = (r2 < N_OBJ) ? rsqrtf((float)max(degin[r2], 1)) : 0.f;
                #pragma unroll
                for (int n = 0; n < 4; n++) {
                    int c = col0 + wc * 32 + n * 8 + (lane & 3) * 2;
                    float bx = bias[c], by = bias[c + 1];
                    accsum[m][n][0] += fmaxf(acc[m][n][0] * nd1 + bx, 0.f) * third;
                    accsum[m][n][1] += fmaxf(acc[m][n][1] * nd1 + by, 0.f) * third;
                    accsum[m][n][2] += fmaxf(acc[m][n][2] * nd2 + bx, 0.f) * third;
                    accsum[m][n][3] += fmaxf(acc[m][n][3] * nd2 + by, 0.f) * third;
                    acc[m][n][0] = 0.f; acc[m][n][1] = 0.f;
                    acc[m][n][2] = 0.f; acc[m][n][3] = 0.f;
                }
            }
        }
        s++; if (s == 3) s = 0;
    }

    // final write: hs = accsum * ns_oo  (fp16)
    #pragma unroll
    for (int m = 0; m < 2; m++) {
        int r1 = row0 + wr * 32 + m * 16 + (lane >> 2);
        int r2 = r1 + 8;
        float sc1 = (r1 < N_OBJ) ? rsqrtf((float)max(g_dout_oo[r1], 1)) : 0.f;
        float sc2 = (r2 < N_OBJ) ? rsqrtf((float)max(g_dout_oo[r2], 1)) : 0.f;
        #pragma unroll
        for (int n = 0; n < 4; n++) {
            int c = col0 + wc * 32 + n * 8 + (lane & 3) * 2;
            if (r1 < N_OBJ)
                *(__half2*)(g_hs + (size_t)r1 * HDIM + c) =
                    __floats2half2_rn(accsum[m][n][0] * sc1, accsum[m][n][1] * sc1);
            if (r2 < N_OBJ)
                *(__half2*)(g_hs + (size_t)r2 * HDIM + c) =
                    __floats2half2_rn(accsum[m][n][2] * sc2, accsum[m][n][3] * sc2);
        }
    }
}

// ---------------- conv2 GEMM (128x128, occupancy 2): out[b] = A2@W2*nd + b2 --
__global__ void __launch_bounds__(256, 2) gemm2(const float* __restrict__ bias,
                                                float* __restrict__ outp) {
    extern __shared__ __align__(16) char smem[];
    SA2_t sA = (SA2_t)smem;
    SB_t  sB = (SB_t)(smem + SMEM_A2_BYTES);

    int tid = threadIdx.x;
    int warp = tid >> 5, lane = tid & 31;
    int row0 = blockIdx.y * 128, col0 = blockIdx.x * 128;
    int wr = warp >> 2, wc = warp & 3;

    float acc[4][4][4] = {};

    int aR = tid >> 2, aC = tid & 3;
    int bR = tid >> 4, bC = tid & 15;

    auto load_stage = [&](int t, int s) {
        int kb = t * 32;
        #pragma unroll
        for (int rr = 0; rr < 2; rr++) {
            cpasync16(&sA[s][aR + rr * 64][aC * 8],
                      g_A2 + (size_t)(row0 + aR + rr * 64) * KP2 + kb + aC * 8);
            cpasync16(&sB[s][bR + rr * 16][bC * 8],
                      g_W[2] + (size_t)(kb + bR + rr * 16) * HDIM + col0 + bC * 8);
        }
    };

    load_stage(0, 0); cp_commit();
    load_stage(1, 1); cp_commit();

    int s = 0;
    for (int t = 0; t < TT2; t++) {
        cp_wait<1>();
        __syncthreads();
        int tp = t + 2;
        if (tp < TT2) load_stage(tp, tp % 3);
        cp_commit();

        int arow = wr * 64 + (lane & 15);
        int acol8 = (lane >> 4) * 8;
        int brow = lane & 15;
        int bcol = wc * 32 + (lane >> 4) * 8;
        #pragma unroll
        for (int ksub = 0; ksub < 2; ksub++) {
            uint32_t aa[4][4], bb[2][4];
            #pragma unroll
            for (int m = 0; m < 4; m++)
                ldsm4(aa[m], &sA[s][arow + m * 16][ksub * 16 + acol8]);
            #pragma unroll
            for (int p = 0; p < 2; p++)
                ldsm4t(bb[p], &sB[s][ksub * 16 + brow][bcol + p * 16]);
            #pragma unroll
            for (int m = 0; m < 4; m++)
                #pragma unroll
                for (int n = 0; n < 4; n++) {
                    int p = n >> 1, h = n & 1;
                    mma_fp16(acc[m][n], aa[m], bb[p][h * 2], bb[p][h * 2 + 1]);
                }
        }
        s++; if (s == 3) s = 0;
    }

    #pragma unroll
    for (int m = 0; m < 4; m++) {
        int r1 = row0 + wr * 64 + m * 16 + (lane >> 2);
        int r2 = r1 + 8;
        float nd1 = (r1 < N_OBJ) ? rsqrtf((float)max(g_din_oo[r1], 1)) : 0.f;
        float nd2 = (r2 < N_OBJ) ? rsqrtf((float)max(g_din_oo[r2], 1)) : 0.f;
        #pragma unroll
        for (int n = 0; n < 4; n++) {
            int c = col0 + wc * 32 + n * 8 + (lane & 3) * 2;
            float bx = bias[c], by = bias[c + 1];
            float v1x = acc[m][n][0] * nd1 + bx;
            float v1y = acc[m][n][1] * nd1 + by;
            float v2x = acc[m][n][2] * nd2 + bx;
            float v2y = acc[m][n][3] * nd2 + by;
            #pragma unroll
            for (int b = 0; b < BATCH; b++) {
                if (r1 < N_OBJ)
                    *(float2*)(outp + (size_t)b * N_OBJ * HDIM + (size_t)r1 * HDIM + c) =
                        make_float2(v1x, v1y);
                if (r2 < N_OBJ)
                    *(float2*)(outp + (size_t)b * N_OBJ * HDIM + (size_t)r2 * HDIM + c) =
                        make_float2(v2x, v2y);
            }
        }
    }
}

// ---------------- launch ----------------
extern "C" void kernel_launch(void* const* d_in, const int* in_sizes, int n_in,
                              void* d_out, int out_size) {
    const float* feat_obj  = (const float*)d_in[1];
    const float* feat_room = (const float*)d_in[2];
    const float* feat_attr = (const float*)d_in[3];
    const float* W1i = (const float*)d_in[4];
    const float* b1i = (const float*)d_in[5];
    const float* W1b = (const float*)d_in[6];
    const float* b1b = (const float*)d_in[7];
    const float* W2  = (const float*)d_in[8];
    const float* b2  = (const float*)d_in[9];
    const int* src_oo = (const int*)d_in[10];
    const int* dst_oo = (const int*)d_in[11];
    const int* src_ro = (const int*)d_in[12];
    const int* dst_ro = (const int*)d_in[13];
    const int* src_ao = (const int*)d_in[14];
    const int* dst_ao = (const int*)d_in[15];
    float* out = (float*)d_out;

    static cudaStream_t s_side = nullptr;
    static cudaEvent_t ev_fork = nullptr, ev_join = nullptr;
    if (!s_side) {
        cudaStreamCreateWithFlags(&s_side, cudaStreamNonBlocking);
        cudaEventCreateWithFlags(&ev_fork, cudaEventDisableTiming);
        cudaEventCreateWithFlags(&ev_join, cudaEventDisableTiming);
        cudaFuncSetAttribute(gemm1, cudaFuncAttributeMaxDynamicSharedMemorySize, SMEM1_BYTES);
        cudaFuncSetAttribute(gemm2, cudaFuncAttributeMaxDynamicSharedMemorySize, SMEM2_BYTES);
    }

    const int ETOT = EOO + ERO + EAO;

    // fork: prep (fp16 converts) concurrent with CSR build
    cudaEventRecord(ev_fork, 0);
    cudaStreamWaitEvent(s_side, ev_fork, 0);
    prep<<<1024, 256, 0, s_side>>>(W1i, W1b, W2, feat_obj, feat_room, feat_attr);
    cudaEventRecord(ev_join, s_side);

    deg_all<<<(ETOT + 255) / 256, 256>>>(src_oo, dst_oo, src_ro, dst_ro, src_ao, dst_ao);
    scan3<<<3, 1024>>>();
    scatter_all<<<(ETOT + 255) / 256, 256>>>(src_oo, dst_oo, src_ro, dst_ro, src_ao, dst_ao);

    cudaStreamWaitEvent(0, ev_join, 0);

    agg1_all<<<dim3(N_OBJ, 3), 128>>>();

    gemm1<<<dim3(4, MP / 64), 256, SMEM1_BYTES>>>(b1i, b1b);

    agg2<<<N_OBJ, 128>>>();

    gemm2<<<dim3(4, MP / 128), 256, SMEM2_BYTES>>>(b2, out);
}